// round 2
// baseline (speedup 1.0000x reference)
#include <cuda_runtime.h>
#include <math.h>

// ---------------------------------------------------------------------------
// LinearSelfAttention (Performer-style) — round 1: correct fp32 SIMT pipeline
//   B=4, L=4096, H=16, D=64, M=128 (features 2M=256), D_MODEL=1024
// Pipeline:
//   gemm:  v  = x        @ W_v        [16384,1024]x[1024,1024]
//   gemm:  pp = pos_ft   @ pos_ft_w
//   gemm:  sp = slopes   @ pos_ft_w
//   feat:  q',k' fourier features + ||sp|| norm factor
//   kvp :  partial kv = k'^T v over L-chunks (deterministic, no atomics)
//   kvr :  reduce partials -> kv[b,h,256,64]
//   z   :  z = q' @ kv, scaled by normf
//   gemm:  out = z @ W_o
// ---------------------------------------------------------------------------

#define B_ 4
#define L_ 4096
#define H_ 16
#define D_ 64
#define M_ 128       // feature half-dim; 2M = 256
#define DM_ 1024
#define NCHUNK 32
#define LC_ (L_ / NCHUNK)   // 128

#define NORMALIZER 0.35355339059327373f   // 64^-0.25
#define RATIO      0.08838834764831845f   // 1/sqrt(128)

// ----- scratch (static device globals; no allocation anywhere) -----
__device__ float g_v   [(size_t)B_ * L_ * DM_];
__device__ float g_pp  [(size_t)B_ * L_ * DM_];
__device__ float g_sp  [(size_t)B_ * L_ * DM_];
__device__ float g_qp  [(size_t)B_ * L_ * H_ * 2 * M_];
__device__ float g_kp  [(size_t)B_ * L_ * H_ * 2 * M_];
__device__ float g_part[(size_t)B_ * H_ * NCHUNK * 2 * M_ * D_];
__device__ float g_kv  [(size_t)B_ * H_ * 2 * M_ * D_];
__device__ float g_z   [(size_t)B_ * L_ * DM_];
__device__ float g_nf  [(size_t)B_ * L_ * H_];

// ---------------------------------------------------------------------------
// Generic fp32 GEMM: C[M,N] = A[M,K] @ B[K,N], row-major.
// BM=BN=128, BK=16, 256 threads, 8x8 per thread.
// Requires M%128==0, N%128==0, K%16==0, all pointers 16B-aligned.
// ---------------------------------------------------------------------------
__global__ __launch_bounds__(256)
void gemm128(const float* __restrict__ A, const float* __restrict__ Bm,
             float* __restrict__ C, int Mr, int N, int K)
{
    __shared__ float AsT[16][128];
    __shared__ float Bs[16][128];

    const int tid = threadIdx.x;
    const int tx = tid & 15;
    const int ty = tid >> 4;
    const int m0 = blockIdx.y * 128;
    const int n0 = blockIdx.x * 128;

    float acc[8][8];
#pragma unroll
    for (int i = 0; i < 8; i++)
#pragma unroll
        for (int j = 0; j < 8; j++) acc[i][j] = 0.0f;

    for (int k0 = 0; k0 < K; k0 += 16) {
        // Load A tile 128x16 -> AsT[k][m] (512 float4, 2 per thread)
#pragma unroll
        for (int j = 0; j < 2; j++) {
            int i = tid * 2 + j;           // 0..511
            int row = i >> 2;              // 0..127
            int kc = (i & 3) * 4;          // 0,4,8,12
            float4 a = *(const float4*)(A + (size_t)(m0 + row) * K + k0 + kc);
            AsT[kc + 0][row] = a.x;
            AsT[kc + 1][row] = a.y;
            AsT[kc + 2][row] = a.z;
            AsT[kc + 3][row] = a.w;
        }
        // Load B tile 16x128 -> Bs[k][n]
#pragma unroll
        for (int j = 0; j < 2; j++) {
            int i = tid * 2 + j;           // 0..511
            int br = i >> 5;               // 0..15
            int nc = (i & 31) * 4;         // 0..124
            *(float4*)(&Bs[br][nc]) =
                *(const float4*)(Bm + (size_t)(k0 + br) * N + n0 + nc);
        }
        __syncthreads();

#pragma unroll
        for (int kk = 0; kk < 16; kk++) {
            float ra[8], rb[8];
            *(float4*)(ra)     = *(float4*)(&AsT[kk][ty * 8]);
            *(float4*)(ra + 4) = *(float4*)(&AsT[kk][ty * 8 + 4]);
            *(float4*)(rb)     = *(float4*)(&Bs[kk][tx * 8]);
            *(float4*)(rb + 4) = *(float4*)(&Bs[kk][tx * 8 + 4]);
#pragma unroll
            for (int i = 0; i < 8; i++)
#pragma unroll
                for (int j = 0; j < 8; j++)
                    acc[i][j] += ra[i] * rb[j];
        }
        __syncthreads();
    }

#pragma unroll
    for (int i = 0; i < 8; i++) {
        float* cp = C + (size_t)(m0 + ty * 8 + i) * N + n0 + tx * 8;
        float4 o0 = make_float4(acc[i][0], acc[i][1], acc[i][2], acc[i][3]);
        float4 o1 = make_float4(acc[i][4], acc[i][5], acc[i][6], acc[i][7]);
        *(float4*)(cp)     = o0;
        *(float4*)(cp + 4) = o1;
    }
}

// ---------------------------------------------------------------------------
// Fourier feature kernel. 128 threads (one per feature m), 32 rows per block.
// Row r enumerates (b,l,h). Reads pp/sp, writes q'[r,256], k'[r,256], normf[r].
// ---------------------------------------------------------------------------
__global__ __launch_bounds__(128)
void feature_kernel(const float* __restrict__ pp, const float* __restrict__ sp,
                    const float* __restrict__ proj,
                    const float* __restrict__ scale, const float* __restrict__ offs,
                    float* __restrict__ qp, float* __restrict__ kp,
                    float* __restrict__ nf)
{
    __shared__ float projT[64][129];   // [d][m], padded
    __shared__ float qpos[64];
    __shared__ float kpos[64];
    __shared__ float spsq[64];

    const int tid = threadIdx.x;       // == m

    // Load proj[m][d] -> projT[d][m]
#pragma unroll
    for (int i = tid; i < M_ * D_; i += 128) {
        int m = i >> 6;
        int d = i & 63;
        projT[d][m] = proj[i];
    }

    const int r0 = blockIdx.x * 32;

    for (int rr = 0; rr < 32; rr++) {
        const int r = r0 + rr;
        const int h = r & (H_ - 1);
        const float s = scale[h];
        const float off = offs[h];

        __syncthreads();   // protect smem reuse across rows (and proj load on rr==0)

        if (tid < 64) {
            float p = pp[(size_t)r * 64 + tid];
            qpos[tid] = s * p;
        } else {
            int d = tid - 64;
            float p = pp[(size_t)r * 64 + d];
            float sl = sp[(size_t)r * 64 + d];
            kpos[d] = s * (p + off * sl);
            spsq[d] = sl * sl;
        }
        __syncthreads();

        float dq = 0.0f, dk = 0.0f;
#pragma unroll
        for (int d = 0; d < 64; d++) {
            float pj = projT[d][tid];
            dq += qpos[d] * pj;
            dk += kpos[d] * pj;
        }
        dq *= NORMALIZER;
        dk *= NORMALIZER;

        float sq, cq, sk, ck;
        __sincosf(dq, &sq, &cq);
        __sincosf(dk, &sk, &ck);

        const size_t base = (size_t)r * (2 * M_);
        qp[base + tid]        = RATIO * sq;
        qp[base + M_ + tid]   = RATIO * cq;
        kp[base + tid]        = RATIO * sk;
        kp[base + M_ + tid]   = RATIO * ck;

        if (tid < 32) {
            float v2 = spsq[tid] + spsq[tid + 32];
#pragma unroll
            for (int o = 16; o; o >>= 1)
                v2 += __shfl_down_sync(0xffffffffu, v2, o);
            if (tid == 0) nf[r] = sqrtf(v2) * (1.0f / (float)L_);
        }
    }
}

// ---------------------------------------------------------------------------
// kv partial: per (b,h,chunk), accumulate k'[l,m] * v[l,d] over LC_ l-values.
// 256 threads, each an 8x8 (m,d) micro-tile of the 256x64 outer product.
// ---------------------------------------------------------------------------
__global__ __launch_bounds__(256)
void kv_partial_kernel(const float* __restrict__ kp, const float* __restrict__ v,
                       float* __restrict__ part)
{
    const int chunk = blockIdx.x;
    const int h = blockIdx.y;
    const int b = blockIdx.z;
    const int tid = threadIdx.x;
    const int td = tid & 7;            // 8 d-groups
    const int tm = tid >> 3;           // 32 m-groups
    const int d0 = td * 8;
    const int m0 = tm * 8;

    __shared__ float ks[2 * M_];
    __shared__ float vs[D_];

    float acc[8][8];
#pragma unroll
    for (int i = 0; i < 8; i++)
#pragma unroll
        for (int j = 0; j < 8; j++) acc[i][j] = 0.0f;

    const int l0 = chunk * LC_;
    for (int l = l0; l < l0 + LC_; l++) {
        const size_t rbase = ((size_t)(b * L_ + l) * H_ + h);
        ks[tid] = kp[rbase * (2 * M_) + tid];
        if (tid < D_) vs[tid] = v[rbase * D_ + tid];
        __syncthreads();

        float rm[8], rd[8];
        *(float4*)(rm)     = *(float4*)(&ks[m0]);
        *(float4*)(rm + 4) = *(float4*)(&ks[m0 + 4]);
        *(float4*)(rd)     = *(float4*)(&vs[d0]);
        *(float4*)(rd + 4) = *(float4*)(&vs[d0 + 4]);
#pragma unroll
        for (int i = 0; i < 8; i++)
#pragma unroll
            for (int j = 0; j < 8; j++)
                acc[i][j] += rm[i] * rd[j];
        __syncthreads();
    }

    const size_t pbase = ((size_t)((b * H_ + h) * NCHUNK + chunk)) * (2 * M_ * D_);
#pragma unroll
    for (int i = 0; i < 8; i++) {
        float* op = part + pbase + (size_t)(m0 + i) * D_ + d0;
        *(float4*)(op)     = make_float4(acc[i][0], acc[i][1], acc[i][2], acc[i][3]);
        *(float4*)(op + 4) = make_float4(acc[i][4], acc[i][5], acc[i][6], acc[i][7]);
    }
}

// ---------------------------------------------------------------------------
// kv reduce: sum NCHUNK partials (fixed order -> deterministic)
// ---------------------------------------------------------------------------
__global__ __launch_bounds__(256)
void kv_reduce_kernel(const float* __restrict__ part, float* __restrict__ kv)
{
    const int idx = blockIdx.x * 256 + threadIdx.x;     // over B*H*256*64
    const int bh = idx / (2 * M_ * D_);
    const int md = idx % (2 * M_ * D_);
    float s = 0.0f;
#pragma unroll
    for (int c = 0; c < NCHUNK; c++)
        s += part[((size_t)bh * NCHUNK + c) * (2 * M_ * D_) + md];
    kv[idx] = s;
}

// ---------------------------------------------------------------------------
// z = q' @ kv, times normf.   Per (b,h): [4096,256] @ [256,64].
// Block: 64 l x 64 d, 256 threads, 4x4 per thread, BK=32.
// ---------------------------------------------------------------------------
__global__ __launch_bounds__(256)
void z_kernel(const float* __restrict__ qp, const float* __restrict__ kv,
              const float* __restrict__ nf, float* __restrict__ z)
{
    const int lt = blockIdx.x;
    const int h = blockIdx.y;
    const int b = blockIdx.z;
    const int tid = threadIdx.x;
    const int tx = tid & 15;
    const int ty = tid >> 4;
    const int l0 = lt * 64;

    __shared__ float qsT[32][68];   // [k][l], row stride 68 floats = 16B aligned
    __shared__ float kvs[32][64];   // [k][d]

    const float* kvb = kv + (size_t)(b * H_ + h) * (2 * M_ * D_);

    float acc[4][4];
#pragma unroll
    for (int i = 0; i < 4; i++)
#pragma unroll
        for (int j = 0; j < 4; j++) acc[i][j] = 0.0f;

    for (int ko = 0; ko < 2 * M_; ko += 32) {
        // q tile: 64 l x 32 k  (512 float4, 2 per thread)
#pragma unroll
        for (int j = 0; j < 2; j++) {
            int i = tid * 2 + j;       // 0..511
            int lr = i >> 3;           // 0..63
            int kc = (i & 7) * 4;      // 0..28
            float4 qv = *(const float4*)(qp +
                ((size_t)(b * L_ + l0 + lr) * H_ + h) * (2 * M_) + ko + kc);
            qsT[kc + 0][lr] = qv.x;
            qsT[kc + 1][lr] = qv.y;
            qsT[kc + 2][lr] = qv.z;
            qsT[kc + 3][lr] = qv.w;
        }
        // kv tile: 32 k x 64 d (512 float4, 2 per thread)
#pragma unroll
        for (int j = 0; j < 2; j++) {
            int i = tid * 2 + j;       // 0..511
            int kr = i >> 4;           // 0..31
            int nc = (i & 15) * 4;     // 0..60
            *(float4*)(&kvs[kr][nc]) =
                *(const float4*)(kvb + (size_t)(ko + kr) * D_ + nc);
        }
        __syncthreads();

#pragma unroll
        for (int kk = 0; kk < 32; kk++) {
            float ra[4], rb[4];
            *(float4*)(ra) = *(float4*)(&qsT[kk][ty * 4]);
            *(float4*)(rb) = *(float4*)(&kvs[kk][tx * 4]);
#pragma unroll
            for (int i = 0; i < 4; i++)
#pragma unroll
                for (int j = 0; j < 4; j++)
                    acc[i][j] += ra[i] * rb[j];
        }
        __syncthreads();
    }

#pragma unroll
    for (int i = 0; i < 4; i++) {
        const int l = l0 + ty * 4 + i;
        const float f = nf[(size_t)(b * L_ + l) * H_ + h];
        float* op = z + ((size_t)(b * L_ + l) * H_ + h) * D_ + tx * 4;
        *(float4*)op = make_float4(acc[i][0] * f, acc[i][1] * f,
                                   acc[i][2] * f, acc[i][3] * f);
    }
}

// ---------------------------------------------------------------------------
extern "C" void kernel_launch(void* const* d_in, const int* in_sizes, int n_in,
                              void* d_out, int out_size)
{
    const float* x   = (const float*)d_in[0];
    const float* pft = (const float*)d_in[1];
    const float* psl = (const float*)d_in[2];
    const float* Wv  = (const float*)d_in[3];
    const float* Wo  = (const float*)d_in[4];
    const float* Wp  = (const float*)d_in[5];
    const float* sc  = (const float*)d_in[6];
    const float* ofs = (const float*)d_in[7];
    const float* prj = (const float*)d_in[8];
    float* out = (float*)d_out;

    float *pv, *ppp, *psp, *pqp, *pkp, *ppart, *pkv, *pz, *pnf;
    cudaGetSymbolAddress((void**)&pv,    g_v);
    cudaGetSymbolAddress((void**)&ppp,   g_pp);
    cudaGetSymbolAddress((void**)&psp,   g_sp);
    cudaGetSymbolAddress((void**)&pqp,   g_qp);
    cudaGetSymbolAddress((void**)&pkp,   g_kp);
    cudaGetSymbolAddress((void**)&ppart, g_part);
    cudaGetSymbolAddress((void**)&pkv,   g_kv);
    cudaGetSymbolAddress((void**)&pz,    g_z);
    cudaGetSymbolAddress((void**)&pnf,   g_nf);

    const int Mrows = B_ * L_;           // 16384
    dim3 gg(DM_ / 128, Mrows / 128);     // (8, 128)

    gemm128<<<gg, 256>>>(x,   Wv, pv,  Mrows, DM_, DM_);
    gemm128<<<gg, 256>>>(pft, Wp, ppp, Mrows, DM_, DM_);
    gemm128<<<gg, 256>>>(psl, Wp, psp, Mrows, DM_, DM_);

    feature_kernel<<<(B_ * L_ * H_) / 32, 128>>>(ppp, psp, prj, sc, ofs,
                                                 pqp, pkp, pnf);

    kv_partial_kernel<<<dim3(NCHUNK, H_, B_), 256>>>(pkp, pv, ppart);
    kv_reduce_kernel<<<(B_ * H_ * 2 * M_ * D_) / 256, 256>>>(ppart, pkv);

    z_kernel<<<dim3(L_ / 64, H_, B_), 256>>>(pqp, pkv, pnf, pz);

    gemm128<<<gg, 256>>>(pz, Wo, out, Mrows, DM_, DM_);
}

// round 4
// speedup vs baseline: 1.7196x; 1.7196x over previous
#include <cuda_runtime.h>
#include <cuda_fp16.h>
#include <cstdint>
#include <math.h>

// ---------------------------------------------------------------------------
// LinearSelfAttention — round 3: mma.sync (HMMA) split-fp16 GEMMs
//   (tcgen05 unavailable: harness PTX targets base sm_103, no 'a' features)
//   B=4, L=4096, H=16, D=64, M=128 (2M=256), D_MODEL=1024
// ---------------------------------------------------------------------------

#define B_ 4
#define L_ 4096
#define H_ 16
#define D_ 64
#define M_ 128
#define DM_ 1024
#define NCHUNK 32
#define LC_ (L_ / NCHUNK)

#define NORMALIZER 0.35355339059327373f
#define RATIO      0.08838834764831845f

// ----- fp32 scratch -----
__device__ float g_v   [(size_t)B_ * L_ * DM_];
__device__ float g_pp  [(size_t)B_ * L_ * DM_];
__device__ float g_sp  [(size_t)B_ * L_ * DM_];
__device__ float g_qp  [(size_t)B_ * L_ * H_ * 2 * M_];
__device__ float g_kp  [(size_t)B_ * L_ * H_ * 2 * M_];
__device__ float g_part[(size_t)B_ * H_ * NCHUNK * 2 * M_ * D_];
__device__ float g_z   [(size_t)B_ * L_ * DM_];
__device__ float g_nf  [(size_t)B_ * L_ * H_];
__device__ float g_kv  [(size_t)B_ * H_ * 2 * M_ * D_];

// ----- fp16 split scratch -----
#define NROW16 ((size_t)B_ * L_ * DM_)
__device__ __half g_x16h [NROW16];
__device__ __half g_x16l [NROW16];
__device__ __half g_p16h [NROW16];
__device__ __half g_p16l [NROW16];
__device__ __half g_s16h [NROW16];
__device__ __half g_s16l [NROW16];
__device__ __half g_z16h [NROW16];
__device__ __half g_z16l [NROW16];
__device__ __half g_WvTh [(size_t)DM_ * DM_];
__device__ __half g_WvTl [(size_t)DM_ * DM_];
__device__ __half g_WpTh [(size_t)DM_ * DM_];
__device__ __half g_WpTl [(size_t)DM_ * DM_];
__device__ __half g_WoTh [(size_t)DM_ * DM_];
__device__ __half g_WoTl [(size_t)DM_ * DM_];

// ===========================================================================
// PTX helpers (base sm_103 ISA only: cp.async / ldmatrix / mma.sync)
// ===========================================================================
__device__ __forceinline__ uint32_t smem_u32(const void* p) {
    uint32_t a;
    asm("{ .reg .u64 t; cvta.to.shared.u64 t, %1; cvt.u32.u64 %0, t; }"
        : "=r"(a) : "l"(p));
    return a;
}

__device__ __forceinline__ void ldmatrix_x4(uint32_t* r, uint32_t addr) {
    asm volatile("ldmatrix.sync.aligned.m8n8.x4.shared.b16 {%0,%1,%2,%3}, [%4];"
                 : "=r"(r[0]), "=r"(r[1]), "=r"(r[2]), "=r"(r[3]) : "r"(addr));
}
__device__ __forceinline__ void ldmatrix_x2(uint32_t* r, uint32_t addr) {
    asm volatile("ldmatrix.sync.aligned.m8n8.x2.shared.b16 {%0,%1}, [%2];"
                 : "=r"(r[0]), "=r"(r[1]) : "r"(addr));
}
__device__ __forceinline__ void mma16816(float* c, const uint32_t* a,
                                         const uint32_t* b) {
    asm volatile(
        "mma.sync.aligned.m16n8k16.row.col.f32.f16.f16.f32 "
        "{%0,%1,%2,%3}, {%4,%5,%6,%7}, {%8,%9}, {%0,%1,%2,%3};"
        : "+f"(c[0]), "+f"(c[1]), "+f"(c[2]), "+f"(c[3])
        : "r"(a[0]), "r"(a[1]), "r"(a[2]), "r"(a[3]), "r"(b[0]), "r"(b[1]));
}

// ===========================================================================
// tc_gemm3: C[M,N] = (A0+A1) @ (B0+B1)^T with 3 cross terms (fp32 accuracy).
// A*: [Mtot,K] fp16 K-major.  B*: [Nld,K] fp16 K-major (pre-transposed W).
// CTA tile 128x128, BK=64, 256 thr (8 warps of 64x32), 2-stage cp.async.
// ===========================================================================
#define TG_THREADS 256
#define KC_ 64
#define ROWB 144                       // 64 halves * 2B + 16B pad (conflict-free)
#define TB_ (128 * ROWB)               // 18432 B per tile buffer
#define STAGE_BYTES (4 * TB_)          // Ah, Al, Bh, Bl
#define TCG_SMEM (2 * STAGE_BYTES)     // 147456

__global__ __launch_bounds__(TG_THREADS, 1)
void tc_gemm3(const __half* __restrict__ A0, const __half* __restrict__ A1,
              const __half* __restrict__ B0, const __half* __restrict__ B1,
              float* __restrict__ C, int Mtot, int Nld, int K)
{
    extern __shared__ char smem[];
    const uint32_t sb = smem_u32(smem);
    const int tid = threadIdx.x;
    const int wid = tid >> 5;
    const int lane = tid & 31;
    const int wm = wid & 1;            // 2 warp rows  -> 64 m each
    const int wn = wid >> 1;           // 4 warp cols  -> 32 n each
    const int n0 = blockIdx.x * 128;
    const int m0 = blockIdx.y * 128;

    const __half* srcs[4] = {A0, A1, B0, B1};

    // per-lane ldmatrix offsets (bytes, within a tile buffer)
    // A/x4: row = base + ((lane>>3)&1)*8 + (lane&7), kcol8 = (lane>>4)*8
    const uint32_t a_off = (uint32_t)((((lane >> 3) & 1) * 8 + (lane & 7)) * ROWB
                                      + ((lane >> 4) * 8) * 2);
    // B/x2: row = base + (lane&7), kcol8 = ((lane>>3)&1)*8   (lanes 0..15 used)
    const int bl_ = lane & 15;
    const uint32_t b_off = (uint32_t)(((bl_ & 7)) * ROWB + (((bl_ >> 3) & 1) * 8) * 2);

    float acc[4][4][4];
#pragma unroll
    for (int i = 0; i < 4; i++)
#pragma unroll
        for (int j = 0; j < 4; j++)
#pragma unroll
            for (int q = 0; q < 4; q++) acc[i][j][q] = 0.0f;

    const int nch = K / KC_;

    // ---- stage loader ----
    auto load_stage = [&](int s, int chunk) {
        const int k0 = chunk * KC_;
        const uint32_t stage = sb + s * STAGE_BYTES;
#pragma unroll
        for (int buf = 0; buf < 4; buf++) {
            const __half* src = srcs[buf];
            const int r0 = (buf < 2) ? m0 : n0;
            const uint32_t tb = stage + buf * TB_;
#pragma unroll
            for (int j = 0; j < 4; j++) {
                const int c = tid + j * 256;          // 0..1023
                const int row = c >> 3;               // 0..127
                const int seg = c & 7;                // 16B segments
                const uint32_t dst = tb + (uint32_t)(row * ROWB + seg * 16);
                const __half* sp = src + (size_t)(r0 + row) * K + k0 + seg * 8;
                asm volatile("cp.async.cg.shared.global [%0], [%1], 16;\n"
                             :: "r"(dst), "l"(sp));
            }
        }
        asm volatile("cp.async.commit_group;\n");
    };

    load_stage(0, 0);

    for (int i = 0; i < nch; i++) {
        const int s = i & 1;
        if (i + 1 < nch) {
            load_stage(s ^ 1, i + 1);
            asm volatile("cp.async.wait_group 1;\n");
        } else {
            asm volatile("cp.async.wait_group 0;\n");
        }
        __syncthreads();

        const uint32_t stage = sb + s * STAGE_BYTES;
        const uint32_t Ah = stage + 0 * TB_;
        const uint32_t Al = stage + 1 * TB_;
        const uint32_t Bh = stage + 2 * TB_;
        const uint32_t Bl = stage + 3 * TB_;
        const uint32_t a_row = (uint32_t)(wm * 64 * ROWB);
        const uint32_t b_row = (uint32_t)(wn * 32 * ROWB);

#pragma unroll
        for (int kk = 0; kk < 4; kk++) {
            const uint32_t kb = (uint32_t)(kk * 32);   // kk*16 halves
            uint32_t ah[4][4], al[4][4], bh[4][2], bl2[4][2];
#pragma unroll
            for (int mf = 0; mf < 4; mf++) {
                const uint32_t ro = a_row + (uint32_t)(mf * 16 * ROWB) + kb + a_off;
                ldmatrix_x4(ah[mf], Ah + ro);
                ldmatrix_x4(al[mf], Al + ro);
            }
#pragma unroll
            for (int nf = 0; nf < 4; nf++) {
                const uint32_t ro = b_row + (uint32_t)(nf * 8 * ROWB) + kb + b_off;
                ldmatrix_x2(bh[nf], Bh + ro);
                ldmatrix_x2(bl2[nf], Bl + ro);
            }
#pragma unroll
            for (int mf = 0; mf < 4; mf++)
#pragma unroll
                for (int nf = 0; nf < 4; nf++) {
                    mma16816(acc[mf][nf], ah[mf], bh[nf]);
                    mma16816(acc[mf][nf], ah[mf], bl2[nf]);
                    mma16816(acc[mf][nf], al[mf], bh[nf]);
                }
        }
        __syncthreads();
    }

    // ---- epilogue: direct global store ----
    const int mrow = lane >> 2;            // 0..7
    const int ncol = (lane & 3) * 2;       // 0,2,4,6
#pragma unroll
    for (int mf = 0; mf < 4; mf++) {
        const int gm = m0 + wm * 64 + mf * 16 + mrow;
#pragma unroll
        for (int nf = 0; nf < 4; nf++) {
            const int gn = n0 + wn * 32 + nf * 8 + ncol;
            float2 v0 = make_float2(acc[mf][nf][0], acc[mf][nf][1]);
            float2 v1 = make_float2(acc[mf][nf][2], acc[mf][nf][3]);
            *(float2*)(C + (size_t)gm * Nld + gn) = v0;
            *(float2*)(C + (size_t)(gm + 8) * Nld + gn) = v1;
        }
    }
}

// ===========================================================================
// split fp32 -> (hi, lo) fp16
// ===========================================================================
__global__ __launch_bounds__(256)
void split2_kernel(const float* __restrict__ src, __half* __restrict__ hi,
                   __half* __restrict__ lo)
{
    const size_t i0 = ((size_t)blockIdx.x * 256 + threadIdx.x) * 4;
    float4 v = *(const float4*)(src + i0);
    float f[4] = {v.x, v.y, v.z, v.w};
    __half2 h2[2], l2[2];
#pragma unroll
    for (int j = 0; j < 2; j++) {
        __half ha = __float2half_rn(f[j * 2]);
        __half hb = __float2half_rn(f[j * 2 + 1]);
        h2[j] = __halves2half2(ha, hb);
        l2[j] = __halves2half2(__float2half_rn(f[j * 2] - __half2float(ha)),
                               __float2half_rn(f[j * 2 + 1] - __half2float(hb)));
    }
    *(__half2*)(hi + i0)     = h2[0];
    *(__half2*)(hi + i0 + 2) = h2[1];
    *(__half2*)(lo + i0)     = l2[0];
    *(__half2*)(lo + i0 + 2) = l2[1];
}

// transpose [K,N] fp32 -> [N,K] fp16 hi/lo
__global__ __launch_bounds__(256)
void wtrans_split_kernel(const float* __restrict__ W, __half* __restrict__ th,
                         __half* __restrict__ tl)
{
    __shared__ float tile[32][33];
    const int tx = threadIdx.x & 31;
    const int ty = threadIdx.x >> 5;
    const int n0 = blockIdx.x * 32;
    const int k0 = blockIdx.y * 32;
#pragma unroll
    for (int i = 0; i < 4; i++)
        tile[ty + i * 8][tx] = W[(size_t)(k0 + ty + i * 8) * DM_ + n0 + tx];
    __syncthreads();
#pragma unroll
    for (int i = 0; i < 4; i++) {
        const int n = ty + i * 8;
        float v = tile[tx][n];
        __half h = __float2half_rn(v);
        const size_t o = (size_t)(n0 + n) * DM_ + k0 + tx;
        th[o] = h;
        tl[o] = __float2half_rn(v - __half2float(h));
    }
}

// ===========================================================================
// feature / kv / z kernels (unchanged — known correct)
// ===========================================================================
__global__ __launch_bounds__(128)
void feature_kernel(const float* __restrict__ pp, const float* __restrict__ sp,
                    const float* __restrict__ proj,
                    const float* __restrict__ scale, const float* __restrict__ offs,
                    float* __restrict__ qp, float* __restrict__ kp,
                    float* __restrict__ nf)
{
    __shared__ float projT[64][129];
    __shared__ float qpos[64];
    __shared__ float kpos[64];
    __shared__ float spsq[64];

    const int tid = threadIdx.x;
#pragma unroll
    for (int i = tid; i < M_ * D_; i += 128) {
        int m = i >> 6;
        int d = i & 63;
        projT[d][m] = proj[i];
    }
    const int r0 = blockIdx.x * 32;
    for (int rr = 0; rr < 32; rr++) {
        const int r = r0 + rr;
        const int h = r & (H_ - 1);
        const float s = scale[h];
        const float off = offs[h];
        __syncthreads();
        if (tid < 64) {
            float p = pp[(size_t)r * 64 + tid];
            qpos[tid] = s * p;
        } else {
            int d = tid - 64;
            float p = pp[(size_t)r * 64 + d];
            float sl = sp[(size_t)r * 64 + d];
            kpos[d] = s * (p + off * sl);
            spsq[d] = sl * sl;
        }
        __syncthreads();
        float dq = 0.0f, dk = 0.0f;
#pragma unroll
        for (int d = 0; d < 64; d++) {
            float pj = projT[d][tid];
            dq += qpos[d] * pj;
            dk += kpos[d] * pj;
        }
        dq *= NORMALIZER;
        dk *= NORMALIZER;
        float sq, cq, sk, ck;
        __sincosf(dq, &sq, &cq);
        __sincosf(dk, &sk, &ck);
        const size_t base = (size_t)r * (2 * M_);
        qp[base + tid]      = RATIO * sq;
        qp[base + M_ + tid] = RATIO * cq;
        kp[base + tid]      = RATIO * sk;
        kp[base + M_ + tid] = RATIO * ck;
        if (tid < 32) {
            float v2 = spsq[tid] + spsq[tid + 32];
#pragma unroll
            for (int o = 16; o; o >>= 1)
                v2 += __shfl_down_sync(0xffffffffu, v2, o);
            if (tid == 0) nf[r] = sqrtf(v2) * (1.0f / (float)L_);
        }
    }
}

__global__ __launch_bounds__(256)
void kv_partial_kernel(const float* __restrict__ kp, const float* __restrict__ v,
                       float* __restrict__ part)
{
    const int chunk = blockIdx.x;
    const int h = blockIdx.y;
    const int b = blockIdx.z;
    const int tid = threadIdx.x;
    const int td = tid & 7;
    const int tm = tid >> 3;
    const int d0 = td * 8;
    const int m0 = tm * 8;
    __shared__ float ks[2 * M_];
    __shared__ float vs[D_];
    float acc[8][8];
#pragma unroll
    for (int i = 0; i < 8; i++)
#pragma unroll
        for (int j = 0; j < 8; j++) acc[i][j] = 0.0f;
    const int l0 = chunk * LC_;
    for (int l = l0; l < l0 + LC_; l++) {
        const size_t rbase = ((size_t)(b * L_ + l) * H_ + h);
        ks[tid] = kp[rbase * (2 * M_) + tid];
        if (tid < D_) vs[tid] = v[rbase * D_ + tid];
        __syncthreads();
        float rm[8], rd[8];
        *(float4*)(rm)     = *(float4*)(&ks[m0]);
        *(float4*)(rm + 4) = *(float4*)(&ks[m0 + 4]);
        *(float4*)(rd)     = *(float4*)(&vs[d0]);
        *(float4*)(rd + 4) = *(float4*)(&vs[d0 + 4]);
#pragma unroll
        for (int i = 0; i < 8; i++)
#pragma unroll
            for (int j = 0; j < 8; j++)
                acc[i][j] += rm[i] * rd[j];
        __syncthreads();
    }
    const size_t pbase = ((size_t)((b * H_ + h) * NCHUNK + chunk)) * (2 * M_ * D_);
#pragma unroll
    for (int i = 0; i < 8; i++) {
        float* op = part + pbase + (size_t)(m0 + i) * D_ + d0;
        *(float4*)(op)     = make_float4(acc[i][0], acc[i][1], acc[i][2], acc[i][3]);
        *(float4*)(op + 4) = make_float4(acc[i][4], acc[i][5], acc[i][6], acc[i][7]);
    }
}

__global__ __launch_bounds__(256)
void kv_reduce_kernel(const float* __restrict__ part, float* __restrict__ kv)
{
    const int idx = blockIdx.x * 256 + threadIdx.x;
    const int bh = idx / (2 * M_ * D_);
    const int md = idx % (2 * M_ * D_);
    float s = 0.0f;
#pragma unroll
    for (int c = 0; c < NCHUNK; c++)
        s += part[((size_t)bh * NCHUNK + c) * (2 * M_ * D_) + md];
    kv[idx] = s;
}

__global__ __launch_bounds__(256)
void z_kernel(const float* __restrict__ qp, const float* __restrict__ kv,
              const float* __restrict__ nf, float* __restrict__ z)
{
    const int lt = blockIdx.x;
    const int h = blockIdx.y;
    const int b = blockIdx.z;
    const int tid = threadIdx.x;
    const int tx = tid & 15;
    const int ty = tid >> 4;
    const int l0 = lt * 64;
    __shared__ float qsT[32][68];
    __shared__ float kvs[32][64];
    const float* kvb = kv + (size_t)(b * H_ + h) * (2 * M_ * D_);
    float acc[4][4];
#pragma unroll
    for (int i = 0; i < 4; i++)
#pragma unroll
        for (int j = 0; j < 4; j++) acc[i][j] = 0.0f;
    for (int ko = 0; ko < 2 * M_; ko += 32) {
#pragma unroll
        for (int j = 0; j < 2; j++) {
            int i = tid * 2 + j;
            int lr = i >> 3;
            int kc = (i & 7) * 4;
            float4 qv = *(const float4*)(qp +
                ((size_t)(b * L_ + l0 + lr) * H_ + h) * (2 * M_) + ko + kc);
            qsT[kc + 0][lr] = qv.x;
            qsT[kc + 1][lr] = qv.y;
            qsT[kc + 2][lr] = qv.z;
            qsT[kc + 3][lr] = qv.w;
        }
#pragma unroll
        for (int j = 0; j < 2; j++) {
            int i = tid * 2 + j;
            int kr = i >> 4;
            int nc = (i & 15) * 4;
            *(float4*)(&kvs[kr][nc]) =
                *(const float4*)(kvb + (size_t)(ko + kr) * D_ + nc);
        }
        __syncthreads();
#pragma unroll
        for (int kk = 0; kk < 32; kk++) {
            float ra[4], rb[4];
            *(float4*)(ra) = *(float4*)(&qsT[kk][ty * 4]);
            *(float4*)(rb) = *(float4*)(&kvs[kk][tx * 4]);
#pragma unroll
            for (int i = 0; i < 4; i++)
#pragma unroll
                for (int j = 0; j < 4; j++)
                    acc[i][j] += ra[i] * rb[j];
        }
        __syncthreads();
    }
#pragma unroll
    for (int i = 0; i < 4; i++) {
        const int l = l0 + ty * 4 + i;
        const float f = nf[(size_t)(b * L_ + l) * H_ + h];
        float* op = z + ((size_t)(b * L_ + l) * H_ + h) * D_ + tx * 4;
        *(float4*)op = make_float4(acc[i][0] * f, acc[i][1] * f,
                                   acc[i][2] * f, acc[i][3] * f);
    }
}

// ===========================================================================
extern "C" void kernel_launch(void* const* d_in, const int* in_sizes, int n_in,
                              void* d_out, int out_size)
{
    const float* x   = (const float*)d_in[0];
    const float* pft = (const float*)d_in[1];
    const float* psl = (const float*)d_in[2];
    const float* Wv  = (const float*)d_in[3];
    const float* Wo  = (const float*)d_in[4];
    const float* Wp  = (const float*)d_in[5];
    const float* sc  = (const float*)d_in[6];
    const float* ofs = (const float*)d_in[7];
    const float* prj = (const float*)d_in[8];
    float* out = (float*)d_out;

    float *pv, *ppp, *psp, *pqp, *pkp, *ppart, *pkv, *pz, *pnf;
    cudaGetSymbolAddress((void**)&pv,    g_v);
    cudaGetSymbolAddress((void**)&ppp,   g_pp);
    cudaGetSymbolAddress((void**)&psp,   g_sp);
    cudaGetSymbolAddress((void**)&pqp,   g_qp);
    cudaGetSymbolAddress((void**)&pkp,   g_kp);
    cudaGetSymbolAddress((void**)&ppart, g_part);
    cudaGetSymbolAddress((void**)&pkv,   g_kv);
    cudaGetSymbolAddress((void**)&pz,    g_z);
    cudaGetSymbolAddress((void**)&pnf,   g_nf);

    __half *xh, *xl, *ph, *pl, *sh, *sl, *zh, *zl;
    __half *wvh, *wvl, *wph, *wpl, *woh, *wol;
    cudaGetSymbolAddress((void**)&xh,  g_x16h);
    cudaGetSymbolAddress((void**)&xl,  g_x16l);
    cudaGetSymbolAddress((void**)&ph,  g_p16h);
    cudaGetSymbolAddress((void**)&pl,  g_p16l);
    cudaGetSymbolAddress((void**)&sh,  g_s16h);
    cudaGetSymbolAddress((void**)&sl,  g_s16l);
    cudaGetSymbolAddress((void**)&zh,  g_z16h);
    cudaGetSymbolAddress((void**)&zl,  g_z16l);
    cudaGetSymbolAddress((void**)&wvh, g_WvTh);
    cudaGetSymbolAddress((void**)&wvl, g_WvTl);
    cudaGetSymbolAddress((void**)&wph, g_WpTh);
    cudaGetSymbolAddress((void**)&wpl, g_WpTl);
    cudaGetSymbolAddress((void**)&woh, g_WoTh);
    cudaGetSymbolAddress((void**)&wol, g_WoTl);

    cudaFuncSetAttribute(tc_gemm3, cudaFuncAttributeMaxDynamicSharedMemorySize,
                         TCG_SMEM);

    const int Mrows = B_ * L_;                       // 16384
    const int nsplit = (int)(NROW16 / 1024);

    split2_kernel<<<nsplit, 256>>>(x,   xh, xl);
    split2_kernel<<<nsplit, 256>>>(pft, ph, pl);
    split2_kernel<<<nsplit, 256>>>(psl, sh, sl);
    dim3 wg(DM_ / 32, DM_ / 32);
    wtrans_split_kernel<<<wg, 256>>>(Wv, wvh, wvl);
    wtrans_split_kernel<<<wg, 256>>>(Wp, wph, wpl);
    wtrans_split_kernel<<<wg, 256>>>(Wo, woh, wol);

    dim3 gg(DM_ / 128, Mrows / 128);                 // (8, 128)
    tc_gemm3<<<gg, TG_THREADS, TCG_SMEM>>>(xh, xl, wvh, wvl, pv,  Mrows, DM_, DM_);
    tc_gemm3<<<gg, TG_THREADS, TCG_SMEM>>>(ph, pl, wph, wpl, ppp, Mrows, DM_, DM_);
    tc_gemm3<<<gg, TG_THREADS, TCG_SMEM>>>(sh, sl, wph, wpl, psp, Mrows, DM_, DM_);

    feature_kernel<<<(B_ * L_ * H_) / 32, 128>>>(ppp, psp, prj, sc, ofs,
                                                 pqp, pkp, pnf);

    kv_partial_kernel<<<dim3(NCHUNK, H_, B_), 256>>>(pkp, pv, ppart);
    kv_reduce_kernel<<<(B_ * H_ * 2 * M_ * D_) / 256, 256>>>(ppart, pkv);

    z_kernel<<<dim3(L_ / 64, H_, B_), 256>>>(pqp, pkv, pnf, pz);

    split2_kernel<<<nsplit, 256>>>(pz, zh, zl);
    tc_gemm3<<<gg, TG_THREADS, TCG_SMEM>>>(zh, zl, woh, wol, out, Mrows, DM_, DM_);
}

// round 5
// speedup vs baseline: 2.1974x; 1.2778x over previous
#include <cuda_runtime.h>
#include <cuda_fp16.h>
#include <cstdint>
#include <math.h>

// ---------------------------------------------------------------------------
// LinearSelfAttention — round 5: HMMA split-fp16 GEMMs + rewritten feature
// path (tiled per-head GEMM, fused sincos) + staged kv accumulation.
//   B=4, L=4096, H=16, D=64, M=128 (2M=256), D_MODEL=1024
// ---------------------------------------------------------------------------

#define B_ 4
#define L_ 4096
#define H_ 16
#define D_ 64
#define M_ 128
#define DM_ 1024
#define NCHUNK 8
#define LC_ (L_ / NCHUNK)    // 512

#define NORMALIZER 0.35355339059327373f
#define RATIO      0.08838834764831845f

// ----- fp32 scratch -----
__device__ float g_v   [(size_t)B_ * L_ * DM_];
__device__ float g_pp  [(size_t)B_ * L_ * DM_];
__device__ float g_sp  [(size_t)B_ * L_ * DM_];
__device__ float g_qp  [(size_t)B_ * L_ * H_ * 2 * M_];
__device__ float g_kp  [(size_t)B_ * L_ * H_ * 2 * M_];
__device__ float g_part[(size_t)B_ * H_ * NCHUNK * 2 * M_ * D_];
__device__ float g_z   [(size_t)B_ * L_ * DM_];
__device__ float g_nf  [(size_t)B_ * L_ * H_];
__device__ float g_kv  [(size_t)B_ * H_ * 2 * M_ * D_];

// ----- fp16 split scratch -----
#define NROW16 ((size_t)B_ * L_ * DM_)
__device__ __half g_x16h [NROW16];
__device__ __half g_x16l [NROW16];
__device__ __half g_p16h [NROW16];
__device__ __half g_p16l [NROW16];
__device__ __half g_s16h [NROW16];
__device__ __half g_s16l [NROW16];
__device__ __half g_z16h [NROW16];
__device__ __half g_z16l [NROW16];
__device__ __half g_WvTh [(size_t)DM_ * DM_];
__device__ __half g_WvTl [(size_t)DM_ * DM_];
__device__ __half g_WpTh [(size_t)DM_ * DM_];
__device__ __half g_WpTl [(size_t)DM_ * DM_];
__device__ __half g_WoTh [(size_t)DM_ * DM_];
__device__ __half g_WoTl [(size_t)DM_ * DM_];

// ===========================================================================
// PTX helpers (base sm_103 ISA only: cp.async / ldmatrix / mma.sync)
// ===========================================================================
__device__ __forceinline__ uint32_t smem_u32(const void* p) {
    uint32_t a;
    asm("{ .reg .u64 t; cvta.to.shared.u64 t, %1; cvt.u32.u64 %0, t; }"
        : "=r"(a) : "l"(p));
    return a;
}
__device__ __forceinline__ void ldmatrix_x4(uint32_t* r, uint32_t addr) {
    asm volatile("ldmatrix.sync.aligned.m8n8.x4.shared.b16 {%0,%1,%2,%3}, [%4];"
                 : "=r"(r[0]), "=r"(r[1]), "=r"(r[2]), "=r"(r[3]) : "r"(addr));
}
__device__ __forceinline__ void ldmatrix_x2(uint32_t* r, uint32_t addr) {
    asm volatile("ldmatrix.sync.aligned.m8n8.x2.shared.b16 {%0,%1}, [%2];"
                 : "=r"(r[0]), "=r"(r[1]) : "r"(addr));
}
__device__ __forceinline__ void mma16816(float* c, const uint32_t* a,
                                         const uint32_t* b) {
    asm volatile(
        "mma.sync.aligned.m16n8k16.row.col.f32.f16.f16.f32 "
        "{%0,%1,%2,%3}, {%4,%5,%6,%7}, {%8,%9}, {%0,%1,%2,%3};"
        : "+f"(c[0]), "+f"(c[1]), "+f"(c[2]), "+f"(c[3])
        : "r"(a[0]), "r"(a[1]), "r"(a[2]), "r"(a[3]), "r"(b[0]), "r"(b[1]));
}

// ===========================================================================
// tc_gemm3 (unchanged from round 4 — at HMMA ceiling)
// ===========================================================================
#define TG_THREADS 256
#define KC_ 64
#define ROWB 144
#define TB_ (128 * ROWB)
#define STAGE_BYTES (4 * TB_)
#define TCG_SMEM (2 * STAGE_BYTES)

__global__ __launch_bounds__(TG_THREADS, 1)
void tc_gemm3(const __half* __restrict__ A0, const __half* __restrict__ A1,
              const __half* __restrict__ B0, const __half* __restrict__ B1,
              float* __restrict__ C, int Mtot, int Nld, int K)
{
    extern __shared__ char smem[];
    const uint32_t sb = smem_u32(smem);
    const int tid = threadIdx.x;
    const int wid = tid >> 5;
    const int lane = tid & 31;
    const int wm = wid & 1;
    const int wn = wid >> 1;
    const int n0 = blockIdx.x * 128;
    const int m0 = blockIdx.y * 128;

    const __half* srcs[4] = {A0, A1, B0, B1};

    const uint32_t a_off = (uint32_t)((((lane >> 3) & 1) * 8 + (lane & 7)) * ROWB
                                      + ((lane >> 4) * 8) * 2);
    const int bl_ = lane & 15;
    const uint32_t b_off = (uint32_t)(((bl_ & 7)) * ROWB + (((bl_ >> 3) & 1) * 8) * 2);

    float acc[4][4][4];
#pragma unroll
    for (int i = 0; i < 4; i++)
#pragma unroll
        for (int j = 0; j < 4; j++)
#pragma unroll
            for (int q = 0; q < 4; q++) acc[i][j][q] = 0.0f;

    const int nch = K / KC_;

    auto load_stage = [&](int s, int chunk) {
        const int k0 = chunk * KC_;
        const uint32_t stage = sb + s * STAGE_BYTES;
#pragma unroll
        for (int buf = 0; buf < 4; buf++) {
            const __half* src = srcs[buf];
            const int r0 = (buf < 2) ? m0 : n0;
            const uint32_t tb = stage + buf * TB_;
#pragma unroll
            for (int j = 0; j < 4; j++) {
                const int c = tid + j * 256;
                const int row = c >> 3;
                const int seg = c & 7;
                const uint32_t dst = tb + (uint32_t)(row * ROWB + seg * 16);
                const __half* sp = src + (size_t)(r0 + row) * K + k0 + seg * 8;
                asm volatile("cp.async.cg.shared.global [%0], [%1], 16;\n"
                             :: "r"(dst), "l"(sp));
            }
        }
        asm volatile("cp.async.commit_group;\n");
    };

    load_stage(0, 0);

    for (int i = 0; i < nch; i++) {
        const int s = i & 1;
        if (i + 1 < nch) {
            load_stage(s ^ 1, i + 1);
            asm volatile("cp.async.wait_group 1;\n");
        } else {
            asm volatile("cp.async.wait_group 0;\n");
        }
        __syncthreads();

        const uint32_t stage = sb + s * STAGE_BYTES;
        const uint32_t Ah = stage + 0 * TB_;
        const uint32_t Al = stage + 1 * TB_;
        const uint32_t Bh = stage + 2 * TB_;
        const uint32_t Bl = stage + 3 * TB_;
        const uint32_t a_row = (uint32_t)(wm * 64 * ROWB);
        const uint32_t b_row = (uint32_t)(wn * 32 * ROWB);

#pragma unroll
        for (int kk = 0; kk < 4; kk++) {
            const uint32_t kb = (uint32_t)(kk * 32);
            uint32_t ah[4][4], al[4][4], bh[4][2], bl2[4][2];
#pragma unroll
            for (int mf = 0; mf < 4; mf++) {
                const uint32_t ro = a_row + (uint32_t)(mf * 16 * ROWB) + kb + a_off;
                ldmatrix_x4(ah[mf], Ah + ro);
                ldmatrix_x4(al[mf], Al + ro);
            }
#pragma unroll
            for (int nf = 0; nf < 4; nf++) {
                const uint32_t ro = b_row + (uint32_t)(nf * 8 * ROWB) + kb + b_off;
                ldmatrix_x2(bh[nf], Bh + ro);
                ldmatrix_x2(bl2[nf], Bl + ro);
            }
#pragma unroll
            for (int mf = 0; mf < 4; mf++)
#pragma unroll
                for (int nf = 0; nf < 4; nf++) {
                    mma16816(acc[mf][nf], ah[mf], bh[nf]);
                    mma16816(acc[mf][nf], ah[mf], bl2[nf]);
                    mma16816(acc[mf][nf], al[mf], bh[nf]);
                }
        }
        __syncthreads();
    }

    const int mrow = lane >> 2;
    const int ncol = (lane & 3) * 2;
#pragma unroll
    for (int mf = 0; mf < 4; mf++) {
        const int gm = m0 + wm * 64 + mf * 16 + mrow;
#pragma unroll
        for (int nf = 0; nf < 4; nf++) {
            const int gn = n0 + wn * 32 + nf * 8 + ncol;
            float2 v0 = make_float2(acc[mf][nf][0], acc[mf][nf][1]);
            float2 v1 = make_float2(acc[mf][nf][2], acc[mf][nf][3]);
            *(float2*)(C + (size_t)gm * Nld + gn) = v0;
            *(float2*)(C + (size_t)(gm + 8) * Nld + gn) = v1;
        }
    }
}

// ===========================================================================
// split fp32 -> (hi, lo) fp16
// ===========================================================================
__global__ __launch_bounds__(256)
void split2_kernel(const float* __restrict__ src, __half* __restrict__ hi,
                   __half* __restrict__ lo)
{
    const size_t i0 = ((size_t)blockIdx.x * 256 + threadIdx.x) * 4;
    float4 v = *(const float4*)(src + i0);
    float f[4] = {v.x, v.y, v.z, v.w};
    __half2 h2[2], l2[2];
#pragma unroll
    for (int j = 0; j < 2; j++) {
        __half ha = __float2half_rn(f[j * 2]);
        __half hb = __float2half_rn(f[j * 2 + 1]);
        h2[j] = __halves2half2(ha, hb);
        l2[j] = __halves2half2(__float2half_rn(f[j * 2] - __half2float(ha)),
                               __float2half_rn(f[j * 2 + 1] - __half2float(hb)));
    }
    *(__half2*)(hi + i0)     = h2[0];
    *(__half2*)(hi + i0 + 2) = h2[1];
    *(__half2*)(lo + i0)     = l2[0];
    *(__half2*)(lo + i0 + 2) = l2[1];
}

__global__ __launch_bounds__(256)
void wtrans_split_kernel(const float* __restrict__ W, __half* __restrict__ th,
                         __half* __restrict__ tl)
{
    __shared__ float tile[32][33];
    const int tx = threadIdx.x & 31;
    const int ty = threadIdx.x >> 5;
    const int n0 = blockIdx.x * 32;
    const int k0 = blockIdx.y * 32;
#pragma unroll
    for (int i = 0; i < 4; i++)
        tile[ty + i * 8][tx] = W[(size_t)(k0 + ty + i * 8) * DM_ + n0 + tx];
    __syncthreads();
#pragma unroll
    for (int i = 0; i < 4; i++) {
        const int n = ty + i * 8;
        float v = tile[tx][n];
        __half h = __float2half_rn(v);
        const size_t o = (size_t)(n0 + n) * DM_ + k0 + tx;
        th[o] = h;
        tl[o] = __float2half_rn(v - __half2float(h));
    }
}

// ===========================================================================
// feat2: per-head tiled feature GEMM + fused sincos + norm factor.
// grid (BL/128, H), 256 threads. Block computes 128 rows x 128 m for head h.
// Dynamic smem: qpos[128][65] | kpos[128][65] | projT[64][132]
// ===========================================================================
#define FQP(r, d)  sm[(r) * 65 + (d)]
#define FKP(r, d)  sm[128 * 65 + (r) * 65 + (d)]
#define FPJ(d, m)  sm[2 * 128 * 65 + (d) * 132 + (m)]
#define FEAT_SMEM  ((2 * 128 * 65 + 64 * 132) * 4)   // 100352 B

__global__ __launch_bounds__(256)
void feat2_kernel(const float* __restrict__ pp, const float* __restrict__ sp,
                  const float* __restrict__ proj,
                  const float* __restrict__ scale, const float* __restrict__ offs,
                  float* __restrict__ qp, float* __restrict__ kp,
                  float* __restrict__ nf)
{
    extern __shared__ float sm[];
    __shared__ float nfp[256];

    const int tid = threadIdx.x;
    const int h = blockIdx.y;
    const int r0 = blockIdx.x * 128;       // row offset within B*L
    const float s = scale[h];
    const float off = offs[h];

    // ---- load proj [128m x 64d] -> projT[d][m] ----
#pragma unroll
    for (int i = tid; i < M_ * D_ / 4; i += 256) {   // 2048 float4
        const int m = i >> 4;
        const int dseg = (i & 15) * 4;
        float4 pv = *(const float4*)(proj + (size_t)m * 64 + dseg);
        FPJ(dseg + 0, m) = pv.x;
        FPJ(dseg + 1, m) = pv.y;
        FPJ(dseg + 2, m) = pv.z;
        FPJ(dseg + 3, m) = pv.w;
    }

    // ---- load pp/sp tiles, build qpos/kpos, partial ||sp||^2 ----
    {
        const int r = tid >> 1;             // 0..127
        const int hf = tid & 1;             // 0..1 -> d in [hf*32, hf*32+32)
        const size_t g = (size_t)(r0 + r) * DM_ + h * 64 + hf * 32;
        float s2 = 0.0f;
#pragma unroll
        for (int j = 0; j < 8; j++) {
            float4 p  = *(const float4*)(pp + g + j * 4);
            float4 sl = *(const float4*)(sp + g + j * 4);
            const int d = hf * 32 + j * 4;
            FQP(r, d + 0) = s * p.x;
            FQP(r, d + 1) = s * p.y;
            FQP(r, d + 2) = s * p.z;
            FQP(r, d + 3) = s * p.w;
            FKP(r, d + 0) = s * (p.x + off * sl.x);
            FKP(r, d + 1) = s * (p.y + off * sl.y);
            FKP(r, d + 2) = s * (p.z + off * sl.z);
            FKP(r, d + 3) = s * (p.w + off * sl.w);
            s2 += sl.x * sl.x + sl.y * sl.y + sl.z * sl.z + sl.w * sl.w;
        }
        nfp[tid] = s2;
    }
    __syncthreads();

    if (tid < 128) {
        const float v2 = nfp[tid * 2] + nfp[tid * 2 + 1];
        nf[(size_t)(r0 + tid) * H_ + h] = sqrtf(v2) * (1.0f / (float)L_);
    }

    // ---- GEMM phase: rows 8 per thread, m 4 per thread, 2 m-half passes ----
    const int tm = tid & 15;                // m lane
    const int tr = tid >> 4;                // 0..15 -> rows tr*8..+7
    const int rb = tr * 8;

#pragma unroll
    for (int mh = 0; mh < 2; mh++) {
        float aq[8][4], ak[8][4];
#pragma unroll
        for (int i = 0; i < 8; i++)
#pragma unroll
            for (int j = 0; j < 4; j++) { aq[i][j] = 0.0f; ak[i][j] = 0.0f; }

#pragma unroll 4
        for (int d = 0; d < 64; d++) {
            float pj[4];
#pragma unroll
            for (int j = 0; j < 4; j++)
                pj[j] = FPJ(d, mh * 64 + tm + j * 16);
#pragma unroll
            for (int i = 0; i < 8; i++) {
                const float rq = FQP(rb + i, d);
                const float rk = FKP(rb + i, d);
#pragma unroll
                for (int j = 0; j < 4; j++) {
                    aq[i][j] += rq * pj[j];
                    ak[i][j] += rk * pj[j];
                }
            }
        }

#pragma unroll
        for (int i = 0; i < 8; i++) {
            const size_t base = ((size_t)(r0 + rb + i) * H_ + h) * (2 * M_);
#pragma unroll
            for (int j = 0; j < 4; j++) {
                const int m = mh * 64 + tm + j * 16;
                float sq, cq, sk, ck;
                __sincosf(NORMALIZER * aq[i][j], &sq, &cq);
                __sincosf(NORMALIZER * ak[i][j], &sk, &ck);
                qp[base + m]      = RATIO * sq;
                qp[base + M_ + m] = RATIO * cq;
                kp[base + m]      = RATIO * sk;
                kp[base + M_ + m] = RATIO * ck;
            }
        }
    }
}

// ===========================================================================
// kv partial: per (b,h,chunk) accumulate k'[l,m]*v[l,d]; 4 rows per barrier.
// ===========================================================================
__global__ __launch_bounds__(256)
void kv_partial_kernel(const float* __restrict__ kp, const float* __restrict__ v,
                       float* __restrict__ part)
{
    const int chunk = blockIdx.x;
    const int h = blockIdx.y;
    const int b = blockIdx.z;
    const int tid = threadIdx.x;
    const int td = tid & 7;
    const int tm = tid >> 3;
    const int d0 = td * 8;
    const int m0 = tm * 8;
    __shared__ float ks[4][2 * M_];
    __shared__ float vs[4][D_];
    float acc[8][8];
#pragma unroll
    for (int i = 0; i < 8; i++)
#pragma unroll
        for (int j = 0; j < 8; j++) acc[i][j] = 0.0f;

    const int l0 = chunk * LC_;
    for (int lg = l0; lg < l0 + LC_; lg += 4) {
#pragma unroll
        for (int u = 0; u < 4; u++)
            ks[u][tid] = kp[((size_t)(b * L_ + lg + u) * H_ + h) * (2 * M_) + tid];
        vs[tid >> 6][tid & 63] =
            v[((size_t)(b * L_ + lg + (tid >> 6)) * H_ + h) * D_ + (tid & 63)];
        __syncthreads();
#pragma unroll
        for (int u = 0; u < 4; u++) {
            float rm[8], rd[8];
            *(float4*)(rm)     = *(float4*)(&ks[u][m0]);
            *(float4*)(rm + 4) = *(float4*)(&ks[u][m0 + 4]);
            *(float4*)(rd)     = *(float4*)(&vs[u][d0]);
            *(float4*)(rd + 4) = *(float4*)(&vs[u][d0 + 4]);
#pragma unroll
            for (int i = 0; i < 8; i++)
#pragma unroll
                for (int j = 0; j < 8; j++)
                    acc[i][j] += rm[i] * rd[j];
        }
        __syncthreads();
    }

    const size_t pbase = ((size_t)((b * H_ + h) * NCHUNK + chunk)) * (2 * M_ * D_);
#pragma unroll
    for (int i = 0; i < 8; i++) {
        float* op = part + pbase + (size_t)(m0 + i) * D_ + d0;
        *(float4*)(op)     = make_float4(acc[i][0], acc[i][1], acc[i][2], acc[i][3]);
        *(float4*)(op + 4) = make_float4(acc[i][4], acc[i][5], acc[i][6], acc[i][7]);
    }
}

__global__ __launch_bounds__(256)
void kv_reduce_kernel(const float* __restrict__ part, float* __restrict__ kv)
{
    const int idx = blockIdx.x * 256 + threadIdx.x;
    const int bh = idx / (2 * M_ * D_);
    const int md = idx % (2 * M_ * D_);
    float s = 0.0f;
#pragma unroll
    for (int c = 0; c < NCHUNK; c++)
        s += part[((size_t)bh * NCHUNK + c) * (2 * M_ * D_) + md];
    kv[idx] = s;
}

__global__ __launch_bounds__(256)
void z_kernel(const float* __restrict__ qp, const float* __restrict__ kv,
              const float* __restrict__ nf, float* __restrict__ z)
{
    const int lt = blockIdx.x;
    const int h = blockIdx.y;
    const int b = blockIdx.z;
    const int tid = threadIdx.x;
    const int tx = tid & 15;
    const int ty = tid >> 4;
    const int l0 = lt * 64;
    __shared__ float qsT[32][68];
    __shared__ float kvs[32][64];
    const float* kvb = kv + (size_t)(b * H_ + h) * (2 * M_ * D_);
    float acc[4][4];
#pragma unroll
    for (int i = 0; i < 4; i++)
#pragma unroll
        for (int j = 0; j < 4; j++) acc[i][j] = 0.0f;
    for (int ko = 0; ko < 2 * M_; ko += 32) {
#pragma unroll
        for (int j = 0; j < 2; j++) {
            int i = tid * 2 + j;
            int lr = i >> 3;
            int kc = (i & 7) * 4;
            float4 qv = *(const float4*)(qp +
                ((size_t)(b * L_ + l0 + lr) * H_ + h) * (2 * M_) + ko + kc);
            qsT[kc + 0][lr] = qv.x;
            qsT[kc + 1][lr] = qv.y;
            qsT[kc + 2][lr] = qv.z;
            qsT[kc + 3][lr] = qv.w;
        }
#pragma unroll
        for (int j = 0; j < 2; j++) {
            int i = tid * 2 + j;
            int kr = i >> 4;
            int nc = (i & 15) * 4;
            *(float4*)(&kvs[kr][nc]) =
                *(const float4*)(kvb + (size_t)(ko + kr) * D_ + nc);
        }
        __syncthreads();
#pragma unroll
        for (int kk = 0; kk < 32; kk++) {
            float ra[4], rb[4];
            *(float4*)(ra) = *(float4*)(&qsT[kk][ty * 4]);
            *(float4*)(rb) = *(float4*)(&kvs[kk][tx * 4]);
#pragma unroll
            for (int i = 0; i < 4; i++)
#pragma unroll
                for (int j = 0; j < 4; j++)
                    acc[i][j] += ra[i] * rb[j];
        }
        __syncthreads();
    }
#pragma unroll
    for (int i = 0; i < 4; i++) {
        const int l = l0 + ty * 4 + i;
        const float f = nf[(size_t)(b * L_ + l) * H_ + h];
        float* op = z + ((size_t)(b * L_ + l) * H_ + h) * D_ + tx * 4;
        *(float4*)op = make_float4(acc[i][0] * f, acc[i][1] * f,
                                   acc[i][2] * f, acc[i][3] * f);
    }
}

// ===========================================================================
extern "C" void kernel_launch(void* const* d_in, const int* in_sizes, int n_in,
                              void* d_out, int out_size)
{
    const float* x   = (const float*)d_in[0];
    const float* pft = (const float*)d_in[1];
    const float* psl = (const float*)d_in[2];
    const float* Wv  = (const float*)d_in[3];
    const float* Wo  = (const float*)d_in[4];
    const float* Wp  = (const float*)d_in[5];
    const float* sc  = (const float*)d_in[6];
    const float* ofs = (const float*)d_in[7];
    const float* prj = (const float*)d_in[8];
    float* out = (float*)d_out;

    float *pv, *ppp, *psp, *pqp, *pkp, *ppart, *pkv, *pz, *pnf;
    cudaGetSymbolAddress((void**)&pv,    g_v);
    cudaGetSymbolAddress((void**)&ppp,   g_pp);
    cudaGetSymbolAddress((void**)&psp,   g_sp);
    cudaGetSymbolAddress((void**)&pqp,   g_qp);
    cudaGetSymbolAddress((void**)&pkp,   g_kp);
    cudaGetSymbolAddress((void**)&ppart, g_part);
    cudaGetSymbolAddress((void**)&pkv,   g_kv);
    cudaGetSymbolAddress((void**)&pz,    g_z);
    cudaGetSymbolAddress((void**)&pnf,   g_nf);

    __half *xh, *xl, *ph, *pl, *sh, *sl, *zh, *zl;
    __half *wvh, *wvl, *wph, *wpl, *woh, *wol;
    cudaGetSymbolAddress((void**)&xh,  g_x16h);
    cudaGetSymbolAddress((void**)&xl,  g_x16l);
    cudaGetSymbolAddress((void**)&ph,  g_p16h);
    cudaGetSymbolAddress((void**)&pl,  g_p16l);
    cudaGetSymbolAddress((void**)&sh,  g_s16h);
    cudaGetSymbolAddress((void**)&sl,  g_s16l);
    cudaGetSymbolAddress((void**)&zh,  g_z16h);
    cudaGetSymbolAddress((void**)&zl,  g_z16l);
    cudaGetSymbolAddress((void**)&wvh, g_WvTh);
    cudaGetSymbolAddress((void**)&wvl, g_WvTl);
    cudaGetSymbolAddress((void**)&wph, g_WpTh);
    cudaGetSymbolAddress((void**)&wpl, g_WpTl);
    cudaGetSymbolAddress((void**)&woh, g_WoTh);
    cudaGetSymbolAddress((void**)&wol, g_WoTl);

    cudaFuncSetAttribute(tc_gemm3, cudaFuncAttributeMaxDynamicSharedMemorySize,
                         TCG_SMEM);
    cudaFuncSetAttribute(feat2_kernel, cudaFuncAttributeMaxDynamicSharedMemorySize,
                         FEAT_SMEM);

    const int Mrows = B_ * L_;                       // 16384
    const int nsplit = (int)(NROW16 / 1024);

    split2_kernel<<<nsplit, 256>>>(x,   xh, xl);
    split2_kernel<<<nsplit, 256>>>(pft, ph, pl);
    split2_kernel<<<nsplit, 256>>>(psl, sh, sl);
    dim3 wg(DM_ / 32, DM_ / 32);
    wtrans_split_kernel<<<wg, 256>>>(Wv, wvh, wvl);
    wtrans_split_kernel<<<wg, 256>>>(Wp, wph, wpl);
    wtrans_split_kernel<<<wg, 256>>>(Wo, woh, wol);

    dim3 gg(DM_ / 128, Mrows / 128);                 // (8, 128)
    tc_gemm3<<<gg, TG_THREADS, TCG_SMEM>>>(xh, xl, wvh, wvl, pv,  Mrows, DM_, DM_);
    tc_gemm3<<<gg, TG_THREADS, TCG_SMEM>>>(ph, pl, wph, wpl, ppp, Mrows, DM_, DM_);
    tc_gemm3<<<gg, TG_THREADS, TCG_SMEM>>>(sh, sl, wph, wpl, psp, Mrows, DM_, DM_);

    feat2_kernel<<<dim3(Mrows / 128, H_), 256, FEAT_SMEM>>>(ppp, psp, prj, sc, ofs,
                                                            pqp, pkp, pnf);

    kv_partial_kernel<<<dim3(NCHUNK, H_, B_), 256>>>(pkp, pv, ppart);
    kv_reduce_kernel<<<(B_ * H_ * 2 * M_ * D_) / 256, 256>>>(ppart, pkv);

    z_kernel<<<dim3(L_ / 64, H_, B_), 256>>>(pqp, pkv, pnf, pz);

    split2_kernel<<<nsplit, 256>>>(pz, zh, zl);
    tc_gemm3<<<gg, TG_THREADS, TCG_SMEM>>>(zh, zl, woh, wol, out, Mrows, DM_, DM_);
}

// round 6
// speedup vs baseline: 2.4065x; 1.0951x over previous
#include <cuda_runtime.h>
#include <cuda_fp16.h>
#include <cstdint>
#include <math.h>

// ---------------------------------------------------------------------------
// LinearSelfAttention — round 6:
//   * v / out GEMMs -> 2-term split (weight-lo dropped, loads skipped)
//   * z via HMMA (fp16 q', fp16 kv^T), fused nf scale + fp16 split epilogue
//   B=4, L=4096, H=16, D=64, M=128 (2M=256), D_MODEL=1024
// ---------------------------------------------------------------------------

#define B_ 4
#define L_ 4096
#define H_ 16
#define D_ 64
#define M_ 128
#define DM_ 1024
#define NCHUNK 8
#define LC_ (L_ / NCHUNK)    // 512

#define NORMALIZER 0.35355339059327373f
#define RATIO      0.08838834764831845f

// ----- fp32 scratch -----
__device__ float g_v   [(size_t)B_ * L_ * DM_];
__device__ float g_pp  [(size_t)B_ * L_ * DM_];
__device__ float g_sp  [(size_t)B_ * L_ * DM_];
__device__ float g_kp  [(size_t)B_ * L_ * H_ * 2 * M_];
__device__ float g_part[(size_t)B_ * H_ * NCHUNK * 2 * M_ * D_];
__device__ float g_nf  [(size_t)B_ * L_ * H_];
__device__ float g_kv  [(size_t)B_ * H_ * 2 * M_ * D_];

// ----- fp16 scratch -----
#define NROW16 ((size_t)B_ * L_ * DM_)
__device__ __half g_qp16 [(size_t)B_ * L_ * H_ * 2 * M_];
__device__ __half g_kvT16[(size_t)B_ * H_ * D_ * 2 * M_];
__device__ __half g_x16h [NROW16];
__device__ __half g_x16l [NROW16];
__device__ __half g_p16h [NROW16];
__device__ __half g_p16l [NROW16];
__device__ __half g_s16h [NROW16];
__device__ __half g_s16l [NROW16];
__device__ __half g_z16h [NROW16];
__device__ __half g_z16l [NROW16];
__device__ __half g_WvTh [(size_t)DM_ * DM_];
__device__ __half g_WvTl [(size_t)DM_ * DM_];
__device__ __half g_WpTh [(size_t)DM_ * DM_];
__device__ __half g_WpTl [(size_t)DM_ * DM_];
__device__ __half g_WoTh [(size_t)DM_ * DM_];
__device__ __half g_WoTl [(size_t)DM_ * DM_];

// ===========================================================================
// PTX helpers (base sm_103 ISA: cp.async / ldmatrix / mma.sync)
// ===========================================================================
__device__ __forceinline__ uint32_t smem_u32(const void* p) {
    uint32_t a;
    asm("{ .reg .u64 t; cvta.to.shared.u64 t, %1; cvt.u32.u64 %0, t; }"
        : "=r"(a) : "l"(p));
    return a;
}
__device__ __forceinline__ void ldmatrix_x4(uint32_t* r, uint32_t addr) {
    asm volatile("ldmatrix.sync.aligned.m8n8.x4.shared.b16 {%0,%1,%2,%3}, [%4];"
                 : "=r"(r[0]), "=r"(r[1]), "=r"(r[2]), "=r"(r[3]) : "r"(addr));
}
__device__ __forceinline__ void ldmatrix_x2(uint32_t* r, uint32_t addr) {
    asm volatile("ldmatrix.sync.aligned.m8n8.x2.shared.b16 {%0,%1}, [%2];"
                 : "=r"(r[0]), "=r"(r[1]) : "r"(addr));
}
__device__ __forceinline__ void mma16816(float* c, const uint32_t* a,
                                         const uint32_t* b) {
    asm volatile(
        "mma.sync.aligned.m16n8k16.row.col.f32.f16.f16.f32 "
        "{%0,%1,%2,%3}, {%4,%5,%6,%7}, {%8,%9}, {%0,%1,%2,%3};"
        : "+f"(c[0]), "+f"(c[1]), "+f"(c[2]), "+f"(c[3])
        : "r"(a[0]), "r"(a[1]), "r"(a[2]), "r"(a[3]), "r"(b[0]), "r"(b[1]));
}

// ===========================================================================
// tc_gemm3: C = (A0+A1) @ (B0+B1)^T; `terms` = 3 (full) or 2 (drop Ah*Bl).
// term order: t0 = Ah*Bh, t1 = Al*Bh, t2 = Ah*Bl.  terms==2 skips Bl loads.
// ===========================================================================
#define TG_THREADS 256
#define KC_ 64
#define ROWB 144
#define TB_ (128 * ROWB)
#define STAGE_BYTES (4 * TB_)
#define TCG_SMEM (2 * STAGE_BYTES)

__global__ __launch_bounds__(TG_THREADS, 1)
void tc_gemm3(const __half* __restrict__ A0, const __half* __restrict__ A1,
              const __half* __restrict__ B0, const __half* __restrict__ B1,
              float* __restrict__ C, int Mtot, int Nld, int K, int terms)
{
    extern __shared__ char smem[];
    const uint32_t sb = smem_u32(smem);
    const int tid = threadIdx.x;
    const int wid = tid >> 5;
    const int lane = tid & 31;
    const int wm = wid & 1;
    const int wn = wid >> 1;
    const int n0 = blockIdx.x * 128;
    const int m0 = blockIdx.y * 128;

    const __half* srcs[4] = {A0, A1, B0, B1};
    const int nbuf = (terms == 3) ? 4 : 3;   // skip Bl when terms==2

    const uint32_t a_off = (uint32_t)((((lane >> 3) & 1) * 8 + (lane & 7)) * ROWB
                                      + ((lane >> 4) * 8) * 2);
    const int bl_ = lane & 15;
    const uint32_t b_off = (uint32_t)(((bl_ & 7)) * ROWB + (((bl_ >> 3) & 1) * 8) * 2);

    float acc[4][4][4];
#pragma unroll
    for (int i = 0; i < 4; i++)
#pragma unroll
        for (int j = 0; j < 4; j++)
#pragma unroll
            for (int q = 0; q < 4; q++) acc[i][j][q] = 0.0f;

    const int nch = K / KC_;

    auto load_stage = [&](int s, int chunk) {
        const int k0 = chunk * KC_;
        const uint32_t stage = sb + s * STAGE_BYTES;
        for (int buf = 0; buf < nbuf; buf++) {
            const __half* src = srcs[buf];
            const int r0 = (buf < 2) ? m0 : n0;
            const uint32_t tb = stage + buf * TB_;
#pragma unroll
            for (int j = 0; j < 4; j++) {
                const int c = tid + j * 256;
                const int row = c >> 3;
                const int seg = c & 7;
                const uint32_t dst = tb + (uint32_t)(row * ROWB + seg * 16);
                const __half* sp = src + (size_t)(r0 + row) * K + k0 + seg * 8;
                asm volatile("cp.async.cg.shared.global [%0], [%1], 16;\n"
                             :: "r"(dst), "l"(sp));
            }
        }
        asm volatile("cp.async.commit_group;\n");
    };

    load_stage(0, 0);

    for (int i = 0; i < nch; i++) {
        const int s = i & 1;
        if (i + 1 < nch) {
            load_stage(s ^ 1, i + 1);
            asm volatile("cp.async.wait_group 1;\n");
        } else {
            asm volatile("cp.async.wait_group 0;\n");
        }
        __syncthreads();

        const uint32_t stage = sb + s * STAGE_BYTES;
        const uint32_t Ah = stage + 0 * TB_;
        const uint32_t Al = stage + 1 * TB_;
        const uint32_t Bh = stage + 2 * TB_;
        const uint32_t Bl = stage + 3 * TB_;
        const uint32_t a_row = (uint32_t)(wm * 64 * ROWB);
        const uint32_t b_row = (uint32_t)(wn * 32 * ROWB);

#pragma unroll
        for (int kk = 0; kk < 4; kk++) {
            const uint32_t kb = (uint32_t)(kk * 32);
            uint32_t ah[4][4], al[4][4], bh[4][2], bl2[4][2];
#pragma unroll
            for (int mf = 0; mf < 4; mf++) {
                const uint32_t ro = a_row + (uint32_t)(mf * 16 * ROWB) + kb + a_off;
                ldmatrix_x4(ah[mf], Ah + ro);
                ldmatrix_x4(al[mf], Al + ro);
            }
#pragma unroll
            for (int nf = 0; nf < 4; nf++) {
                const uint32_t ro = b_row + (uint32_t)(nf * 8 * ROWB) + kb + b_off;
                ldmatrix_x2(bh[nf], Bh + ro);
                if (terms == 3) ldmatrix_x2(bl2[nf], Bl + ro);
            }
#pragma unroll
            for (int mf = 0; mf < 4; mf++)
#pragma unroll
                for (int nf = 0; nf < 4; nf++) {
                    mma16816(acc[mf][nf], ah[mf], bh[nf]);
                    mma16816(acc[mf][nf], al[mf], bh[nf]);
                    if (terms == 3) mma16816(acc[mf][nf], ah[mf], bl2[nf]);
                }
        }
        __syncthreads();
    }

    const int mrow = lane >> 2;
    const int ncol = (lane & 3) * 2;
#pragma unroll
    for (int mf = 0; mf < 4; mf++) {
        const int gm = m0 + wm * 64 + mf * 16 + mrow;
#pragma unroll
        for (int nf = 0; nf < 4; nf++) {
            const int gn = n0 + wn * 32 + nf * 8 + ncol;
            float2 v0 = make_float2(acc[mf][nf][0], acc[mf][nf][1]);
            float2 v1 = make_float2(acc[mf][nf][2], acc[mf][nf][3]);
            *(float2*)(C + (size_t)gm * Nld + gn) = v0;
            *(float2*)(C + (size_t)(gm + 8) * Nld + gn) = v1;
        }
    }
}

// ===========================================================================
// split / transpose helpers
// ===========================================================================
__global__ __launch_bounds__(256)
void split2_kernel(const float* __restrict__ src, __half* __restrict__ hi,
                   __half* __restrict__ lo)
{
    const size_t i0 = ((size_t)blockIdx.x * 256 + threadIdx.x) * 4;
    float4 v = *(const float4*)(src + i0);
    float f[4] = {v.x, v.y, v.z, v.w};
    __half2 h2[2], l2[2];
#pragma unroll
    for (int j = 0; j < 2; j++) {
        __half ha = __float2half_rn(f[j * 2]);
        __half hb = __float2half_rn(f[j * 2 + 1]);
        h2[j] = __halves2half2(ha, hb);
        l2[j] = __halves2half2(__float2half_rn(f[j * 2] - __half2float(ha)),
                               __float2half_rn(f[j * 2 + 1] - __half2float(hb)));
    }
    *(__half2*)(hi + i0)     = h2[0];
    *(__half2*)(hi + i0 + 2) = h2[1];
    *(__half2*)(lo + i0)     = l2[0];
    *(__half2*)(lo + i0 + 2) = l2[1];
}

__global__ __launch_bounds__(256)
void wtrans_split_kernel(const float* __restrict__ W, __half* __restrict__ th,
                         __half* __restrict__ tl)
{
    __shared__ float tile[32][33];
    const int tx = threadIdx.x & 31;
    const int ty = threadIdx.x >> 5;
    const int n0 = blockIdx.x * 32;
    const int k0 = blockIdx.y * 32;
#pragma unroll
    for (int i = 0; i < 4; i++)
        tile[ty + i * 8][tx] = W[(size_t)(k0 + ty + i * 8) * DM_ + n0 + tx];
    __syncthreads();
#pragma unroll
    for (int i = 0; i < 4; i++) {
        const int n = ty + i * 8;
        float v = tile[tx][n];
        __half h = __float2half_rn(v);
        const size_t o = (size_t)(n0 + n) * DM_ + k0 + tx;
        th[o] = h;
        tl[o] = __float2half_rn(v - __half2float(h));
    }
}

// ===========================================================================
// feat2: per-head feature GEMM + fused sincos. q' -> fp16, k' -> fp32.
// ===========================================================================
#define FQP(r, d)  sm[(r) * 65 + (d)]
#define FKP(r, d)  sm[128 * 65 + (r) * 65 + (d)]
#define FPJ(d, m)  sm[2 * 128 * 65 + (d) * 132 + (m)]
#define FEAT_SMEM  ((2 * 128 * 65 + 64 * 132) * 4)

__global__ __launch_bounds__(256)
void feat2_kernel(const float* __restrict__ pp, const float* __restrict__ sp,
                  const float* __restrict__ proj,
                  const float* __restrict__ scale, const float* __restrict__ offs,
                  __half* __restrict__ qp16, float* __restrict__ kp,
                  float* __restrict__ nf)
{
    extern __shared__ float sm[];
    __shared__ float nfp[256];

    const int tid = threadIdx.x;
    const int h = blockIdx.y;
    const int r0 = blockIdx.x * 128;
    const float s = scale[h];
    const float off = offs[h];

#pragma unroll
    for (int i = tid; i < M_ * D_ / 4; i += 256) {
        const int m = i >> 4;
        const int dseg = (i & 15) * 4;
        float4 pv = *(const float4*)(proj + (size_t)m * 64 + dseg);
        FPJ(dseg + 0, m) = pv.x;
        FPJ(dseg + 1, m) = pv.y;
        FPJ(dseg + 2, m) = pv.z;
        FPJ(dseg + 3, m) = pv.w;
    }

    {
        const int r = tid >> 1;
        const int hf = tid & 1;
        const size_t g = (size_t)(r0 + r) * DM_ + h * 64 + hf * 32;
        float s2 = 0.0f;
#pragma unroll
        for (int j = 0; j < 8; j++) {
            float4 p  = *(const float4*)(pp + g + j * 4);
            float4 sl = *(const float4*)(sp + g + j * 4);
            const int d = hf * 32 + j * 4;
            FQP(r, d + 0) = s * p.x;
            FQP(r, d + 1) = s * p.y;
            FQP(r, d + 2) = s * p.z;
            FQP(r, d + 3) = s * p.w;
            FKP(r, d + 0) = s * (p.x + off * sl.x);
            FKP(r, d + 1) = s * (p.y + off * sl.y);
            FKP(r, d + 2) = s * (p.z + off * sl.z);
            FKP(r, d + 3) = s * (p.w + off * sl.w);
            s2 += sl.x * sl.x + sl.y * sl.y + sl.z * sl.z + sl.w * sl.w;
        }
        nfp[tid] = s2;
    }
    __syncthreads();

    if (tid < 128) {
        const float v2 = nfp[tid * 2] + nfp[tid * 2 + 1];
        nf[(size_t)(r0 + tid) * H_ + h] = sqrtf(v2) * (1.0f / (float)L_);
    }

    const int tm = tid & 15;
    const int tr = tid >> 4;
    const int rb = tr * 8;

#pragma unroll
    for (int mh = 0; mh < 2; mh++) {
        float aq[8][4], ak[8][4];
#pragma unroll
        for (int i = 0; i < 8; i++)
#pragma unroll
            for (int j = 0; j < 4; j++) { aq[i][j] = 0.0f; ak[i][j] = 0.0f; }

#pragma unroll 4
        for (int d = 0; d < 64; d++) {
            float pj[4];
#pragma unroll
            for (int j = 0; j < 4; j++)
                pj[j] = FPJ(d, mh * 64 + tm + j * 16);
#pragma unroll
            for (int i = 0; i < 8; i++) {
                const float rq = FQP(rb + i, d);
                const float rk = FKP(rb + i, d);
#pragma unroll
                for (int j = 0; j < 4; j++) {
                    aq[i][j] += rq * pj[j];
                    ak[i][j] += rk * pj[j];
                }
            }
        }

#pragma unroll
        for (int i = 0; i < 8; i++) {
            const size_t base = ((size_t)(r0 + rb + i) * H_ + h) * (2 * M_);
#pragma unroll
            for (int j = 0; j < 4; j++) {
                const int m = mh * 64 + tm + j * 16;
                float sq, cq, sk, ck;
                __sincosf(NORMALIZER * aq[i][j], &sq, &cq);
                __sincosf(NORMALIZER * ak[i][j], &sk, &ck);
                qp16[base + m]      = __float2half_rn(RATIO * sq);
                qp16[base + M_ + m] = __float2half_rn(RATIO * cq);
                kp[base + m]        = RATIO * sk;
                kp[base + M_ + m]   = RATIO * ck;
            }
        }
    }
}

// ===========================================================================
// kv partial + reduce (reduce also emits fp16 kv^T [d][m])
// ===========================================================================
__global__ __launch_bounds__(256)
void kv_partial_kernel(const float* __restrict__ kp, const float* __restrict__ v,
                       float* __restrict__ part)
{
    const int chunk = blockIdx.x;
    const int h = blockIdx.y;
    const int b = blockIdx.z;
    const int tid = threadIdx.x;
    const int td = tid & 7;
    const int tm = tid >> 3;
    const int d0 = td * 8;
    const int m0 = tm * 8;
    __shared__ float ks[4][2 * M_];
    __shared__ float vs[4][D_];
    float acc[8][8];
#pragma unroll
    for (int i = 0; i < 8; i++)
#pragma unroll
        for (int j = 0; j < 8; j++) acc[i][j] = 0.0f;

    const int l0 = chunk * LC_;
    for (int lg = l0; lg < l0 + LC_; lg += 4) {
#pragma unroll
        for (int u = 0; u < 4; u++)
            ks[u][tid] = kp[((size_t)(b * L_ + lg + u) * H_ + h) * (2 * M_) + tid];
        vs[tid >> 6][tid & 63] =
            v[((size_t)(b * L_ + lg + (tid >> 6)) * H_ + h) * D_ + (tid & 63)];
        __syncthreads();
#pragma unroll
        for (int u = 0; u < 4; u++) {
            float rm[8], rd[8];
            *(float4*)(rm)     = *(float4*)(&ks[u][m0]);
            *(float4*)(rm + 4) = *(float4*)(&ks[u][m0 + 4]);
            *(float4*)(rd)     = *(float4*)(&vs[u][d0]);
            *(float4*)(rd + 4) = *(float4*)(&vs[u][d0 + 4]);
#pragma unroll
            for (int i = 0; i < 8; i++)
#pragma unroll
                for (int j = 0; j < 8; j++)
                    acc[i][j] += rm[i] * rd[j];
        }
        __syncthreads();
    }

    const size_t pbase = ((size_t)((b * H_ + h) * NCHUNK + chunk)) * (2 * M_ * D_);
#pragma unroll
    for (int i = 0; i < 8; i++) {
        float* op = part + pbase + (size_t)(m0 + i) * D_ + d0;
        *(float4*)(op)     = make_float4(acc[i][0], acc[i][1], acc[i][2], acc[i][3]);
        *(float4*)(op + 4) = make_float4(acc[i][4], acc[i][5], acc[i][6], acc[i][7]);
    }
}

__global__ __launch_bounds__(256)
void kv_reduce_kernel(const float* __restrict__ part, __half* __restrict__ kvt)
{
    const int idx = blockIdx.x * 256 + threadIdx.x;
    const int bh = idx / (2 * M_ * D_);
    const int md = idx % (2 * M_ * D_);
    float s = 0.0f;
#pragma unroll
    for (int c = 0; c < NCHUNK; c++)
        s += part[((size_t)bh * NCHUNK + c) * (2 * M_ * D_) + md];
    const int m = md >> 6;
    const int d = md & 63;
    kvt[((size_t)bh * D_ + d) * (2 * M_) + m] = __float2half_rn(s);
}

// ===========================================================================
// z_hmma: per (b,h) C[128l, 64d] = q'16[128,256] @ kvT16[64,256]^T,
// scaled by nf, split to zh/zl fp16 in epilogue.
// smem: A 128 rows x 528B, B 64 rows x 528B.
// ===========================================================================
#define ROWZB 528
#define ZA_BYTES (128 * ROWZB)
#define ZB_BYTES (64 * ROWZB)
#define Z_SMEM (ZA_BYTES + ZB_BYTES)

__global__ __launch_bounds__(256)
void z_hmma_kernel(const __half* __restrict__ qp16, const __half* __restrict__ kvt,
                   const float* __restrict__ nf,
                   __half* __restrict__ zh, __half* __restrict__ zl)
{
    extern __shared__ char smem[];
    const uint32_t sb = smem_u32(smem);
    const int tid = threadIdx.x;
    const int wid = tid >> 5;
    const int lane = tid & 31;
    const int lt = blockIdx.x;
    const int h = blockIdx.y;
    const int b = blockIdx.z;
    const int l0 = lt * 128;

    // load A: q' tile 128 rows x 256 halves (32 segs of 16B) -> 4096 f4 loads
    {
        const __half* src = qp16 + ((size_t)(b * L_ + l0) * H_ + h) * (2 * M_);
#pragma unroll
        for (int j = 0; j < 16; j++) {
            const int c = tid + j * 256;         // 0..4095
            const int row = c >> 5;
            const int seg = c & 31;
            const uint32_t dst = sb + (uint32_t)(row * ROWZB + seg * 16);
            asm volatile("cp.async.cg.shared.global [%0], [%1], 16;\n"
                         :: "r"(dst), "l"(src + (size_t)row * H_ * (2 * M_) + seg * 8));
        }
    }
    // load B: kvT tile 64 rows x 256 halves -> 2048 f4 loads
    {
        const __half* src = kvt + (size_t)(b * H_ + h) * D_ * (2 * M_);
#pragma unroll
        for (int j = 0; j < 8; j++) {
            const int c = tid + j * 256;         // 0..2047
            const int row = c >> 5;
            const int seg = c & 31;
            const uint32_t dst = sb + (uint32_t)(ZA_BYTES + row * ROWZB + seg * 16);
            asm volatile("cp.async.cg.shared.global [%0], [%1], 16;\n"
                         :: "r"(dst), "l"(src + (size_t)row * (2 * M_) + seg * 8));
        }
    }
    asm volatile("cp.async.commit_group;\n");
    asm volatile("cp.async.wait_group 0;\n");
    __syncthreads();

    const uint32_t a_off = (uint32_t)((((lane >> 3) & 1) * 8 + (lane & 7)) * ROWZB
                                      + (lane >> 4) * 16);
    const int bl_ = lane & 15;
    const uint32_t b_off = (uint32_t)((bl_ & 7) * ROWZB + ((bl_ >> 3) & 1) * 16);

    float acc[8][4];
#pragma unroll
    for (int j = 0; j < 8; j++)
#pragma unroll
        for (int q = 0; q < 4; q++) acc[j][q] = 0.0f;

    const uint32_t a_base = sb + (uint32_t)(wid * 16 * ROWZB) + a_off;
    const uint32_t b_base = sb + ZA_BYTES + b_off;

#pragma unroll
    for (int kk = 0; kk < 16; kk++) {
        const uint32_t kb = (uint32_t)(kk * 32);
        uint32_t a[4];
        ldmatrix_x4(a, a_base + kb);
#pragma unroll
        for (int j = 0; j < 8; j++) {
            uint32_t bfr[2];
            ldmatrix_x2(bfr, b_base + (uint32_t)(j * 8 * ROWZB) + kb);
            mma16816(acc[j], a, bfr);
        }
    }

    // epilogue: scale by nf, split fp16
    const int mrow = lane >> 2;
    const int ncol = (lane & 3) * 2;
    const int gl0 = l0 + wid * 16 + mrow;
    const float f0 = nf[(size_t)(b * L_ + gl0) * H_ + h];
    const float f1 = nf[(size_t)(b * L_ + gl0 + 8) * H_ + h];
#pragma unroll
    for (int j = 0; j < 8; j++) {
        const int gn = h * 64 + j * 8 + ncol;
#pragma unroll
        for (int half = 0; half < 2; half++) {
            const int row = gl0 + half * 8;
            const float f = half ? f1 : f0;
            const float v0 = acc[j][half * 2 + 0] * f;
            const float v1 = acc[j][half * 2 + 1] * f;
            const __half h0 = __float2half_rn(v0);
            const __half h1 = __float2half_rn(v1);
            const __half e0 = __float2half_rn(v0 - __half2float(h0));
            const __half e1 = __float2half_rn(v1 - __half2float(h1));
            const size_t o = (size_t)(b * L_ + row) * DM_ + gn;
            *(__half2*)(zh + o) = __halves2half2(h0, h1);
            *(__half2*)(zl + o) = __halves2half2(e0, e1);
        }
    }
}

// ===========================================================================
extern "C" void kernel_launch(void* const* d_in, const int* in_sizes, int n_in,
                              void* d_out, int out_size)
{
    const float* x   = (const float*)d_in[0];
    const float* pft = (const float*)d_in[1];
    const float* psl = (const float*)d_in[2];
    const float* Wv  = (const float*)d_in[3];
    const float* Wo  = (const float*)d_in[4];
    const float* Wp  = (const float*)d_in[5];
    const float* sc  = (const float*)d_in[6];
    const float* ofs = (const float*)d_in[7];
    const float* prj = (const float*)d_in[8];
    float* out = (float*)d_out;

    float *pv, *ppp, *psp, *pkp, *ppart, *pnf;
    cudaGetSymbolAddress((void**)&pv,    g_v);
    cudaGetSymbolAddress((void**)&ppp,   g_pp);
    cudaGetSymbolAddress((void**)&psp,   g_sp);
    cudaGetSymbolAddress((void**)&pkp,   g_kp);
    cudaGetSymbolAddress((void**)&ppart, g_part);
    cudaGetSymbolAddress((void**)&pnf,   g_nf);

    __half *pqp16, *pkvt;
    cudaGetSymbolAddress((void**)&pqp16, g_qp16);
    cudaGetSymbolAddress((void**)&pkvt,  g_kvT16);

    __half *xh, *xl, *ph, *pl, *sh, *sl, *zh, *zl;
    __half *wvh, *wvl, *wph, *wpl, *woh, *wol;
    cudaGetSymbolAddress((void**)&xh,  g_x16h);
    cudaGetSymbolAddress((void**)&xl,  g_x16l);
    cudaGetSymbolAddress((void**)&ph,  g_p16h);
    cudaGetSymbolAddress((void**)&pl,  g_p16l);
    cudaGetSymbolAddress((void**)&sh,  g_s16h);
    cudaGetSymbolAddress((void**)&sl,  g_s16l);
    cudaGetSymbolAddress((void**)&zh,  g_z16h);
    cudaGetSymbolAddress((void**)&zl,  g_z16l);
    cudaGetSymbolAddress((void**)&wvh, g_WvTh);
    cudaGetSymbolAddress((void**)&wvl, g_WvTl);
    cudaGetSymbolAddress((void**)&wph, g_WpTh);
    cudaGetSymbolAddress((void**)&wpl, g_WpTl);
    cudaGetSymbolAddress((void**)&woh, g_WoTh);
    cudaGetSymbolAddress((void**)&wol, g_WoTl);

    cudaFuncSetAttribute(tc_gemm3, cudaFuncAttributeMaxDynamicSharedMemorySize,
                         TCG_SMEM);
    cudaFuncSetAttribute(feat2_kernel, cudaFuncAttributeMaxDynamicSharedMemorySize,
                         FEAT_SMEM);
    cudaFuncSetAttribute(z_hmma_kernel, cudaFuncAttributeMaxDynamicSharedMemorySize,
                         Z_SMEM);

    const int Mrows = B_ * L_;                       // 16384
    const int nsplit = (int)(NROW16 / 1024);

    split2_kernel<<<nsplit, 256>>>(x,   xh, xl);
    split2_kernel<<<nsplit, 256>>>(pft, ph, pl);
    split2_kernel<<<nsplit, 256>>>(psl, sh, sl);
    dim3 wg(DM_ / 32, DM_ / 32);
    wtrans_split_kernel<<<wg, 256>>>(Wv, wvh, wvl);
    wtrans_split_kernel<<<wg, 256>>>(Wp, wph, wpl);
    wtrans_split_kernel<<<wg, 256>>>(Wo, woh, wol);

    dim3 gg(DM_ / 128, Mrows / 128);                 // (8, 128)
    tc_gemm3<<<gg, TG_THREADS, TCG_SMEM>>>(xh, xl, wvh, wvl, pv,  Mrows, DM_, DM_, 2);
    tc_gemm3<<<gg, TG_THREADS, TCG_SMEM>>>(ph, pl, wph, wpl, ppp, Mrows, DM_, DM_, 3);
    tc_gemm3<<<gg, TG_THREADS, TCG_SMEM>>>(sh, sl, wph, wpl, psp, Mrows, DM_, DM_, 3);

    feat2_kernel<<<dim3(Mrows / 128, H_), 256, FEAT_SMEM>>>(ppp, psp, prj, sc, ofs,
                                                            pqp16, pkp, pnf);

    kv_partial_kernel<<<dim3(NCHUNK, H_, B_), 256>>>(pkp, pv, ppart);
    kv_reduce_kernel<<<(B_ * H_ * 2 * M_ * D_) / 256, 256>>>(ppart, pkvt);

    z_hmma_kernel<<<dim3(L_ / 128, H_, B_), 256, Z_SMEM>>>(pqp16, pkvt, pnf, zh, zl);

    tc_gemm3<<<gg, TG_THREADS, TCG_SMEM>>>(zh, zl, woh, wol, out, Mrows, DM_, DM_, 2);
}

// round 7
// speedup vs baseline: 2.7342x; 1.1362x over previous
#include <cuda_runtime.h>
#include <cuda_fp16.h>
#include <cstdint>
#include <math.h>

// ---------------------------------------------------------------------------
// LinearSelfAttention — round 7:
//   * kv = k'^T v via HMMA (3-term split-fp16, exact), ldmatrix.trans operands
//   * v-GEMM epilogue emits fp16 hi/lo directly; feat2 emits k' as fp16 hi/lo
//   B=4, L=4096, H=16, D=64, M=128 (2M=256), D_MODEL=1024
// ---------------------------------------------------------------------------

#define B_ 4
#define L_ 4096
#define H_ 16
#define D_ 64
#define M_ 128
#define DM_ 1024
#define NCHUNK 8
#define LC_ (L_ / NCHUNK)    // 512

#define NORMALIZER 0.35355339059327373f
#define RATIO      0.08838834764831845f

// ----- fp32 scratch -----
__device__ float g_pp  [(size_t)B_ * L_ * DM_];
__device__ float g_sp  [(size_t)B_ * L_ * DM_];
__device__ float g_part[(size_t)B_ * H_ * NCHUNK * 2 * M_ * D_];
__device__ float g_nf  [(size_t)B_ * L_ * H_];

// ----- fp16 scratch -----
#define NROW16 ((size_t)B_ * L_ * DM_)
__device__ __half g_qp16 [(size_t)B_ * L_ * H_ * 2 * M_];
__device__ __half g_kh16 [(size_t)B_ * L_ * H_ * 2 * M_];
__device__ __half g_kl16 [(size_t)B_ * L_ * H_ * 2 * M_];
__device__ __half g_vh16 [NROW16];
__device__ __half g_vl16 [NROW16];
__device__ __half g_kvT16[(size_t)B_ * H_ * D_ * 2 * M_];
__device__ __half g_x16h [NROW16];
__device__ __half g_x16l [NROW16];
__device__ __half g_p16h [NROW16];
__device__ __half g_p16l [NROW16];
__device__ __half g_s16h [NROW16];
__device__ __half g_s16l [NROW16];
__device__ __half g_z16h [NROW16];
__device__ __half g_z16l [NROW16];
__device__ __half g_WvTh [(size_t)DM_ * DM_];
__device__ __half g_WvTl [(size_t)DM_ * DM_];
__device__ __half g_WpTh [(size_t)DM_ * DM_];
__device__ __half g_WpTl [(size_t)DM_ * DM_];
__device__ __half g_WoTh [(size_t)DM_ * DM_];
__device__ __half g_WoTl [(size_t)DM_ * DM_];

// ===========================================================================
// PTX helpers (base sm_103 ISA: cp.async / ldmatrix / mma.sync)
// ===========================================================================
__device__ __forceinline__ uint32_t smem_u32(const void* p) {
    uint32_t a;
    asm("{ .reg .u64 t; cvta.to.shared.u64 t, %1; cvt.u32.u64 %0, t; }"
        : "=r"(a) : "l"(p));
    return a;
}
__device__ __forceinline__ void ldmatrix_x4(uint32_t* r, uint32_t addr) {
    asm volatile("ldmatrix.sync.aligned.m8n8.x4.shared.b16 {%0,%1,%2,%3}, [%4];"
                 : "=r"(r[0]), "=r"(r[1]), "=r"(r[2]), "=r"(r[3]) : "r"(addr));
}
__device__ __forceinline__ void ldmatrix_x2(uint32_t* r, uint32_t addr) {
    asm volatile("ldmatrix.sync.aligned.m8n8.x2.shared.b16 {%0,%1}, [%2];"
                 : "=r"(r[0]), "=r"(r[1]) : "r"(addr));
}
__device__ __forceinline__ void ldmatrix_x4_t(uint32_t* r, uint32_t addr) {
    asm volatile("ldmatrix.sync.aligned.m8n8.x4.trans.shared.b16 {%0,%1,%2,%3}, [%4];"
                 : "=r"(r[0]), "=r"(r[1]), "=r"(r[2]), "=r"(r[3]) : "r"(addr));
}
__device__ __forceinline__ void ldmatrix_x2_t(uint32_t* r, uint32_t addr) {
    asm volatile("ldmatrix.sync.aligned.m8n8.x2.trans.shared.b16 {%0,%1}, [%2];"
                 : "=r"(r[0]), "=r"(r[1]) : "r"(addr));
}
__device__ __forceinline__ void mma16816(float* c, const uint32_t* a,
                                         const uint32_t* b) {
    asm volatile(
        "mma.sync.aligned.m16n8k16.row.col.f32.f16.f16.f32 "
        "{%0,%1,%2,%3}, {%4,%5,%6,%7}, {%8,%9}, {%0,%1,%2,%3};"
        : "+f"(c[0]), "+f"(c[1]), "+f"(c[2]), "+f"(c[3])
        : "r"(a[0]), "r"(a[1]), "r"(a[2]), "r"(a[3]), "r"(b[0]), "r"(b[1]));
}

// ===========================================================================
// tc_gemm3: C = (A0+A1) @ (B0+B1)^T.
// terms: 3 = full split, 2 = drop Ah*Bl (skip Bl loads).
// out16: 0 -> fp32 C; 1 -> fp16 hi/lo pair (Ch, Cl).
// ===========================================================================
#define TG_THREADS 256
#define KC_ 64
#define ROWB 144
#define TB_ (128 * ROWB)
#define STAGE_BYTES (4 * TB_)
#define TCG_SMEM (2 * STAGE_BYTES)

__global__ __launch_bounds__(TG_THREADS, 1)
void tc_gemm3(const __half* __restrict__ A0, const __half* __restrict__ A1,
              const __half* __restrict__ B0, const __half* __restrict__ B1,
              float* __restrict__ C, __half* __restrict__ Ch,
              __half* __restrict__ Cl, int Nld, int K, int terms, int out16)
{
    extern __shared__ char smem[];
    const uint32_t sb = smem_u32(smem);
    const int tid = threadIdx.x;
    const int wid = tid >> 5;
    const int lane = tid & 31;
    const int wm = wid & 1;
    const int wn = wid >> 1;
    const int n0 = blockIdx.x * 128;
    const int m0 = blockIdx.y * 128;

    const __half* srcs[4] = {A0, A1, B0, B1};
    const int nbuf = (terms == 3) ? 4 : 3;

    const uint32_t a_off = (uint32_t)((((lane >> 3) & 1) * 8 + (lane & 7)) * ROWB
                                      + ((lane >> 4) * 8) * 2);
    const int bl_ = lane & 15;
    const uint32_t b_off = (uint32_t)(((bl_ & 7)) * ROWB + (((bl_ >> 3) & 1) * 8) * 2);

    float acc[4][4][4];
#pragma unroll
    for (int i = 0; i < 4; i++)
#pragma unroll
        for (int j = 0; j < 4; j++)
#pragma unroll
            for (int q = 0; q < 4; q++) acc[i][j][q] = 0.0f;

    const int nch = K / KC_;

    auto load_stage = [&](int s, int chunk) {
        const int k0 = chunk * KC_;
        const uint32_t stage = sb + s * STAGE_BYTES;
        for (int buf = 0; buf < nbuf; buf++) {
            const __half* src = srcs[buf];
            const int r0 = (buf < 2) ? m0 : n0;
            const uint32_t tb = stage + buf * TB_;
#pragma unroll
            for (int j = 0; j < 4; j++) {
                const int c = tid + j * 256;
                const int row = c >> 3;
                const int seg = c & 7;
                const uint32_t dst = tb + (uint32_t)(row * ROWB + seg * 16);
                const __half* sp = src + (size_t)(r0 + row) * K + k0 + seg * 8;
                asm volatile("cp.async.cg.shared.global [%0], [%1], 16;\n"
                             :: "r"(dst), "l"(sp));
            }
        }
        asm volatile("cp.async.commit_group;\n");
    };

    load_stage(0, 0);

    for (int i = 0; i < nch; i++) {
        const int s = i & 1;
        if (i + 1 < nch) {
            load_stage(s ^ 1, i + 1);
            asm volatile("cp.async.wait_group 1;\n");
        } else {
            asm volatile("cp.async.wait_group 0;\n");
        }
        __syncthreads();

        const uint32_t stage = sb + s * STAGE_BYTES;
        const uint32_t Ah = stage + 0 * TB_;
        const uint32_t Al = stage + 1 * TB_;
        const uint32_t Bh = stage + 2 * TB_;
        const uint32_t Bl = stage + 3 * TB_;
        const uint32_t a_row = (uint32_t)(wm * 64 * ROWB);
        const uint32_t b_row = (uint32_t)(wn * 32 * ROWB);

#pragma unroll
        for (int kk = 0; kk < 4; kk++) {
            const uint32_t kb = (uint32_t)(kk * 32);
            uint32_t ah[4][4], al[4][4], bh[4][2], bl2[4][2];
#pragma unroll
            for (int mf = 0; mf < 4; mf++) {
                const uint32_t ro = a_row + (uint32_t)(mf * 16 * ROWB) + kb + a_off;
                ldmatrix_x4(ah[mf], Ah + ro);
                ldmatrix_x4(al[mf], Al + ro);
            }
#pragma unroll
            for (int nf = 0; nf < 4; nf++) {
                const uint32_t ro = b_row + (uint32_t)(nf * 8 * ROWB) + kb + b_off;
                ldmatrix_x2(bh[nf], Bh + ro);
                if (terms == 3) ldmatrix_x2(bl2[nf], Bl + ro);
            }
#pragma unroll
            for (int mf = 0; mf < 4; mf++)
#pragma unroll
                for (int nf = 0; nf < 4; nf++) {
                    mma16816(acc[mf][nf], ah[mf], bh[nf]);
                    mma16816(acc[mf][nf], al[mf], bh[nf]);
                    if (terms == 3) mma16816(acc[mf][nf], ah[mf], bl2[nf]);
                }
        }
        __syncthreads();
    }

    const int mrow = lane >> 2;
    const int ncol = (lane & 3) * 2;
#pragma unroll
    for (int mf = 0; mf < 4; mf++) {
        const int gm = m0 + wm * 64 + mf * 16 + mrow;
#pragma unroll
        for (int nf = 0; nf < 4; nf++) {
            const int gn = n0 + wn * 32 + nf * 8 + ncol;
            if (!out16) {
                *(float2*)(C + (size_t)gm * Nld + gn) =
                    make_float2(acc[mf][nf][0], acc[mf][nf][1]);
                *(float2*)(C + (size_t)(gm + 8) * Nld + gn) =
                    make_float2(acc[mf][nf][2], acc[mf][nf][3]);
            } else {
#pragma unroll
                for (int hh = 0; hh < 2; hh++) {
                    const float v0 = acc[mf][nf][hh * 2 + 0];
                    const float v1 = acc[mf][nf][hh * 2 + 1];
                    const __half h0 = __float2half_rn(v0);
                    const __half h1 = __float2half_rn(v1);
                    const __half e0 = __float2half_rn(v0 - __half2float(h0));
                    const __half e1 = __float2half_rn(v1 - __half2float(h1));
                    const size_t o = (size_t)(gm + hh * 8) * Nld + gn;
                    *(__half2*)(Ch + o) = __halves2half2(h0, h1);
                    *(__half2*)(Cl + o) = __halves2half2(e0, e1);
                }
            }
        }
    }
}

// ===========================================================================
// split / transpose helpers
// ===========================================================================
__global__ __launch_bounds__(256)
void split2_kernel(const float* __restrict__ src, __half* __restrict__ hi,
                   __half* __restrict__ lo)
{
    const size_t i0 = ((size_t)blockIdx.x * 256 + threadIdx.x) * 4;
    float4 v = *(const float4*)(src + i0);
    float f[4] = {v.x, v.y, v.z, v.w};
    __half2 h2[2], l2[2];
#pragma unroll
    for (int j = 0; j < 2; j++) {
        __half ha = __float2half_rn(f[j * 2]);
        __half hb = __float2half_rn(f[j * 2 + 1]);
        h2[j] = __halves2half2(ha, hb);
        l2[j] = __halves2half2(__float2half_rn(f[j * 2] - __half2float(ha)),
                               __float2half_rn(f[j * 2 + 1] - __half2float(hb)));
    }
    *(__half2*)(hi + i0)     = h2[0];
    *(__half2*)(hi + i0 + 2) = h2[1];
    *(__half2*)(lo + i0)     = l2[0];
    *(__half2*)(lo + i0 + 2) = l2[1];
}

__global__ __launch_bounds__(256)
void wtrans_split_kernel(const float* __restrict__ W, __half* __restrict__ th,
                         __half* __restrict__ tl)
{
    __shared__ float tile[32][33];
    const int tx = threadIdx.x & 31;
    const int ty = threadIdx.x >> 5;
    const int n0 = blockIdx.x * 32;
    const int k0 = blockIdx.y * 32;
#pragma unroll
    for (int i = 0; i < 4; i++)
        tile[ty + i * 8][tx] = W[(size_t)(k0 + ty + i * 8) * DM_ + n0 + tx];
    __syncthreads();
#pragma unroll
    for (int i = 0; i < 4; i++) {
        const int n = ty + i * 8;
        float v = tile[tx][n];
        __half h = __float2half_rn(v);
        const size_t o = (size_t)(n0 + n) * DM_ + k0 + tx;
        th[o] = h;
        tl[o] = __float2half_rn(v - __half2float(h));
    }
}

// ===========================================================================
// feat2: per-head feature GEMM + fused sincos. q' -> fp16, k' -> fp16 hi/lo.
// ===========================================================================
#define FQP(r, d)  sm[(r) * 65 + (d)]
#define FKP(r, d)  sm[128 * 65 + (r) * 65 + (d)]
#define FPJ(d, m)  sm[2 * 128 * 65 + (d) * 132 + (m)]
#define FEAT_SMEM  ((2 * 128 * 65 + 64 * 132) * 4)

__global__ __launch_bounds__(256)
void feat2_kernel(const float* __restrict__ pp, const float* __restrict__ sp,
                  const float* __restrict__ proj,
                  const float* __restrict__ scale, const float* __restrict__ offs,
                  __half* __restrict__ qp16, __half* __restrict__ kh16,
                  __half* __restrict__ kl16, float* __restrict__ nf)
{
    extern __shared__ float sm[];
    __shared__ float nfp[256];

    const int tid = threadIdx.x;
    const int h = blockIdx.y;
    const int r0 = blockIdx.x * 128;
    const float s = scale[h];
    const float off = offs[h];

#pragma unroll
    for (int i = tid; i < M_ * D_ / 4; i += 256) {
        const int m = i >> 4;
        const int dseg = (i & 15) * 4;
        float4 pv = *(const float4*)(proj + (size_t)m * 64 + dseg);
        FPJ(dseg + 0, m) = pv.x;
        FPJ(dseg + 1, m) = pv.y;
        FPJ(dseg + 2, m) = pv.z;
        FPJ(dseg + 3, m) = pv.w;
    }

    {
        const int r = tid >> 1;
        const int hf = tid & 1;
        const size_t g = (size_t)(r0 + r) * DM_ + h * 64 + hf * 32;
        float s2 = 0.0f;
#pragma unroll
        for (int j = 0; j < 8; j++) {
            float4 p  = *(const float4*)(pp + g + j * 4);
            float4 sl = *(const float4*)(sp + g + j * 4);
            const int d = hf * 32 + j * 4;
            FQP(r, d + 0) = s * p.x;
            FQP(r, d + 1) = s * p.y;
            FQP(r, d + 2) = s * p.z;
            FQP(r, d + 3) = s * p.w;
            FKP(r, d + 0) = s * (p.x + off * sl.x);
            FKP(r, d + 1) = s * (p.y + off * sl.y);
            FKP(r, d + 2) = s * (p.z + off * sl.z);
            FKP(r, d + 3) = s * (p.w + off * sl.w);
            s2 += sl.x * sl.x + sl.y * sl.y + sl.z * sl.z + sl.w * sl.w;
        }
        nfp[tid] = s2;
    }
    __syncthreads();

    if (tid < 128) {
        const float v2 = nfp[tid * 2] + nfp[tid * 2 + 1];
        nf[(size_t)(r0 + tid) * H_ + h] = sqrtf(v2) * (1.0f / (float)L_);
    }

    const int tm = tid & 15;
    const int tr = tid >> 4;
    const int rb = tr * 8;

#pragma unroll
    for (int mh = 0; mh < 2; mh++) {
        float aq[8][4], ak[8][4];
#pragma unroll
        for (int i = 0; i < 8; i++)
#pragma unroll
            for (int j = 0; j < 4; j++) { aq[i][j] = 0.0f; ak[i][j] = 0.0f; }

#pragma unroll 4
        for (int d = 0; d < 64; d++) {
            float pj[4];
#pragma unroll
            for (int j = 0; j < 4; j++)
                pj[j] = FPJ(d, mh * 64 + tm + j * 16);
#pragma unroll
            for (int i = 0; i < 8; i++) {
                const float rq = FQP(rb + i, d);
                const float rk = FKP(rb + i, d);
#pragma unroll
                for (int j = 0; j < 4; j++) {
                    aq[i][j] += rq * pj[j];
                    ak[i][j] += rk * pj[j];
                }
            }
        }

#pragma unroll
        for (int i = 0; i < 8; i++) {
            const size_t base = ((size_t)(r0 + rb + i) * H_ + h) * (2 * M_);
#pragma unroll
            for (int j = 0; j < 4; j++) {
                const int m = mh * 64 + tm + j * 16;
                float sq, cq, sk, ck;
                __sincosf(NORMALIZER * aq[i][j], &sq, &cq);
                __sincosf(NORMALIZER * ak[i][j], &sk, &ck);
                qp16[base + m]      = __float2half_rn(RATIO * sq);
                qp16[base + M_ + m] = __float2half_rn(RATIO * cq);
                const float vks = RATIO * sk;
                const float vkc = RATIO * ck;
                const __half hks = __float2half_rn(vks);
                const __half hkc = __float2half_rn(vkc);
                kh16[base + m]      = hks;
                kh16[base + M_ + m] = hkc;
                kl16[base + m]      = __float2half_rn(vks - __half2float(hks));
                kl16[base + M_ + m] = __float2half_rn(vkc - __half2float(hkc));
            }
        }
    }
}

// ===========================================================================
// kv_hmma: per (b,h,chunk): part[256 m, 64 d] = sum_l k'[l,m] v[l,d]
// 3-term split (kh*vh + kl*vh + kh*vl). Operands are K-major in smem
// ([l][m], [l][d]) -> ldmatrix .trans for A and B fragments.
// ===========================================================================
#define KROWB 528                      // 256 halves + 16B pad
#define VROWB 144                      // 64 halves + 16B pad
#define KTB (64 * KROWB)               // 33792
#define VTB (64 * VROWB)               // 9216
#define KV_STAGE (2 * KTB + 2 * VTB)   // 86016
#define KV_SMEM (2 * KV_STAGE)         // 172032

__global__ __launch_bounds__(256, 1)
void kv_hmma_kernel(const __half* __restrict__ kh16, const __half* __restrict__ kl16,
                    const __half* __restrict__ vh16, const __half* __restrict__ vl16,
                    float* __restrict__ part)
{
    extern __shared__ char smem[];
    const uint32_t sb = smem_u32(smem);
    const int tid = threadIdx.x;
    const int wid = tid >> 5;
    const int lane = tid & 31;
    const int wm = wid & 3;            // 4 m-warps: 64 m each
    const int wd = wid >> 2;           // 2 d-warps: 32 d each
    const int chunk = blockIdx.x;
    const int h = blockIdx.y;
    const int b = blockIdx.z;
    const int lbase = chunk * LC_;

    // per-lane trans-ldmatrix offsets
    const int grp = lane >> 3;
    const int lrow = lane & 7;
    const uint32_t a_off = (uint32_t)(((grp >> 1) * 8 + lrow) * KROWB
                                      + ((grp & 1) * 8) * 2);
    const int bl_ = lane & 15;
    const uint32_t b_off = (uint32_t)((((bl_ >> 3) * 8) + (bl_ & 7)) * VROWB);

    float acc[4][4][4];
#pragma unroll
    for (int i = 0; i < 4; i++)
#pragma unroll
        for (int j = 0; j < 4; j++)
#pragma unroll
            for (int q = 0; q < 4; q++) acc[i][j][q] = 0.0f;

    auto load_stage = [&](int s, int it) {
        const int l0 = lbase + it * 64;
        const uint32_t stage = sb + s * KV_STAGE;
        // k' hi/lo: 64 rows x 512B = 2048 segs each
#pragma unroll
        for (int j = 0; j < 8; j++) {
            const int c = tid + j * 256;
            const int row = c >> 5;
            const int seg = c & 31;
            const size_t src = ((size_t)(b * L_ + l0 + row) * H_ + h) * (2 * M_) + seg * 8;
            const uint32_t d0 = stage + (uint32_t)(row * KROWB + seg * 16);
            asm volatile("cp.async.cg.shared.global [%0], [%1], 16;\n"
                         :: "r"(d0), "l"(kh16 + src));
            asm volatile("cp.async.cg.shared.global [%0], [%1], 16;\n"
                         :: "r"(d0 + KTB), "l"(kl16 + src));
        }
        // v hi/lo: 64 rows x 128B = 512 segs each
#pragma unroll
        for (int j = 0; j < 2; j++) {
            const int c = tid + j * 256;
            const int row = c >> 3;
            const int seg = c & 7;
            const size_t src = (size_t)(b * L_ + l0 + row) * DM_ + h * 64 + seg * 8;
            const uint32_t d0 = stage + (uint32_t)(2 * KTB + row * VROWB + seg * 16);
            asm volatile("cp.async.cg.shared.global [%0], [%1], 16;\n"
                         :: "r"(d0), "l"(vh16 + src));
            asm volatile("cp.async.cg.shared.global [%0], [%1], 16;\n"
                         :: "r"(d0 + VTB), "l"(vl16 + src));
        }
        asm volatile("cp.async.commit_group;\n");
    };

    const int NIT = LC_ / 64;          // 8
    load_stage(0, 0);

    for (int it = 0; it < NIT; it++) {
        const int s = it & 1;
        if (it + 1 < NIT) {
            load_stage(s ^ 1, it + 1);
            asm volatile("cp.async.wait_group 1;\n");
        } else {
            asm volatile("cp.async.wait_group 0;\n");
        }
        __syncthreads();

        const uint32_t stage = sb + s * KV_STAGE;
        const uint32_t KH = stage;
        const uint32_t KL = stage + KTB;
        const uint32_t VH = stage + 2 * KTB;
        const uint32_t VL = VH + VTB;
        const uint32_t a_base = (uint32_t)((wm * 64) * 2) + a_off;
        const uint32_t b_base = (uint32_t)((wd * 32) * 2) + b_off;

#pragma unroll
        for (int kk = 0; kk < 4; kk++) {
            uint32_t akh[4][4], akl[4][4], bvh[4][2], bvl[4][2];
#pragma unroll
            for (int mf = 0; mf < 4; mf++) {
                const uint32_t ro = (uint32_t)(kk * 16 * KROWB) + a_base
                                    + (uint32_t)(mf * 16 * 2);
                ldmatrix_x4_t(akh[mf], KH + ro);
                ldmatrix_x4_t(akl[mf], KL + ro);
            }
#pragma unroll
            for (int nf = 0; nf < 4; nf++) {
                const uint32_t ro = (uint32_t)(kk * 16 * VROWB) + b_base
                                    + (uint32_t)(nf * 8 * 2);
                ldmatrix_x2_t(bvh[nf], VH + ro);
                ldmatrix_x2_t(bvl[nf], VL + ro);
            }
#pragma unroll
            for (int mf = 0; mf < 4; mf++)
#pragma unroll
                for (int nf = 0; nf < 4; nf++) {
                    mma16816(acc[mf][nf], akh[mf], bvh[nf]);
                    mma16816(acc[mf][nf], akl[mf], bvh[nf]);
                    mma16816(acc[mf][nf], akh[mf], bvl[nf]);
                }
        }
        __syncthreads();
    }

    // epilogue: fp32 partial store [m][d]
    const size_t pbase = ((size_t)((b * H_ + h) * NCHUNK + chunk)) * (2 * M_ * D_);
    const int mrow = lane >> 2;
    const int ncol = (lane & 3) * 2;
#pragma unroll
    for (int mf = 0; mf < 4; mf++) {
        const int m = wm * 64 + mf * 16 + mrow;
#pragma unroll
        for (int nf = 0; nf < 4; nf++) {
            const int d = wd * 32 + nf * 8 + ncol;
            *(float2*)(part + pbase + (size_t)m * D_ + d) =
                make_float2(acc[mf][nf][0], acc[mf][nf][1]);
            *(float2*)(part + pbase + (size_t)(m + 8) * D_ + d) =
                make_float2(acc[mf][nf][2], acc[mf][nf][3]);
        }
    }
}

__global__ __launch_bounds__(256)
void kv_reduce_kernel(const float* __restrict__ part, __half* __restrict__ kvt)
{
    const int idx = blockIdx.x * 256 + threadIdx.x;
    const int bh = idx / (2 * M_ * D_);
    const int md = idx % (2 * M_ * D_);
    float s = 0.0f;
#pragma unroll
    for (int c = 0; c < NCHUNK; c++)
        s += part[((size_t)bh * NCHUNK + c) * (2 * M_ * D_) + md];
    const int m = md >> 6;
    const int d = md & 63;
    kvt[((size_t)bh * D_ + d) * (2 * M_) + m] = __float2half_rn(s);
}

// ===========================================================================
// z_hmma: per (b,h) C[128l, 64d] = q'16 @ kvT16^T, nf-scaled, fp16-split out
// ===========================================================================
#define ROWZB 528
#define ZA_BYTES (128 * ROWZB)
#define ZB_BYTES (64 * ROWZB)
#define Z_SMEM (ZA_BYTES + ZB_BYTES)

__global__ __launch_bounds__(256)
void z_hmma_kernel(const __half* __restrict__ qp16, const __half* __restrict__ kvt,
                   const float* __restrict__ nf,
                   __half* __restrict__ zh, __half* __restrict__ zl)
{
    extern __shared__ char smem[];
    const uint32_t sb = smem_u32(smem);
    const int tid = threadIdx.x;
    const int wid = tid >> 5;
    const int lane = tid & 31;
    const int lt = blockIdx.x;
    const int h = blockIdx.y;
    const int b = blockIdx.z;
    const int l0 = lt * 128;

    {
        const __half* src = qp16 + ((size_t)(b * L_ + l0) * H_ + h) * (2 * M_);
#pragma unroll
        for (int j = 0; j < 16; j++) {
            const int c = tid + j * 256;
            const int row = c >> 5;
            const int seg = c & 31;
            const uint32_t dst = sb + (uint32_t)(row * ROWZB + seg * 16);
            asm volatile("cp.async.cg.shared.global [%0], [%1], 16;\n"
                         :: "r"(dst), "l"(src + (size_t)row * H_ * (2 * M_) + seg * 8));
        }
    }
    {
        const __half* src = kvt + (size_t)(b * H_ + h) * D_ * (2 * M_);
#pragma unroll
        for (int j = 0; j < 8; j++) {
            const int c = tid + j * 256;
            const int row = c >> 5;
            const int seg = c & 31;
            const uint32_t dst = sb + (uint32_t)(ZA_BYTES + row * ROWZB + seg * 16);
            asm volatile("cp.async.cg.shared.global [%0], [%1], 16;\n"
                         :: "r"(dst), "l"(src + (size_t)row * (2 * M_) + seg * 8));
        }
    }
    asm volatile("cp.async.commit_group;\n");
    asm volatile("cp.async.wait_group 0;\n");
    __syncthreads();

    const uint32_t a_off = (uint32_t)((((lane >> 3) & 1) * 8 + (lane & 7)) * ROWZB
                                      + (lane >> 4) * 16);
    const int bl_ = lane & 15;
    const uint32_t b_off = (uint32_t)((bl_ & 7) * ROWZB + ((bl_ >> 3) & 1) * 16);

    float acc[8][4];
#pragma unroll
    for (int j = 0; j < 8; j++)
#pragma unroll
        for (int q = 0; q < 4; q++) acc[j][q] = 0.0f;

    const uint32_t a_base = sb + (uint32_t)(wid * 16 * ROWZB) + a_off;
    const uint32_t b_base = sb + ZA_BYTES + b_off;

#pragma unroll
    for (int kk = 0; kk < 16; kk++) {
        const uint32_t kb = (uint32_t)(kk * 32);
        uint32_t a[4];
        ldmatrix_x4(a, a_base + kb);
#pragma unroll
        for (int j = 0; j < 8; j++) {
            uint32_t bfr[2];
            ldmatrix_x2(bfr, b_base + (uint32_t)(j * 8 * ROWZB) + kb);
            mma16816(acc[j], a, bfr);
        }
    }

    const int mrow = lane >> 2;
    const int ncol = (lane & 3) * 2;
    const int gl0 = l0 + wid * 16 + mrow;
    const float f0 = nf[(size_t)(b * L_ + gl0) * H_ + h];
    const float f1 = nf[(size_t)(b * L_ + gl0 + 8) * H_ + h];
#pragma unroll
    for (int j = 0; j < 8; j++) {
        const int gn = h * 64 + j * 8 + ncol;
#pragma unroll
        for (int half = 0; half < 2; half++) {
            const int row = gl0 + half * 8;
            const float f = half ? f1 : f0;
            const float v0 = acc[j][half * 2 + 0] * f;
            const float v1 = acc[j][half * 2 + 1] * f;
            const __half h0 = __float2half_rn(v0);
            const __half h1 = __float2half_rn(v1);
            const __half e0 = __float2half_rn(v0 - __half2float(h0));
            const __half e1 = __float2half_rn(v1 - __half2float(h1));
            const size_t o = (size_t)(b * L_ + row) * DM_ + gn;
            *(__half2*)(zh + o) = __halves2half2(h0, h1);
            *(__half2*)(zl + o) = __halves2half2(e0, e1);
        }
    }
}

// ===========================================================================
extern "C" void kernel_launch(void* const* d_in, const int* in_sizes, int n_in,
                              void* d_out, int out_size)
{
    const float* x   = (const float*)d_in[0];
    const float* pft = (const float*)d_in[1];
    const float* psl = (const float*)d_in[2];
    const float* Wv  = (const float*)d_in[3];
    const float* Wo  = (const float*)d_in[4];
    const float* Wp  = (const float*)d_in[5];
    const float* sc  = (const float*)d_in[6];
    const float* ofs = (const float*)d_in[7];
    const float* prj = (const float*)d_in[8];
    float* out = (float*)d_out;

    float *ppp, *psp, *ppart, *pnf;
    cudaGetSymbolAddress((void**)&ppp,   g_pp);
    cudaGetSymbolAddress((void**)&psp,   g_sp);
    cudaGetSymbolAddress((void**)&ppart, g_part);
    cudaGetSymbolAddress((void**)&pnf,   g_nf);

    __half *pqp16, *pkh, *pkl, *pvh, *pvl, *pkvt;
    cudaGetSymbolAddress((void**)&pqp16, g_qp16);
    cudaGetSymbolAddress((void**)&pkh,   g_kh16);
    cudaGetSymbolAddress((void**)&pkl,   g_kl16);
    cudaGetSymbolAddress((void**)&pvh,   g_vh16);
    cudaGetSymbolAddress((void**)&pvl,   g_vl16);
    cudaGetSymbolAddress((void**)&pkvt,  g_kvT16);

    __half *xh, *xl, *ph, *pl, *sh, *sl, *zh, *zl;
    __half *wvh, *wvl, *wph, *wpl, *woh, *wol;
    cudaGetSymbolAddress((void**)&xh,  g_x16h);
    cudaGetSymbolAddress((void**)&xl,  g_x16l);
    cudaGetSymbolAddress((void**)&ph,  g_p16h);
    cudaGetSymbolAddress((void**)&pl,  g_p16l);
    cudaGetSymbolAddress((void**)&sh,  g_s16h);
    cudaGetSymbolAddress((void**)&sl,  g_s16l);
    cudaGetSymbolAddress((void**)&zh,  g_z16h);
    cudaGetSymbolAddress((void**)&zl,  g_z16l);
    cudaGetSymbolAddress((void**)&wvh, g_WvTh);
    cudaGetSymbolAddress((void**)&wvl, g_WvTl);
    cudaGetSymbolAddress((void**)&wph, g_WpTh);
    cudaGetSymbolAddress((void**)&wpl, g_WpTl);
    cudaGetSymbolAddress((void**)&woh, g_WoTh);
    cudaGetSymbolAddress((void**)&wol, g_WoTl);

    cudaFuncSetAttribute(tc_gemm3, cudaFuncAttributeMaxDynamicSharedMemorySize,
                         TCG_SMEM);
    cudaFuncSetAttribute(feat2_kernel, cudaFuncAttributeMaxDynamicSharedMemorySize,
                         FEAT_SMEM);
    cudaFuncSetAttribute(kv_hmma_kernel, cudaFuncAttributeMaxDynamicSharedMemorySize,
                         KV_SMEM);
    cudaFuncSetAttribute(z_hmma_kernel, cudaFuncAttributeMaxDynamicSharedMemorySize,
                         Z_SMEM);

    const int Mrows = B_ * L_;                       // 16384
    const int nsplit = (int)(NROW16 / 1024);

    split2_kernel<<<nsplit, 256>>>(x,   xh, xl);
    split2_kernel<<<nsplit, 256>>>(pft, ph, pl);
    split2_kernel<<<nsplit, 256>>>(psl, sh, sl);
    dim3 wg(DM_ / 32, DM_ / 32);
    wtrans_split_kernel<<<wg, 256>>>(Wv, wvh, wvl);
    wtrans_split_kernel<<<wg, 256>>>(Wp, wph, wpl);
    wtrans_split_kernel<<<wg, 256>>>(Wo, woh, wol);

    dim3 gg(DM_ / 128, Mrows / 128);                 // (8, 128)
    // v GEMM: 2-term, fp16 hi/lo output
    tc_gemm3<<<gg, TG_THREADS, TCG_SMEM>>>(xh, xl, wvh, wvl,
                                           (float*)0, pvh, pvl, DM_, DM_, 2, 1);
    // pos/slope GEMMs: 3-term, fp32 output
    tc_gemm3<<<gg, TG_THREADS, TCG_SMEM>>>(ph, pl, wph, wpl,
                                           ppp, (__half*)0, (__half*)0, DM_, DM_, 3, 0);
    tc_gemm3<<<gg, TG_THREADS, TCG_SMEM>>>(sh, sl, wph, wpl,
                                           psp, (__half*)0, (__half*)0, DM_, DM_, 3, 0);

    feat2_kernel<<<dim3(Mrows / 128, H_), 256, FEAT_SMEM>>>(ppp, psp, prj, sc, ofs,
                                                            pqp16, pkh, pkl, pnf);

    kv_hmma_kernel<<<dim3(NCHUNK, H_, B_), 256, KV_SMEM>>>(pkh, pkl, pvh, pvl, ppart);
    kv_reduce_kernel<<<(B_ * H_ * 2 * M_ * D_) / 256, 256>>>(ppart, pkvt);

    z_hmma_kernel<<<dim3(L_ / 128, H_, B_), 256, Z_SMEM>>>(pqp16, pkvt, pnf, zh, zl);

    // out GEMM: 2-term, fp32 output
    tc_gemm3<<<gg, TG_THREADS, TCG_SMEM>>>(zh, zl, woh, wol,
                                           out, (__half*)0, (__half*)0, DM_, DM_, 2, 0);
}

// round 8
// speedup vs baseline: 2.8458x; 1.0408x over previous
#include <cuda_runtime.h>
#include <cuda_fp16.h>
#include <cstdint>
#include <math.h>

// ---------------------------------------------------------------------------
// LinearSelfAttention — round 8:
//   * feature matvec -> HMMA (feat3): G1=pp@projT', G2=sp@projT' split-fp16,
//     fused scale/sincos/nf epilogue with smem-staged coalesced stores
//   * pos/slope GEMMs emit fp16 hi/lo directly (no fp32 round-trip)
//   B=4, L=4096, H=16, D=64, M=128 (2M=256), D_MODEL=1024
// ---------------------------------------------------------------------------

#define B_ 4
#define L_ 4096
#define H_ 16
#define D_ 64
#define M_ 128
#define DM_ 1024
#define NCHUNK 8
#define LC_ (L_ / NCHUNK)    // 512

#define NORMALIZER 0.35355339059327373f
#define RATIO      0.08838834764831845f

// ----- fp32 scratch -----
__device__ float g_part[(size_t)B_ * H_ * NCHUNK * 2 * M_ * D_];
__device__ float g_nf  [(size_t)B_ * L_ * H_];

// ----- fp16 scratch -----
#define NROW16 ((size_t)B_ * L_ * DM_)
__device__ __half g_qp16 [(size_t)B_ * L_ * H_ * 2 * M_];
__device__ __half g_kh16 [(size_t)B_ * L_ * H_ * 2 * M_];
__device__ __half g_kl16 [(size_t)B_ * L_ * H_ * 2 * M_];
__device__ __half g_vh16 [NROW16];
__device__ __half g_vl16 [NROW16];
__device__ __half g_kvT16[(size_t)B_ * H_ * D_ * 2 * M_];
__device__ __half g_pph  [NROW16];
__device__ __half g_ppl  [NROW16];
__device__ __half g_sph  [NROW16];
__device__ __half g_spl  [NROW16];
__device__ __half g_prjh [(size_t)M_ * D_];
__device__ __half g_prjl [(size_t)M_ * D_];
__device__ __half g_x16h [NROW16];
__device__ __half g_x16l [NROW16];
__device__ __half g_p16h [NROW16];
__device__ __half g_p16l [NROW16];
__device__ __half g_s16h [NROW16];
__device__ __half g_s16l [NROW16];
__device__ __half g_z16h [NROW16];
__device__ __half g_z16l [NROW16];
__device__ __half g_WvTh [(size_t)DM_ * DM_];
__device__ __half g_WvTl [(size_t)DM_ * DM_];
__device__ __half g_WpTh [(size_t)DM_ * DM_];
__device__ __half g_WpTl [(size_t)DM_ * DM_];
__device__ __half g_WoTh [(size_t)DM_ * DM_];
__device__ __half g_WoTl [(size_t)DM_ * DM_];

// ===========================================================================
// PTX helpers (base sm_103 ISA: cp.async / ldmatrix / mma.sync)
// ===========================================================================
__device__ __forceinline__ uint32_t smem_u32(const void* p) {
    uint32_t a;
    asm("{ .reg .u64 t; cvta.to.shared.u64 t, %1; cvt.u32.u64 %0, t; }"
        : "=r"(a) : "l"(p));
    return a;
}
__device__ __forceinline__ void ldmatrix_x4(uint32_t* r, uint32_t addr) {
    asm volatile("ldmatrix.sync.aligned.m8n8.x4.shared.b16 {%0,%1,%2,%3}, [%4];"
                 : "=r"(r[0]), "=r"(r[1]), "=r"(r[2]), "=r"(r[3]) : "r"(addr));
}
__device__ __forceinline__ void ldmatrix_x2(uint32_t* r, uint32_t addr) {
    asm volatile("ldmatrix.sync.aligned.m8n8.x2.shared.b16 {%0,%1}, [%2];"
                 : "=r"(r[0]), "=r"(r[1]) : "r"(addr));
}
__device__ __forceinline__ void ldmatrix_x4_t(uint32_t* r, uint32_t addr) {
    asm volatile("ldmatrix.sync.aligned.m8n8.x4.trans.shared.b16 {%0,%1,%2,%3}, [%4];"
                 : "=r"(r[0]), "=r"(r[1]), "=r"(r[2]), "=r"(r[3]) : "r"(addr));
}
__device__ __forceinline__ void ldmatrix_x2_t(uint32_t* r, uint32_t addr) {
    asm volatile("ldmatrix.sync.aligned.m8n8.x2.trans.shared.b16 {%0,%1}, [%2];"
                 : "=r"(r[0]), "=r"(r[1]) : "r"(addr));
}
__device__ __forceinline__ void mma16816(float* c, const uint32_t* a,
                                         const uint32_t* b) {
    asm volatile(
        "mma.sync.aligned.m16n8k16.row.col.f32.f16.f16.f32 "
        "{%0,%1,%2,%3}, {%4,%5,%6,%7}, {%8,%9}, {%0,%1,%2,%3};"
        : "+f"(c[0]), "+f"(c[1]), "+f"(c[2]), "+f"(c[3])
        : "r"(a[0]), "r"(a[1]), "r"(a[2]), "r"(a[3]), "r"(b[0]), "r"(b[1]));
}

// ===========================================================================
// tc_gemm3: C = (A0+A1) @ (B0+B1)^T.
// terms: 3 = full split, 2 = drop Ah*Bl.  out16: 0 -> fp32 C; 1 -> fp16 Ch/Cl.
// ===========================================================================
#define TG_THREADS 256
#define KC_ 64
#define ROWB 144
#define TB_ (128 * ROWB)
#define STAGE_BYTES (4 * TB_)
#define TCG_SMEM (2 * STAGE_BYTES)

__global__ __launch_bounds__(TG_THREADS, 1)
void tc_gemm3(const __half* __restrict__ A0, const __half* __restrict__ A1,
              const __half* __restrict__ B0, const __half* __restrict__ B1,
              float* __restrict__ C, __half* __restrict__ Ch,
              __half* __restrict__ Cl, int Nld, int K, int terms, int out16)
{
    extern __shared__ char smem[];
    const uint32_t sb = smem_u32(smem);
    const int tid = threadIdx.x;
    const int wid = tid >> 5;
    const int lane = tid & 31;
    const int wm = wid & 1;
    const int wn = wid >> 1;
    const int n0 = blockIdx.x * 128;
    const int m0 = blockIdx.y * 128;

    const __half* srcs[4] = {A0, A1, B0, B1};
    const int nbuf = (terms == 3) ? 4 : 3;

    const uint32_t a_off = (uint32_t)((((lane >> 3) & 1) * 8 + (lane & 7)) * ROWB
                                      + ((lane >> 4) * 8) * 2);
    const int bl_ = lane & 15;
    const uint32_t b_off = (uint32_t)(((bl_ & 7)) * ROWB + (((bl_ >> 3) & 1) * 8) * 2);

    float acc[4][4][4];
#pragma unroll
    for (int i = 0; i < 4; i++)
#pragma unroll
        for (int j = 0; j < 4; j++)
#pragma unroll
            for (int q = 0; q < 4; q++) acc[i][j][q] = 0.0f;

    const int nch = K / KC_;

    auto load_stage = [&](int s, int chunk) {
        const int k0 = chunk * KC_;
        const uint32_t stage = sb + s * STAGE_BYTES;
        for (int buf = 0; buf < nbuf; buf++) {
            const __half* src = srcs[buf];
            const int r0 = (buf < 2) ? m0 : n0;
            const uint32_t tb = stage + buf * TB_;
#pragma unroll
            for (int j = 0; j < 4; j++) {
                const int c = tid + j * 256;
                const int row = c >> 3;
                const int seg = c & 7;
                const uint32_t dst = tb + (uint32_t)(row * ROWB + seg * 16);
                const __half* sp = src + (size_t)(r0 + row) * K + k0 + seg * 8;
                asm volatile("cp.async.cg.shared.global [%0], [%1], 16;\n"
                             :: "r"(dst), "l"(sp));
            }
        }
        asm volatile("cp.async.commit_group;\n");
    };

    load_stage(0, 0);

    for (int i = 0; i < nch; i++) {
        const int s = i & 1;
        if (i + 1 < nch) {
            load_stage(s ^ 1, i + 1);
            asm volatile("cp.async.wait_group 1;\n");
        } else {
            asm volatile("cp.async.wait_group 0;\n");
        }
        __syncthreads();

        const uint32_t stage = sb + s * STAGE_BYTES;
        const uint32_t Ah = stage + 0 * TB_;
        const uint32_t Al = stage + 1 * TB_;
        const uint32_t Bh = stage + 2 * TB_;
        const uint32_t Bl = stage + 3 * TB_;
        const uint32_t a_row = (uint32_t)(wm * 64 * ROWB);
        const uint32_t b_row = (uint32_t)(wn * 32 * ROWB);

#pragma unroll
        for (int kk = 0; kk < 4; kk++) {
            const uint32_t kb = (uint32_t)(kk * 32);
            uint32_t ah[4][4], al[4][4], bh[4][2], bl2[4][2];
#pragma unroll
            for (int mf = 0; mf < 4; mf++) {
                const uint32_t ro = a_row + (uint32_t)(mf * 16 * ROWB) + kb + a_off;
                ldmatrix_x4(ah[mf], Ah + ro);
                ldmatrix_x4(al[mf], Al + ro);
            }
#pragma unroll
            for (int nf = 0; nf < 4; nf++) {
                const uint32_t ro = b_row + (uint32_t)(nf * 8 * ROWB) + kb + b_off;
                ldmatrix_x2(bh[nf], Bh + ro);
                if (terms == 3) ldmatrix_x2(bl2[nf], Bl + ro);
            }
#pragma unroll
            for (int mf = 0; mf < 4; mf++)
#pragma unroll
                for (int nf = 0; nf < 4; nf++) {
                    mma16816(acc[mf][nf], ah[mf], bh[nf]);
                    mma16816(acc[mf][nf], al[mf], bh[nf]);
                    if (terms == 3) mma16816(acc[mf][nf], ah[mf], bl2[nf]);
                }
        }
        __syncthreads();
    }

    const int mrow = lane >> 2;
    const int ncol = (lane & 3) * 2;
#pragma unroll
    for (int mf = 0; mf < 4; mf++) {
        const int gm = m0 + wm * 64 + mf * 16 + mrow;
#pragma unroll
        for (int nf = 0; nf < 4; nf++) {
            const int gn = n0 + wn * 32 + nf * 8 + ncol;
            if (!out16) {
                *(float2*)(C + (size_t)gm * Nld + gn) =
                    make_float2(acc[mf][nf][0], acc[mf][nf][1]);
                *(float2*)(C + (size_t)(gm + 8) * Nld + gn) =
                    make_float2(acc[mf][nf][2], acc[mf][nf][3]);
            } else {
#pragma unroll
                for (int hh = 0; hh < 2; hh++) {
                    const float v0 = acc[mf][nf][hh * 2 + 0];
                    const float v1 = acc[mf][nf][hh * 2 + 1];
                    const __half h0 = __float2half_rn(v0);
                    const __half h1 = __float2half_rn(v1);
                    const __half e0 = __float2half_rn(v0 - __half2float(h0));
                    const __half e1 = __float2half_rn(v1 - __half2float(h1));
                    const size_t o = (size_t)(gm + hh * 8) * Nld + gn;
                    *(__half2*)(Ch + o) = __halves2half2(h0, h1);
                    *(__half2*)(Cl + o) = __halves2half2(e0, e1);
                }
            }
        }
    }
}

// ===========================================================================
// split / transpose helpers
// ===========================================================================
__global__ __launch_bounds__(256)
void split2_kernel(const float* __restrict__ src, __half* __restrict__ hi,
                   __half* __restrict__ lo)
{
    const size_t i0 = ((size_t)blockIdx.x * 256 + threadIdx.x) * 4;
    float4 v = *(const float4*)(src + i0);
    float f[4] = {v.x, v.y, v.z, v.w};
    __half2 h2[2], l2[2];
#pragma unroll
    for (int j = 0; j < 2; j++) {
        __half ha = __float2half_rn(f[j * 2]);
        __half hb = __float2half_rn(f[j * 2 + 1]);
        h2[j] = __halves2half2(ha, hb);
        l2[j] = __halves2half2(__float2half_rn(f[j * 2] - __half2float(ha)),
                               __float2half_rn(f[j * 2 + 1] - __half2float(hb)));
    }
    *(__half2*)(hi + i0)     = h2[0];
    *(__half2*)(hi + i0 + 2) = h2[1];
    *(__half2*)(lo + i0)     = l2[0];
    *(__half2*)(lo + i0 + 2) = l2[1];
}

__global__ __launch_bounds__(256)
void wtrans_split_kernel(const float* __restrict__ W, __half* __restrict__ th,
                         __half* __restrict__ tl)
{
    __shared__ float tile[32][33];
    const int tx = threadIdx.x & 31;
    const int ty = threadIdx.x >> 5;
    const int n0 = blockIdx.x * 32;
    const int k0 = blockIdx.y * 32;
#pragma unroll
    for (int i = 0; i < 4; i++)
        tile[ty + i * 8][tx] = W[(size_t)(k0 + ty + i * 8) * DM_ + n0 + tx];
    __syncthreads();
#pragma unroll
    for (int i = 0; i < 4; i++) {
        const int n = ty + i * 8;
        float v = tile[tx][n];
        __half h = __float2half_rn(v);
        const size_t o = (size_t)(n0 + n) * DM_ + k0 + tx;
        th[o] = h;
        tl[o] = __float2half_rn(v - __half2float(h));
    }
}

// proj [M,D] fp32 -> NORM-prescaled fp16 hi/lo
__global__ __launch_bounds__(256)
void proj_split_kernel(const float* __restrict__ proj, __half* __restrict__ ph,
                       __half* __restrict__ pl)
{
    const int i = blockIdx.x * 256 + threadIdx.x;
    if (i < M_ * D_) {
        const float v = NORMALIZER * proj[i];
        const __half h = __float2half_rn(v);
        ph[i] = h;
        pl[i] = __float2half_rn(v - __half2float(h));
    }
}

// ===========================================================================
// feat3: per-head HMMA feature GEMM.
// Block (128 rows, head h): G1 = pp@projT', G2 = sp@projT' (split-fp16,
// 3 terms each), then dash_q = s*G1, dash_k = s*(G1+off*G2), sincos,
// outputs qp16 / kh16 / kl16 via per-warp smem staging; nf from sp.
// ===========================================================================
#define F3_AT (128 * ROWB)             // 18432 per tile
#define F3_STAGE_OFF (6 * F3_AT)       // 110592
#define F3_SMEM (F3_STAGE_OFF + 8 * 16 * 256 * 2)   // 176128

__global__ __launch_bounds__(256, 1)
void feat3_kernel(const __half* __restrict__ pph, const __half* __restrict__ ppl,
                  const __half* __restrict__ sph, const __half* __restrict__ spl,
                  const __half* __restrict__ prjh, const __half* __restrict__ prjl,
                  const float* __restrict__ scale, const float* __restrict__ offs,
                  __half* __restrict__ qp16, __half* __restrict__ kh16,
                  __half* __restrict__ kl16, float* __restrict__ nf)
{
    extern __shared__ char smem[];
    __shared__ float nfp[256];
    const uint32_t sb = smem_u32(smem);
    const int tid = threadIdx.x;
    const int wid = tid >> 5;
    const int lane = tid & 31;
    const int h = blockIdx.y;
    const int r0 = blockIdx.x * 128;
    const float s = scale[h];
    const float off = offs[h];

    // ---- loads: 4 A tiles (128r x 64k) + 2 proj tiles (128m x 64k) ----
    {
        const __half* abuf[4] = {pph, ppl, sph, spl};
#pragma unroll
        for (int buf = 0; buf < 4; buf++) {
#pragma unroll
            for (int j = 0; j < 4; j++) {
                const int c = tid + j * 256;
                const int row = c >> 3;
                const int seg = c & 7;
                const uint32_t dst = sb + (uint32_t)(buf * F3_AT + row * ROWB + seg * 16);
                const __half* sp_ = abuf[buf] + (size_t)(r0 + row) * DM_ + h * 64 + seg * 8;
                asm volatile("cp.async.cg.shared.global [%0], [%1], 16;\n"
                             :: "r"(dst), "l"(sp_));
            }
        }
        const __half* pbuf[2] = {prjh, prjl};
#pragma unroll
        for (int buf = 0; buf < 2; buf++) {
#pragma unroll
            for (int j = 0; j < 4; j++) {
                const int c = tid + j * 256;
                const int row = c >> 3;
                const int seg = c & 7;
                const uint32_t dst = sb + (uint32_t)((4 + buf) * F3_AT + row * ROWB + seg * 16);
                asm volatile("cp.async.cg.shared.global [%0], [%1], 16;\n"
                             :: "r"(dst), "l"(pbuf[buf] + row * 64 + seg * 8));
            }
        }
        asm volatile("cp.async.commit_group;\n");
        asm volatile("cp.async.wait_group 0;\n");
        __syncthreads();
    }

    // ---- nf: ||sp|| per row (reconstruct hi+lo) ----
    {
        const int r = tid >> 1;
        const int hf = tid & 1;
        const uint32_t bh_ = sb + (uint32_t)(2 * F3_AT + r * ROWB + hf * 64);
        const uint32_t bl_ = sb + (uint32_t)(3 * F3_AT + r * ROWB + hf * 64);
        float s2 = 0.0f;
#pragma unroll
        for (int j = 0; j < 16; j++) {
            __half2 vh = *(__half2*)(smem + (bh_ - sb) + j * 4);
            __half2 vl = *(__half2*)(smem + (bl_ - sb) + j * 4);
            const float a0 = __half2float(__low2half(vh)) + __half2float(__low2half(vl));
            const float a1 = __half2float(__high2half(vh)) + __half2float(__high2half(vl));
            s2 += a0 * a0 + a1 * a1;
        }
        nfp[tid] = s2;
    }
    __syncthreads();
    if (tid < 128) {
        const float v2 = nfp[tid * 2] + nfp[tid * 2 + 1];
        nf[(size_t)(r0 + tid) * H_ + h] = sqrtf(v2) * (1.0f / (float)L_);
    }

    // ---- MMA: warp = 16 rows; G1/G2 over 128 m ----
    const uint32_t a_off = (uint32_t)((((lane >> 3) & 1) * 8 + (lane & 7)) * ROWB
                                      + ((lane >> 4) * 8) * 2);
    const int bl_ = lane & 15;
    const uint32_t b_off = (uint32_t)(((bl_ & 7)) * ROWB + (((bl_ >> 3) & 1) * 8) * 2);

    float g1[16][4], g2[16][4];
#pragma unroll
    for (int i = 0; i < 16; i++)
#pragma unroll
        for (int q = 0; q < 4; q++) { g1[i][q] = 0.0f; g2[i][q] = 0.0f; }

    const uint32_t APH = sb;
    const uint32_t APL = sb + F3_AT;
    const uint32_t ASH = sb + 2 * F3_AT;
    const uint32_t ASL = sb + 3 * F3_AT;
    const uint32_t BH  = sb + 4 * F3_AT;
    const uint32_t BL  = sb + 5 * F3_AT;
    const uint32_t a_base = (uint32_t)(wid * 16 * ROWB) + a_off;

#pragma unroll
    for (int kk = 0; kk < 4; kk++) {
        const uint32_t kb = (uint32_t)(kk * 32);
        uint32_t aph[4], apl[4], ash[4], asl[4];
        ldmatrix_x4(aph, APH + a_base + kb);
        ldmatrix_x4(apl, APL + a_base + kb);
        ldmatrix_x4(ash, ASH + a_base + kb);
        ldmatrix_x4(asl, ASL + a_base + kb);
#pragma unroll
        for (int nf8 = 0; nf8 < 16; nf8++) {
            const uint32_t ro = (uint32_t)(nf8 * 8 * ROWB) + kb + b_off;
            uint32_t bh2[2], bl2[2];
            ldmatrix_x2(bh2, BH + ro);
            ldmatrix_x2(bl2, BL + ro);
            mma16816(g1[nf8], aph, bh2);
            mma16816(g1[nf8], apl, bh2);
            mma16816(g1[nf8], aph, bl2);
            mma16816(g2[nf8], ash, bh2);
            mma16816(g2[nf8], asl, bh2);
            mma16816(g2[nf8], ash, bl2);
        }
    }

    // ---- epilogue: 3 output passes via per-warp staging ----
    const int mrow = lane >> 2;
    const int ncol = (lane & 3) * 2;
    const uint32_t stage = sb + (uint32_t)(F3_STAGE_OFF + wid * 8192);

#pragma unroll
    for (int pass = 0; pass < 3; pass++) {
#pragma unroll
        for (int nf8 = 0; nf8 < 16; nf8++) {
#pragma unroll
            for (int hh = 0; hh < 2; hh++) {
                const int lr = mrow + hh * 8;         // local row 0..15
                const int m = nf8 * 8 + ncol;
                float d0, d1;
                if (pass == 0) {
                    d0 = s * g1[nf8][hh * 2 + 0];
                    d1 = s * g1[nf8][hh * 2 + 1];
                } else {
                    d0 = s * (g1[nf8][hh * 2 + 0] + off * g2[nf8][hh * 2 + 0]);
                    d1 = s * (g1[nf8][hh * 2 + 1] + off * g2[nf8][hh * 2 + 1]);
                }
                float s0, c0, s1, c1;
                __sincosf(d0, &s0, &c0);
                __sincosf(d1, &s1, &c1);
                s0 *= RATIO; c0 *= RATIO; s1 *= RATIO; c1 *= RATIO;
                __half2 vs, vc;
                if (pass < 2) {   // hi parts (q' is pure fp16)
                    vs = __halves2half2(__float2half_rn(s0), __float2half_rn(s1));
                    vc = __halves2half2(__float2half_rn(c0), __float2half_rn(c1));
                } else {          // k' lo parts
                    const __half hs0 = __float2half_rn(s0);
                    const __half hs1 = __float2half_rn(s1);
                    const __half hc0 = __float2half_rn(c0);
                    const __half hc1 = __float2half_rn(c1);
                    vs = __halves2half2(__float2half_rn(s0 - __half2float(hs0)),
                                        __float2half_rn(s1 - __half2float(hs1)));
                    vc = __halves2half2(__float2half_rn(c0 - __half2float(hc0)),
                                        __float2half_rn(c1 - __half2float(hc1)));
                }
                *(__half2*)(smem + (stage - sb) + lr * 512 + m * 2) = vs;
                *(__half2*)(smem + (stage - sb) + lr * 512 + (M_ + m) * 2) = vc;
            }
        }
        __syncwarp();
        __half* outp = (pass == 0) ? qp16 : (pass == 1 ? kh16 : kl16);
#pragma unroll
        for (int it = 0; it < 16; it++) {
            const int idx = lane + it * 32;
            const int lr = idx >> 5;
            const int seg = idx & 31;
            const uint4 v = *(uint4*)(smem + (stage - sb) + lr * 512 + seg * 16);
            *(uint4*)(outp + ((size_t)(r0 + wid * 16 + lr) * H_ + h) * (2 * M_)
                      + seg * 8) = v;
        }
        __syncwarp();
    }
}

// ===========================================================================
// kv_hmma (unchanged from R7)
// ===========================================================================
#define KROWB 528
#define VROWB 144
#define KTB (64 * KROWB)
#define VTB (64 * VROWB)
#define KV_STAGE (2 * KTB + 2 * VTB)
#define KV_SMEM (2 * KV_STAGE)

__global__ __launch_bounds__(256, 1)
void kv_hmma_kernel(const __half* __restrict__ kh16, const __half* __restrict__ kl16,
                    const __half* __restrict__ vh16, const __half* __restrict__ vl16,
                    float* __restrict__ part)
{
    extern __shared__ char smem[];
    const uint32_t sb = smem_u32(smem);
    const int tid = threadIdx.x;
    const int wid = tid >> 5;
    const int lane = tid & 31;
    const int wm = wid & 3;
    const int wd = wid >> 2;
    const int chunk = blockIdx.x;
    const int h = blockIdx.y;
    const int b = blockIdx.z;
    const int lbase = chunk * LC_;

    const int grp = lane >> 3;
    const int lrow = lane & 7;
    const uint32_t a_off = (uint32_t)(((grp >> 1) * 8 + lrow) * KROWB
                                      + ((grp & 1) * 8) * 2);
    const int bl_ = lane & 15;
    const uint32_t b_off = (uint32_t)((((bl_ >> 3) * 8) + (bl_ & 7)) * VROWB);

    float acc[4][4][4];
#pragma unroll
    for (int i = 0; i < 4; i++)
#pragma unroll
        for (int j = 0; j < 4; j++)
#pragma unroll
            for (int q = 0; q < 4; q++) acc[i][j][q] = 0.0f;

    auto load_stage = [&](int s, int it) {
        const int l0 = lbase + it * 64;
        const uint32_t stage = sb + s * KV_STAGE;
#pragma unroll
        for (int j = 0; j < 8; j++) {
            const int c = tid + j * 256;
            const int row = c >> 5;
            const int seg = c & 31;
            const size_t src = ((size_t)(b * L_ + l0 + row) * H_ + h) * (2 * M_) + seg * 8;
            const uint32_t d0 = stage + (uint32_t)(row * KROWB + seg * 16);
            asm volatile("cp.async.cg.shared.global [%0], [%1], 16;\n"
                         :: "r"(d0), "l"(kh16 + src));
            asm volatile("cp.async.cg.shared.global [%0], [%1], 16;\n"
                         :: "r"(d0 + KTB), "l"(kl16 + src));
        }
#pragma unroll
        for (int j = 0; j < 2; j++) {
            const int c = tid + j * 256;
            const int row = c >> 3;
            const int seg = c & 7;
            const size_t src = (size_t)(b * L_ + l0 + row) * DM_ + h * 64 + seg * 8;
            const uint32_t d0 = stage + (uint32_t)(2 * KTB + row * VROWB + seg * 16);
            asm volatile("cp.async.cg.shared.global [%0], [%1], 16;\n"
                         :: "r"(d0), "l"(vh16 + src));
            asm volatile("cp.async.cg.shared.global [%0], [%1], 16;\n"
                         :: "r"(d0 + VTB), "l"(vl16 + src));
        }
        asm volatile("cp.async.commit_group;\n");
    };

    const int NIT = LC_ / 64;
    load_stage(0, 0);

    for (int it = 0; it < NIT; it++) {
        const int s = it & 1;
        if (it + 1 < NIT) {
            load_stage(s ^ 1, it + 1);
            asm volatile("cp.async.wait_group 1;\n");
        } else {
            asm volatile("cp.async.wait_group 0;\n");
        }
        __syncthreads();

        const uint32_t stage = sb + s * KV_STAGE;
        const uint32_t KH = stage;
        const uint32_t KL = stage + KTB;
        const uint32_t VH = stage + 2 * KTB;
        const uint32_t VL = VH + VTB;
        const uint32_t a_base = (uint32_t)((wm * 64) * 2) + a_off;
        const uint32_t b_base = (uint32_t)((wd * 32) * 2) + b_off;

#pragma unroll
        for (int kk = 0; kk < 4; kk++) {
            uint32_t akh[4][4], akl[4][4], bvh[4][2], bvl[4][2];
#pragma unroll
            for (int mf = 0; mf < 4; mf++) {
                const uint32_t ro = (uint32_t)(kk * 16 * KROWB) + a_base
                                    + (uint32_t)(mf * 16 * 2);
                ldmatrix_x4_t(akh[mf], KH + ro);
                ldmatrix_x4_t(akl[mf], KL + ro);
            }
#pragma unroll
            for (int nf = 0; nf < 4; nf++) {
                const uint32_t ro = (uint32_t)(kk * 16 * VROWB) + b_base
                                    + (uint32_t)(nf * 8 * 2);
                ldmatrix_x2_t(bvh[nf], VH + ro);
                ldmatrix_x2_t(bvl[nf], VL + ro);
            }
#pragma unroll
            for (int mf = 0; mf < 4; mf++)
#pragma unroll
                for (int nf = 0; nf < 4; nf++) {
                    mma16816(acc[mf][nf], akh[mf], bvh[nf]);
                    mma16816(acc[mf][nf], akl[mf], bvh[nf]);
                    mma16816(acc[mf][nf], akh[mf], bvl[nf]);
                }
        }
        __syncthreads();
    }

    const size_t pbase = ((size_t)((b * H_ + h) * NCHUNK + chunk)) * (2 * M_ * D_);
    const int mrow = lane >> 2;
    const int ncol = (lane & 3) * 2;
#pragma unroll
    for (int mf = 0; mf < 4; mf++) {
        const int m = wm * 64 + mf * 16 + mrow;
#pragma unroll
        for (int nf = 0; nf < 4; nf++) {
            const int d = wd * 32 + nf * 8 + ncol;
            *(float2*)(part + pbase + (size_t)m * D_ + d) =
                make_float2(acc[mf][nf][0], acc[mf][nf][1]);
            *(float2*)(part + pbase + (size_t)(m + 8) * D_ + d) =
                make_float2(acc[mf][nf][2], acc[mf][nf][3]);
        }
    }
}

__global__ __launch_bounds__(256)
void kv_reduce_kernel(const float* __restrict__ part, __half* __restrict__ kvt)
{
    const int idx = blockIdx.x * 256 + threadIdx.x;
    const int bh = idx / (2 * M_ * D_);
    const int md = idx % (2 * M_ * D_);
    float s = 0.0f;
#pragma unroll
    for (int c = 0; c < NCHUNK; c++)
        s += part[((size_t)bh * NCHUNK + c) * (2 * M_ * D_) + md];
    const int m = md >> 6;
    const int d = md & 63;
    kvt[((size_t)bh * D_ + d) * (2 * M_) + m] = __float2half_rn(s);
}

// ===========================================================================
// z_hmma (unchanged from R7)
// ===========================================================================
#define ROWZB 528
#define ZA_BYTES (128 * ROWZB)
#define ZB_BYTES (64 * ROWZB)
#define Z_SMEM (ZA_BYTES + ZB_BYTES)

__global__ __launch_bounds__(256)
void z_hmma_kernel(const __half* __restrict__ qp16, const __half* __restrict__ kvt,
                   const float* __restrict__ nf,
                   __half* __restrict__ zh, __half* __restrict__ zl)
{
    extern __shared__ char smem[];
    const uint32_t sb = smem_u32(smem);
    const int tid = threadIdx.x;
    const int wid = tid >> 5;
    const int lane = tid & 31;
    const int lt = blockIdx.x;
    const int h = blockIdx.y;
    const int b = blockIdx.z;
    const int l0 = lt * 128;

    {
        const __half* src = qp16 + ((size_t)(b * L_ + l0) * H_ + h) * (2 * M_);
#pragma unroll
        for (int j = 0; j < 16; j++) {
            const int c = tid + j * 256;
            const int row = c >> 5;
            const int seg = c & 31;
            const uint32_t dst = sb + (uint32_t)(row * ROWZB + seg * 16);
            asm volatile("cp.async.cg.shared.global [%0], [%1], 16;\n"
                         :: "r"(dst), "l"(src + (size_t)row * H_ * (2 * M_) + seg * 8));
        }
    }
    {
        const __half* src = kvt + (size_t)(b * H_ + h) * D_ * (2 * M_);
#pragma unroll
        for (int j = 0; j < 8; j++) {
            const int c = tid + j * 256;
            const int row = c >> 5;
            const int seg = c & 31;
            const uint32_t dst = sb + (uint32_t)(ZA_BYTES + row * ROWZB + seg * 16);
            asm volatile("cp.async.cg.shared.global [%0], [%1], 16;\n"
                         :: "r"(dst), "l"(src + (size_t)row * (2 * M_) + seg * 8));
        }
    }
    asm volatile("cp.async.commit_group;\n");
    asm volatile("cp.async.wait_group 0;\n");
    __syncthreads();

    const uint32_t a_off = (uint32_t)((((lane >> 3) & 1) * 8 + (lane & 7)) * ROWZB
                                      + (lane >> 4) * 16);
    const int bl_ = lane & 15;
    const uint32_t b_off = (uint32_t)((bl_ & 7) * ROWZB + ((bl_ >> 3) & 1) * 16);

    float acc[8][4];
#pragma unroll
    for (int j = 0; j < 8; j++)
#pragma unroll
        for (int q = 0; q < 4; q++) acc[j][q] = 0.0f;

    const uint32_t a_base = sb + (uint32_t)(wid * 16 * ROWZB) + a_off;
    const uint32_t b_base = sb + ZA_BYTES + b_off;

#pragma unroll
    for (int kk = 0; kk < 16; kk++) {
        const uint32_t kb = (uint32_t)(kk * 32);
        uint32_t a[4];
        ldmatrix_x4(a, a_base + kb);
#pragma unroll
        for (int j = 0; j < 8; j++) {
            uint32_t bfr[2];
            ldmatrix_x2(bfr, b_base + (uint32_t)(j * 8 * ROWZB) + kb);
            mma16816(acc[j], a, bfr);
        }
    }

    const int mrow = lane >> 2;
    const int ncol = (lane & 3) * 2;
    const int gl0 = l0 + wid * 16 + mrow;
    const float f0 = nf[(size_t)(b * L_ + gl0) * H_ + h];
    const float f1 = nf[(size_t)(b * L_ + gl0 + 8) * H_ + h];
#pragma unroll
    for (int j = 0; j < 8; j++) {
        const int gn = h * 64 + j * 8 + ncol;
#pragma unroll
        for (int half = 0; half < 2; half++) {
            const int row = gl0 + half * 8;
            const float f = half ? f1 : f0;
            const float v0 = acc[j][half * 2 + 0] * f;
            const float v1 = acc[j][half * 2 + 1] * f;
            const __half h0 = __float2half_rn(v0);
            const __half h1 = __float2half_rn(v1);
            const __half e0 = __float2half_rn(v0 - __half2float(h0));
            const __half e1 = __float2half_rn(v1 - __half2float(h1));
            const size_t o = (size_t)(b * L_ + row) * DM_ + gn;
            *(__half2*)(zh + o) = __halves2half2(h0, h1);
            *(__half2*)(zl + o) = __halves2half2(e0, e1);
        }
    }
}

// ===========================================================================
extern "C" void kernel_launch(void* const* d_in, const int* in_sizes, int n_in,
                              void* d_out, int out_size)
{
    const float* x   = (const float*)d_in[0];
    const float* pft = (const float*)d_in[1];
    const float* psl = (const float*)d_in[2];
    const float* Wv  = (const float*)d_in[3];
    const float* Wo  = (const float*)d_in[4];
    const float* Wp  = (const float*)d_in[5];
    const float* sc  = (const float*)d_in[6];
    const float* ofs = (const float*)d_in[7];
    const float* prj = (const float*)d_in[8];
    float* out = (float*)d_out;

    float *ppart, *pnf;
    cudaGetSymbolAddress((void**)&ppart, g_part);
    cudaGetSymbolAddress((void**)&pnf,   g_nf);

    __half *pqp16, *pkh, *pkl, *pvh, *pvl, *pkvt;
    __half *ppph, *pppl, *psph, *pspl, *pprjh, *pprjl;
    cudaGetSymbolAddress((void**)&pqp16, g_qp16);
    cudaGetSymbolAddress((void**)&pkh,   g_kh16);
    cudaGetSymbolAddress((void**)&pkl,   g_kl16);
    cudaGetSymbolAddress((void**)&pvh,   g_vh16);
    cudaGetSymbolAddress((void**)&pvl,   g_vl16);
    cudaGetSymbolAddress((void**)&pkvt,  g_kvT16);
    cudaGetSymbolAddress((void**)&ppph,  g_pph);
    cudaGetSymbolAddress((void**)&pppl,  g_ppl);
    cudaGetSymbolAddress((void**)&psph,  g_sph);
    cudaGetSymbolAddress((void**)&pspl,  g_spl);
    cudaGetSymbolAddress((void**)&pprjh, g_prjh);
    cudaGetSymbolAddress((void**)&pprjl, g_prjl);

    __half *xh, *xl, *ph, *pl, *sh, *sl, *zh, *zl;
    __half *wvh, *wvl, *wph, *wpl, *woh, *wol;
    cudaGetSymbolAddress((void**)&xh,  g_x16h);
    cudaGetSymbolAddress((void**)&xl,  g_x16l);
    cudaGetSymbolAddress((void**)&ph,  g_p16h);
    cudaGetSymbolAddress((void**)&pl,  g_p16l);
    cudaGetSymbolAddress((void**)&sh,  g_s16h);
    cudaGetSymbolAddress((void**)&sl,  g_s16l);
    cudaGetSymbolAddress((void**)&zh,  g_z16h);
    cudaGetSymbolAddress((void**)&zl,  g_z16l);
    cudaGetSymbolAddress((void**)&wvh, g_WvTh);
    cudaGetSymbolAddress((void**)&wvl, g_WvTl);
    cudaGetSymbolAddress((void**)&wph, g_WpTh);
    cudaGetSymbolAddress((void**)&wpl, g_WpTl);
    cudaGetSymbolAddress((void**)&woh, g_WoTh);
    cudaGetSymbolAddress((void**)&wol, g_WoTl);

    cudaFuncSetAttribute(tc_gemm3, cudaFuncAttributeMaxDynamicSharedMemorySize,
                         TCG_SMEM);
    cudaFuncSetAttribute(feat3_kernel, cudaFuncAttributeMaxDynamicSharedMemorySize,
                         F3_SMEM);
    cudaFuncSetAttribute(kv_hmma_kernel, cudaFuncAttributeMaxDynamicSharedMemorySize,
                         KV_SMEM);
    cudaFuncSetAttribute(z_hmma_kernel, cudaFuncAttributeMaxDynamicSharedMemorySize,
                         Z_SMEM);

    const int Mrows = B_ * L_;                       // 16384
    const int nsplit = (int)(NROW16 / 1024);

    split2_kernel<<<nsplit, 256>>>(x,   xh, xl);
    split2_kernel<<<nsplit, 256>>>(pft, ph, pl);
    split2_kernel<<<nsplit, 256>>>(psl, sh, sl);
    dim3 wg(DM_ / 32, DM_ / 32);
    wtrans_split_kernel<<<wg, 256>>>(Wv, wvh, wvl);
    wtrans_split_kernel<<<wg, 256>>>(Wp, wph, wpl);
    wtrans_split_kernel<<<wg, 256>>>(Wo, woh, wol);
    proj_split_kernel<<<(M_ * D_ + 255) / 256, 256>>>(prj, pprjh, pprjl);

    dim3 gg(DM_ / 128, Mrows / 128);                 // (8, 128)
    // v GEMM: 2-term, fp16 hi/lo output
    tc_gemm3<<<gg, TG_THREADS, TCG_SMEM>>>(xh, xl, wvh, wvl,
                                           (float*)0, pvh, pvl, DM_, DM_, 2, 1);
    // pos/slope GEMMs: 3-term, fp16 hi/lo output (feeds feat3)
    tc_gemm3<<<gg, TG_THREADS, TCG_SMEM>>>(ph, pl, wph, wpl,
                                           (float*)0, ppph, pppl, DM_, DM_, 3, 1);
    tc_gemm3<<<gg, TG_THREADS, TCG_SMEM>>>(sh, sl, wph, wpl,
                                           (float*)0, psph, pspl, DM_, DM_, 3, 1);

    feat3_kernel<<<dim3(Mrows / 128, H_), 256, F3_SMEM>>>(
        ppph, pppl, psph, pspl, pprjh, pprjl, sc, ofs, pqp16, pkh, pkl, pnf);

    kv_hmma_kernel<<<dim3(NCHUNK, H_, B_), 256, KV_SMEM>>>(pkh, pkl, pvh, pvl, ppart);
    kv_reduce_kernel<<<(B_ * H_ * 2 * M_ * D_) / 256, 256>>>(ppart, pkvt);

    z_hmma_kernel<<<dim3(L_ / 128, H_, B_), 256, Z_SMEM>>>(pqp16, pkvt, pnf, zh, zl);

    // out GEMM: 2-term, fp32 output
    tc_gemm3<<<gg, TG_THREADS, TCG_SMEM>>>(zh, zl, woh, wol,
                                           out, (__half*)0, (__half*)0, DM_, DM_, 2, 0);
}

// round 9
// speedup vs baseline: 2.9621x; 1.0409x over previous
#include <cuda_runtime.h>
#include <cuda_fp16.h>
#include <cstdint>
#include <math.h>

// ---------------------------------------------------------------------------
// LinearSelfAttention — round 9:
//   * v GEMM and out GEMM cut to 1 term (xh*Wvh, zh*Woh) — linear paths,
//     error spend computed: total ~7.7e-4 vs 1e-3 budget
//   * x split hi-only; z_hmma drops zl
//   B=4, L=4096, H=16, D=64, M=128 (2M=256), D_MODEL=1024
// ---------------------------------------------------------------------------

#define B_ 4
#define L_ 4096
#define H_ 16
#define D_ 64
#define M_ 128
#define DM_ 1024
#define NCHUNK 8
#define LC_ (L_ / NCHUNK)    // 512

#define NORMALIZER 0.35355339059327373f
#define RATIO      0.08838834764831845f

// ----- fp32 scratch -----
__device__ float g_part[(size_t)B_ * H_ * NCHUNK * 2 * M_ * D_];
__device__ float g_nf  [(size_t)B_ * L_ * H_];

// ----- fp16 scratch -----
#define NROW16 ((size_t)B_ * L_ * DM_)
__device__ __half g_qp16 [(size_t)B_ * L_ * H_ * 2 * M_];
__device__ __half g_kh16 [(size_t)B_ * L_ * H_ * 2 * M_];
__device__ __half g_kl16 [(size_t)B_ * L_ * H_ * 2 * M_];
__device__ __half g_vh16 [NROW16];
__device__ __half g_vl16 [NROW16];
__device__ __half g_kvT16[(size_t)B_ * H_ * D_ * 2 * M_];
__device__ __half g_pph  [NROW16];
__device__ __half g_ppl  [NROW16];
__device__ __half g_sph  [NROW16];
__device__ __half g_spl  [NROW16];
__device__ __half g_prjh [(size_t)M_ * D_];
__device__ __half g_prjl [(size_t)M_ * D_];
__device__ __half g_x16h [NROW16];
__device__ __half g_p16h [NROW16];
__device__ __half g_p16l [NROW16];
__device__ __half g_s16h [NROW16];
__device__ __half g_s16l [NROW16];
__device__ __half g_z16h [NROW16];
__device__ __half g_WvTh [(size_t)DM_ * DM_];
__device__ __half g_WpTh [(size_t)DM_ * DM_];
__device__ __half g_WpTl [(size_t)DM_ * DM_];
__device__ __half g_WoTh [(size_t)DM_ * DM_];

// ===========================================================================
// PTX helpers (base sm_103 ISA: cp.async / ldmatrix / mma.sync)
// ===========================================================================
__device__ __forceinline__ uint32_t smem_u32(const void* p) {
    uint32_t a;
    asm("{ .reg .u64 t; cvta.to.shared.u64 t, %1; cvt.u32.u64 %0, t; }"
        : "=r"(a) : "l"(p));
    return a;
}
__device__ __forceinline__ void ldmatrix_x4(uint32_t* r, uint32_t addr) {
    asm volatile("ldmatrix.sync.aligned.m8n8.x4.shared.b16 {%0,%1,%2,%3}, [%4];"
                 : "=r"(r[0]), "=r"(r[1]), "=r"(r[2]), "=r"(r[3]) : "r"(addr));
}
__device__ __forceinline__ void ldmatrix_x2(uint32_t* r, uint32_t addr) {
    asm volatile("ldmatrix.sync.aligned.m8n8.x2.shared.b16 {%0,%1}, [%2];"
                 : "=r"(r[0]), "=r"(r[1]) : "r"(addr));
}
__device__ __forceinline__ void ldmatrix_x4_t(uint32_t* r, uint32_t addr) {
    asm volatile("ldmatrix.sync.aligned.m8n8.x4.trans.shared.b16 {%0,%1,%2,%3}, [%4];"
                 : "=r"(r[0]), "=r"(r[1]), "=r"(r[2]), "=r"(r[3]) : "r"(addr));
}
__device__ __forceinline__ void ldmatrix_x2_t(uint32_t* r, uint32_t addr) {
    asm volatile("ldmatrix.sync.aligned.m8n8.x2.trans.shared.b16 {%0,%1}, [%2];"
                 : "=r"(r[0]), "=r"(r[1]) : "r"(addr));
}
__device__ __forceinline__ void mma16816(float* c, const uint32_t* a,
                                         const uint32_t* b) {
    asm volatile(
        "mma.sync.aligned.m16n8k16.row.col.f32.f16.f16.f32 "
        "{%0,%1,%2,%3}, {%4,%5,%6,%7}, {%8,%9}, {%0,%1,%2,%3};"
        : "+f"(c[0]), "+f"(c[1]), "+f"(c[2]), "+f"(c[3])
        : "r"(a[0]), "r"(a[1]), "r"(a[2]), "r"(a[3]), "r"(b[0]), "r"(b[1]));
}

// ===========================================================================
// tc_gemm3: C = (A0[+A1]) @ (B0[+B1])^T.
// terms: 1 = A0*B0 only; 2 = +A1*B0; 3 = +A0*B1.
// out16: 0 -> fp32 C; 1 -> fp16 Ch/Cl.
// ===========================================================================
#define TG_THREADS 256
#define KC_ 64
#define ROWB 144
#define TB_ (128 * ROWB)
#define STAGE_BYTES (4 * TB_)
#define TCG_SMEM (2 * STAGE_BYTES)

__global__ __launch_bounds__(TG_THREADS, 1)
void tc_gemm3(const __half* __restrict__ A0, const __half* __restrict__ A1,
              const __half* __restrict__ B0, const __half* __restrict__ B1,
              float* __restrict__ C, __half* __restrict__ Ch,
              __half* __restrict__ Cl, int Nld, int K, int terms, int out16)
{
    extern __shared__ char smem[];
    const uint32_t sb = smem_u32(smem);
    const int tid = threadIdx.x;
    const int wid = tid >> 5;
    const int lane = tid & 31;
    const int wm = wid & 1;
    const int wn = wid >> 1;
    const int n0 = blockIdx.x * 128;
    const int m0 = blockIdx.y * 128;

    const __half* srcs[4] = {A0, A1, B0, B1};

    const uint32_t a_off = (uint32_t)((((lane >> 3) & 1) * 8 + (lane & 7)) * ROWB
                                      + ((lane >> 4) * 8) * 2);
    const int bl_ = lane & 15;
    const uint32_t b_off = (uint32_t)(((bl_ & 7)) * ROWB + (((bl_ >> 3) & 1) * 8) * 2);

    float acc[4][4][4];
#pragma unroll
    for (int i = 0; i < 4; i++)
#pragma unroll
        for (int j = 0; j < 4; j++)
#pragma unroll
            for (int q = 0; q < 4; q++) acc[i][j][q] = 0.0f;

    const int nch = K / KC_;

    auto load_stage = [&](int s, int chunk) {
        const int k0 = chunk * KC_;
        const uint32_t stage = sb + s * STAGE_BYTES;
        for (int buf = 0; buf < 4; buf++) {
            if (buf == 1 && terms < 2) continue;
            if (buf == 3 && terms < 3) continue;
            const __half* src = srcs[buf];
            const int r0 = (buf < 2) ? m0 : n0;
            const uint32_t tb = stage + buf * TB_;
#pragma unroll
            for (int j = 0; j < 4; j++) {
                const int c = tid + j * 256;
                const int row = c >> 3;
                const int seg = c & 7;
                const uint32_t dst = tb + (uint32_t)(row * ROWB + seg * 16);
                const __half* sp = src + (size_t)(r0 + row) * K + k0 + seg * 8;
                asm volatile("cp.async.cg.shared.global [%0], [%1], 16;\n"
                             :: "r"(dst), "l"(sp));
            }
        }
        asm volatile("cp.async.commit_group;\n");
    };

    load_stage(0, 0);

    for (int i = 0; i < nch; i++) {
        const int s = i & 1;
        if (i + 1 < nch) {
            load_stage(s ^ 1, i + 1);
            asm volatile("cp.async.wait_group 1;\n");
        } else {
            asm volatile("cp.async.wait_group 0;\n");
        }
        __syncthreads();

        const uint32_t stage = sb + s * STAGE_BYTES;
        const uint32_t Ah = stage + 0 * TB_;
        const uint32_t Al = stage + 1 * TB_;
        const uint32_t Bh = stage + 2 * TB_;
        const uint32_t Bl = stage + 3 * TB_;
        const uint32_t a_row = (uint32_t)(wm * 64 * ROWB);
        const uint32_t b_row = (uint32_t)(wn * 32 * ROWB);

#pragma unroll
        for (int kk = 0; kk < 4; kk++) {
            const uint32_t kb = (uint32_t)(kk * 32);
            uint32_t ah[4][4], al[4][4], bh[4][2], bl2[4][2];
#pragma unroll
            for (int mf = 0; mf < 4; mf++) {
                const uint32_t ro = a_row + (uint32_t)(mf * 16 * ROWB) + kb + a_off;
                ldmatrix_x4(ah[mf], Ah + ro);
                if (terms >= 2) ldmatrix_x4(al[mf], Al + ro);
            }
#pragma unroll
            for (int nf = 0; nf < 4; nf++) {
                const uint32_t ro = b_row + (uint32_t)(nf * 8 * ROWB) + kb + b_off;
                ldmatrix_x2(bh[nf], Bh + ro);
                if (terms == 3) ldmatrix_x2(bl2[nf], Bl + ro);
            }
#pragma unroll
            for (int mf = 0; mf < 4; mf++)
#pragma unroll
                for (int nf = 0; nf < 4; nf++) {
                    mma16816(acc[mf][nf], ah[mf], bh[nf]);
                    if (terms >= 2) mma16816(acc[mf][nf], al[mf], bh[nf]);
                    if (terms == 3) mma16816(acc[mf][nf], ah[mf], bl2[nf]);
                }
        }
        __syncthreads();
    }

    const int mrow = lane >> 2;
    const int ncol = (lane & 3) * 2;
#pragma unroll
    for (int mf = 0; mf < 4; mf++) {
        const int gm = m0 + wm * 64 + mf * 16 + mrow;
#pragma unroll
        for (int nf = 0; nf < 4; nf++) {
            const int gn = n0 + wn * 32 + nf * 8 + ncol;
            if (!out16) {
                *(float2*)(C + (size_t)gm * Nld + gn) =
                    make_float2(acc[mf][nf][0], acc[mf][nf][1]);
                *(float2*)(C + (size_t)(gm + 8) * Nld + gn) =
                    make_float2(acc[mf][nf][2], acc[mf][nf][3]);
            } else {
#pragma unroll
                for (int hh = 0; hh < 2; hh++) {
                    const float v0 = acc[mf][nf][hh * 2 + 0];
                    const float v1 = acc[mf][nf][hh * 2 + 1];
                    const __half h0 = __float2half_rn(v0);
                    const __half h1 = __float2half_rn(v1);
                    const __half e0 = __float2half_rn(v0 - __half2float(h0));
                    const __half e1 = __float2half_rn(v1 - __half2float(h1));
                    const size_t o = (size_t)(gm + hh * 8) * Nld + gn;
                    *(__half2*)(Ch + o) = __halves2half2(h0, h1);
                    *(__half2*)(Cl + o) = __halves2half2(e0, e1);
                }
            }
        }
    }
}

// ===========================================================================
// split / transpose helpers
// ===========================================================================
__global__ __launch_bounds__(256)
void split2_kernel(const float* __restrict__ src, __half* __restrict__ hi,
                   __half* __restrict__ lo)
{
    const size_t i0 = ((size_t)blockIdx.x * 256 + threadIdx.x) * 4;
    float4 v = *(const float4*)(src + i0);
    float f[4] = {v.x, v.y, v.z, v.w};
    __half2 h2[2], l2[2];
#pragma unroll
    for (int j = 0; j < 2; j++) {
        __half ha = __float2half_rn(f[j * 2]);
        __half hb = __float2half_rn(f[j * 2 + 1]);
        h2[j] = __halves2half2(ha, hb);
        l2[j] = __halves2half2(__float2half_rn(f[j * 2] - __half2float(ha)),
                               __float2half_rn(f[j * 2 + 1] - __half2float(hb)));
    }
    *(__half2*)(hi + i0)     = h2[0];
    *(__half2*)(hi + i0 + 2) = h2[1];
    *(__half2*)(lo + i0)     = l2[0];
    *(__half2*)(lo + i0 + 2) = l2[1];
}

// hi-only split (for x — lo term dropped)
__global__ __launch_bounds__(256)
void split1_kernel(const float* __restrict__ src, __half* __restrict__ hi)
{
    const size_t i0 = ((size_t)blockIdx.x * 256 + threadIdx.x) * 4;
    float4 v = *(const float4*)(src + i0);
    __half2 a = __halves2half2(__float2half_rn(v.x), __float2half_rn(v.y));
    __half2 b = __halves2half2(__float2half_rn(v.z), __float2half_rn(v.w));
    *(__half2*)(hi + i0)     = a;
    *(__half2*)(hi + i0 + 2) = b;
}

// transpose [K,N] fp32 -> [N,K] fp16 hi (+ optional lo)
__global__ __launch_bounds__(256)
void wtrans_split_kernel(const float* __restrict__ W, __half* __restrict__ th,
                         __half* __restrict__ tl)
{
    __shared__ float tile[32][33];
    const int tx = threadIdx.x & 31;
    const int ty = threadIdx.x >> 5;
    const int n0 = blockIdx.x * 32;
    const int k0 = blockIdx.y * 32;
#pragma unroll
    for (int i = 0; i < 4; i++)
        tile[ty + i * 8][tx] = W[(size_t)(k0 + ty + i * 8) * DM_ + n0 + tx];
    __syncthreads();
#pragma unroll
    for (int i = 0; i < 4; i++) {
        const int n = ty + i * 8;
        float v = tile[tx][n];
        __half h = __float2half_rn(v);
        const size_t o = (size_t)(n0 + n) * DM_ + k0 + tx;
        th[o] = h;
        if (tl) tl[o] = __float2half_rn(v - __half2float(h));
    }
}

// proj [M,D] fp32 -> NORM-prescaled fp16 hi/lo
__global__ __launch_bounds__(256)
void proj_split_kernel(const float* __restrict__ proj, __half* __restrict__ ph,
                       __half* __restrict__ pl)
{
    const int i = blockIdx.x * 256 + threadIdx.x;
    if (i < M_ * D_) {
        const float v = NORMALIZER * proj[i];
        const __half h = __float2half_rn(v);
        ph[i] = h;
        pl[i] = __float2half_rn(v - __half2float(h));
    }
}

// ===========================================================================
// feat3 (unchanged from R8)
// ===========================================================================
#define F3_AT (128 * ROWB)
#define F3_STAGE_OFF (6 * F3_AT)
#define F3_SMEM (F3_STAGE_OFF + 8 * 16 * 256 * 2)

__global__ __launch_bounds__(256, 1)
void feat3_kernel(const __half* __restrict__ pph, const __half* __restrict__ ppl,
                  const __half* __restrict__ sph, const __half* __restrict__ spl,
                  const __half* __restrict__ prjh, const __half* __restrict__ prjl,
                  const float* __restrict__ scale, const float* __restrict__ offs,
                  __half* __restrict__ qp16, __half* __restrict__ kh16,
                  __half* __restrict__ kl16, float* __restrict__ nf)
{
    extern __shared__ char smem[];
    __shared__ float nfp[256];
    const uint32_t sb = smem_u32(smem);
    const int tid = threadIdx.x;
    const int wid = tid >> 5;
    const int lane = tid & 31;
    const int h = blockIdx.y;
    const int r0 = blockIdx.x * 128;
    const float s = scale[h];
    const float off = offs[h];

    {
        const __half* abuf[4] = {pph, ppl, sph, spl};
#pragma unroll
        for (int buf = 0; buf < 4; buf++) {
#pragma unroll
            for (int j = 0; j < 4; j++) {
                const int c = tid + j * 256;
                const int row = c >> 3;
                const int seg = c & 7;
                const uint32_t dst = sb + (uint32_t)(buf * F3_AT + row * ROWB + seg * 16);
                const __half* sp_ = abuf[buf] + (size_t)(r0 + row) * DM_ + h * 64 + seg * 8;
                asm volatile("cp.async.cg.shared.global [%0], [%1], 16;\n"
                             :: "r"(dst), "l"(sp_));
            }
        }
        const __half* pbuf[2] = {prjh, prjl};
#pragma unroll
        for (int buf = 0; buf < 2; buf++) {
#pragma unroll
            for (int j = 0; j < 4; j++) {
                const int c = tid + j * 256;
                const int row = c >> 3;
                const int seg = c & 7;
                const uint32_t dst = sb + (uint32_t)((4 + buf) * F3_AT + row * ROWB + seg * 16);
                asm volatile("cp.async.cg.shared.global [%0], [%1], 16;\n"
                             :: "r"(dst), "l"(pbuf[buf] + row * 64 + seg * 8));
            }
        }
        asm volatile("cp.async.commit_group;\n");
        asm volatile("cp.async.wait_group 0;\n");
        __syncthreads();
    }

    {
        const int r = tid >> 1;
        const int hf = tid & 1;
        const uint32_t bh_ = sb + (uint32_t)(2 * F3_AT + r * ROWB + hf * 64);
        const uint32_t bl_ = sb + (uint32_t)(3 * F3_AT + r * ROWB + hf * 64);
        float s2 = 0.0f;
#pragma unroll
        for (int j = 0; j < 16; j++) {
            __half2 vh = *(__half2*)(smem + (bh_ - sb) + j * 4);
            __half2 vl = *(__half2*)(smem + (bl_ - sb) + j * 4);
            const float a0 = __half2float(__low2half(vh)) + __half2float(__low2half(vl));
            const float a1 = __half2float(__high2half(vh)) + __half2float(__high2half(vl));
            s2 += a0 * a0 + a1 * a1;
        }
        nfp[tid] = s2;
    }
    __syncthreads();
    if (tid < 128) {
        const float v2 = nfp[tid * 2] + nfp[tid * 2 + 1];
        nf[(size_t)(r0 + tid) * H_ + h] = sqrtf(v2) * (1.0f / (float)L_);
    }

    const uint32_t a_off = (uint32_t)((((lane >> 3) & 1) * 8 + (lane & 7)) * ROWB
                                      + ((lane >> 4) * 8) * 2);
    const int bl_ = lane & 15;
    const uint32_t b_off = (uint32_t)(((bl_ & 7)) * ROWB + (((bl_ >> 3) & 1) * 8) * 2);

    float g1[16][4], g2[16][4];
#pragma unroll
    for (int i = 0; i < 16; i++)
#pragma unroll
        for (int q = 0; q < 4; q++) { g1[i][q] = 0.0f; g2[i][q] = 0.0f; }

    const uint32_t APH = sb;
    const uint32_t APL = sb + F3_AT;
    const uint32_t ASH = sb + 2 * F3_AT;
    const uint32_t ASL = sb + 3 * F3_AT;
    const uint32_t BH  = sb + 4 * F3_AT;
    const uint32_t BL  = sb + 5 * F3_AT;
    const uint32_t a_base = (uint32_t)(wid * 16 * ROWB) + a_off;

#pragma unroll
    for (int kk = 0; kk < 4; kk++) {
        const uint32_t kb = (uint32_t)(kk * 32);
        uint32_t aph[4], apl[4], ash[4], asl[4];
        ldmatrix_x4(aph, APH + a_base + kb);
        ldmatrix_x4(apl, APL + a_base + kb);
        ldmatrix_x4(ash, ASH + a_base + kb);
        ldmatrix_x4(asl, ASL + a_base + kb);
#pragma unroll
        for (int nf8 = 0; nf8 < 16; nf8++) {
            const uint32_t ro = (uint32_t)(nf8 * 8 * ROWB) + kb + b_off;
            uint32_t bh2[2], bl2[2];
            ldmatrix_x2(bh2, BH + ro);
            ldmatrix_x2(bl2, BL + ro);
            mma16816(g1[nf8], aph, bh2);
            mma16816(g1[nf8], apl, bh2);
            mma16816(g1[nf8], aph, bl2);
            mma16816(g2[nf8], ash, bh2);
            mma16816(g2[nf8], asl, bh2);
            mma16816(g2[nf8], ash, bl2);
        }
    }

    const int mrow = lane >> 2;
    const int ncol = (lane & 3) * 2;
    const uint32_t stage = sb + (uint32_t)(F3_STAGE_OFF + wid * 8192);

#pragma unroll
    for (int pass = 0; pass < 3; pass++) {
#pragma unroll
        for (int nf8 = 0; nf8 < 16; nf8++) {
#pragma unroll
            for (int hh = 0; hh < 2; hh++) {
                const int lr = mrow + hh * 8;
                const int m = nf8 * 8 + ncol;
                float d0, d1;
                if (pass == 0) {
                    d0 = s * g1[nf8][hh * 2 + 0];
                    d1 = s * g1[nf8][hh * 2 + 1];
                } else {
                    d0 = s * (g1[nf8][hh * 2 + 0] + off * g2[nf8][hh * 2 + 0]);
                    d1 = s * (g1[nf8][hh * 2 + 1] + off * g2[nf8][hh * 2 + 1]);
                }
                float s0, c0, s1, c1;
                __sincosf(d0, &s0, &c0);
                __sincosf(d1, &s1, &c1);
                s0 *= RATIO; c0 *= RATIO; s1 *= RATIO; c1 *= RATIO;
                __half2 vs, vc;
                if (pass < 2) {
                    vs = __halves2half2(__float2half_rn(s0), __float2half_rn(s1));
                    vc = __halves2half2(__float2half_rn(c0), __float2half_rn(c1));
                } else {
                    const __half hs0 = __float2half_rn(s0);
                    const __half hs1 = __float2half_rn(s1);
                    const __half hc0 = __float2half_rn(c0);
                    const __half hc1 = __float2half_rn(c1);
                    vs = __halves2half2(__float2half_rn(s0 - __half2float(hs0)),
                                        __float2half_rn(s1 - __half2float(hs1)));
                    vc = __halves2half2(__float2half_rn(c0 - __half2float(hc0)),
                                        __float2half_rn(c1 - __half2float(hc1)));
                }
                *(__half2*)(smem + (stage - sb) + lr * 512 + m * 2) = vs;
                *(__half2*)(smem + (stage - sb) + lr * 512 + (M_ + m) * 2) = vc;
            }
        }
        __syncwarp();
        __half* outp = (pass == 0) ? qp16 : (pass == 1 ? kh16 : kl16);
#pragma unroll
        for (int it = 0; it < 16; it++) {
            const int idx = lane + it * 32;
            const int lr = idx >> 5;
            const int seg = idx & 31;
            const uint4 v = *(uint4*)(smem + (stage - sb) + lr * 512 + seg * 16);
            *(uint4*)(outp + ((size_t)(r0 + wid * 16 + lr) * H_ + h) * (2 * M_)
                      + seg * 8) = v;
        }
        __syncwarp();
    }
}

// ===========================================================================
// kv_hmma (unchanged)
// ===========================================================================
#define KROWB 528
#define VROWB 144
#define KTB (64 * KROWB)
#define VTB (64 * VROWB)
#define KV_STAGE (2 * KTB + 2 * VTB)
#define KV_SMEM (2 * KV_STAGE)

__global__ __launch_bounds__(256, 1)
void kv_hmma_kernel(const __half* __restrict__ kh16, const __half* __restrict__ kl16,
                    const __half* __restrict__ vh16, const __half* __restrict__ vl16,
                    float* __restrict__ part)
{
    extern __shared__ char smem[];
    const uint32_t sb = smem_u32(smem);
    const int tid = threadIdx.x;
    const int wid = tid >> 5;
    const int lane = tid & 31;
    const int wm = wid & 3;
    const int wd = wid >> 2;
    const int chunk = blockIdx.x;
    const int h = blockIdx.y;
    const int b = blockIdx.z;
    const int lbase = chunk * LC_;

    const int grp = lane >> 3;
    const int lrow = lane & 7;
    const uint32_t a_off = (uint32_t)(((grp >> 1) * 8 + lrow) * KROWB
                                      + ((grp & 1) * 8) * 2);
    const int bl_ = lane & 15;
    const uint32_t b_off = (uint32_t)((((bl_ >> 3) * 8) + (bl_ & 7)) * VROWB);

    float acc[4][4][4];
#pragma unroll
    for (int i = 0; i < 4; i++)
#pragma unroll
        for (int j = 0; j < 4; j++)
#pragma unroll
            for (int q = 0; q < 4; q++) acc[i][j][q] = 0.0f;

    auto load_stage = [&](int s, int it) {
        const int l0 = lbase + it * 64;
        const uint32_t stage = sb + s * KV_STAGE;
#pragma unroll
        for (int j = 0; j < 8; j++) {
            const int c = tid + j * 256;
            const int row = c >> 5;
            const int seg = c & 31;
            const size_t src = ((size_t)(b * L_ + l0 + row) * H_ + h) * (2 * M_) + seg * 8;
            const uint32_t d0 = stage + (uint32_t)(row * KROWB + seg * 16);
            asm volatile("cp.async.cg.shared.global [%0], [%1], 16;\n"
                         :: "r"(d0), "l"(kh16 + src));
            asm volatile("cp.async.cg.shared.global [%0], [%1], 16;\n"
                         :: "r"(d0 + KTB), "l"(kl16 + src));
        }
#pragma unroll
        for (int j = 0; j < 2; j++) {
            const int c = tid + j * 256;
            const int row = c >> 3;
            const int seg = c & 7;
            const size_t src = (size_t)(b * L_ + l0 + row) * DM_ + h * 64 + seg * 8;
            const uint32_t d0 = stage + (uint32_t)(2 * KTB + row * VROWB + seg * 16);
            asm volatile("cp.async.cg.shared.global [%0], [%1], 16;\n"
                         :: "r"(d0), "l"(vh16 + src));
            asm volatile("cp.async.cg.shared.global [%0], [%1], 16;\n"
                         :: "r"(d0 + VTB), "l"(vl16 + src));
        }
        asm volatile("cp.async.commit_group;\n");
    };

    const int NIT = LC_ / 64;
    load_stage(0, 0);

    for (int it = 0; it < NIT; it++) {
        const int s = it & 1;
        if (it + 1 < NIT) {
            load_stage(s ^ 1, it + 1);
            asm volatile("cp.async.wait_group 1;\n");
        } else {
            asm volatile("cp.async.wait_group 0;\n");
        }
        __syncthreads();

        const uint32_t stage = sb + s * KV_STAGE;
        const uint32_t KH = stage;
        const uint32_t KL = stage + KTB;
        const uint32_t VH = stage + 2 * KTB;
        const uint32_t VL = VH + VTB;
        const uint32_t a_base = (uint32_t)((wm * 64) * 2) + a_off;
        const uint32_t b_base = (uint32_t)((wd * 32) * 2) + b_off;

#pragma unroll
        for (int kk = 0; kk < 4; kk++) {
            uint32_t akh[4][4], akl[4][4], bvh[4][2], bvl[4][2];
#pragma unroll
            for (int mf = 0; mf < 4; mf++) {
                const uint32_t ro = (uint32_t)(kk * 16 * KROWB) + a_base
                                    + (uint32_t)(mf * 16 * 2);
                ldmatrix_x4_t(akh[mf], KH + ro);
                ldmatrix_x4_t(akl[mf], KL + ro);
            }
#pragma unroll
            for (int nf = 0; nf < 4; nf++) {
                const uint32_t ro = (uint32_t)(kk * 16 * VROWB) + b_base
                                    + (uint32_t)(nf * 8 * 2);
                ldmatrix_x2_t(bvh[nf], VH + ro);
                ldmatrix_x2_t(bvl[nf], VL + ro);
            }
#pragma unroll
            for (int mf = 0; mf < 4; mf++)
#pragma unroll
                for (int nf = 0; nf < 4; nf++) {
                    mma16816(acc[mf][nf], akh[mf], bvh[nf]);
                    mma16816(acc[mf][nf], akl[mf], bvh[nf]);
                    mma16816(acc[mf][nf], akh[mf], bvl[nf]);
                }
        }
        __syncthreads();
    }

    const size_t pbase = ((size_t)((b * H_ + h) * NCHUNK + chunk)) * (2 * M_ * D_);
    const int mrow = lane >> 2;
    const int ncol = (lane & 3) * 2;
#pragma unroll
    for (int mf = 0; mf < 4; mf++) {
        const int m = wm * 64 + mf * 16 + mrow;
#pragma unroll
        for (int nf = 0; nf < 4; nf++) {
            const int d = wd * 32 + nf * 8 + ncol;
            *(float2*)(part + pbase + (size_t)m * D_ + d) =
                make_float2(acc[mf][nf][0], acc[mf][nf][1]);
            *(float2*)(part + pbase + (size_t)(m + 8) * D_ + d) =
                make_float2(acc[mf][nf][2], acc[mf][nf][3]);
        }
    }
}

__global__ __launch_bounds__(256)
void kv_reduce_kernel(const float* __restrict__ part, __half* __restrict__ kvt)
{
    const int idx = blockIdx.x * 256 + threadIdx.x;
    const int bh = idx / (2 * M_ * D_);
    const int md = idx % (2 * M_ * D_);
    float s = 0.0f;
#pragma unroll
    for (int c = 0; c < NCHUNK; c++)
        s += part[((size_t)bh * NCHUNK + c) * (2 * M_ * D_) + md];
    const int m = md >> 6;
    const int d = md & 63;
    kvt[((size_t)bh * D_ + d) * (2 * M_) + m] = __float2half_rn(s);
}

// ===========================================================================
// z_hmma: per (b,h) C[128l, 64d] = q'16 @ kvT16^T, nf-scaled, fp16 zh only
// ===========================================================================
#define ROWZB 528
#define ZA_BYTES (128 * ROWZB)
#define ZB_BYTES (64 * ROWZB)
#define Z_SMEM (ZA_BYTES + ZB_BYTES)

__global__ __launch_bounds__(256)
void z_hmma_kernel(const __half* __restrict__ qp16, const __half* __restrict__ kvt,
                   const float* __restrict__ nf, __half* __restrict__ zh)
{
    extern __shared__ char smem[];
    const uint32_t sb = smem_u32(smem);
    const int tid = threadIdx.x;
    const int wid = tid >> 5;
    const int lane = tid & 31;
    const int lt = blockIdx.x;
    const int h = blockIdx.y;
    const int b = blockIdx.z;
    const int l0 = lt * 128;

    {
        const __half* src = qp16 + ((size_t)(b * L_ + l0) * H_ + h) * (2 * M_);
#pragma unroll
        for (int j = 0; j < 16; j++) {
            const int c = tid + j * 256;
            const int row = c >> 5;
            const int seg = c & 31;
            const uint32_t dst = sb + (uint32_t)(row * ROWZB + seg * 16);
            asm volatile("cp.async.cg.shared.global [%0], [%1], 16;\n"
                         :: "r"(dst), "l"(src + (size_t)row * H_ * (2 * M_) + seg * 8));
        }
    }
    {
        const __half* src = kvt + (size_t)(b * H_ + h) * D_ * (2 * M_);
#pragma unroll
        for (int j = 0; j < 8; j++) {
            const int c = tid + j * 256;
            const int row = c >> 5;
            const int seg = c & 31;
            const uint32_t dst = sb + (uint32_t)(ZA_BYTES + row * ROWZB + seg * 16);
            asm volatile("cp.async.cg.shared.global [%0], [%1], 16;\n"
                         :: "r"(dst), "l"(src + (size_t)row * (2 * M_) + seg * 8));
        }
    }
    asm volatile("cp.async.commit_group;\n");
    asm volatile("cp.async.wait_group 0;\n");
    __syncthreads();

    const uint32_t a_off = (uint32_t)((((lane >> 3) & 1) * 8 + (lane & 7)) * ROWZB
                                      + (lane >> 4) * 16);
    const int bl_ = lane & 15;
    const uint32_t b_off = (uint32_t)((bl_ & 7) * ROWZB + ((bl_ >> 3) & 1) * 16);

    float acc[8][4];
#pragma unroll
    for (int j = 0; j < 8; j++)
#pragma unroll
        for (int q = 0; q < 4; q++) acc[j][q] = 0.0f;

    const uint32_t a_base = sb + (uint32_t)(wid * 16 * ROWZB) + a_off;
    const uint32_t b_base = sb + ZA_BYTES + b_off;

#pragma unroll
    for (int kk = 0; kk < 16; kk++) {
        const uint32_t kb = (uint32_t)(kk * 32);
        uint32_t a[4];
        ldmatrix_x4(a, a_base + kb);
#pragma unroll
        for (int j = 0; j < 8; j++) {
            uint32_t bfr[2];
            ldmatrix_x2(bfr, b_base + (uint32_t)(j * 8 * ROWZB) + kb);
            mma16816(acc[j], a, bfr);
        }
    }

    const int mrow = lane >> 2;
    const int ncol = (lane & 3) * 2;
    const int gl0 = l0 + wid * 16 + mrow;
    const float f0 = nf[(size_t)(b * L_ + gl0) * H_ + h];
    const float f1 = nf[(size_t)(b * L_ + gl0 + 8) * H_ + h];
#pragma unroll
    for (int j = 0; j < 8; j++) {
        const int gn = h * 64 + j * 8 + ncol;
#pragma unroll
        for (int half = 0; half < 2; half++) {
            const int row = gl0 + half * 8;
            const float f = half ? f1 : f0;
            const float v0 = acc[j][half * 2 + 0] * f;
            const float v1 = acc[j][half * 2 + 1] * f;
            const size_t o = (size_t)(b * L_ + row) * DM_ + gn;
            *(__half2*)(zh + o) = __halves2half2(__float2half_rn(v0),
                                                 __float2half_rn(v1));
        }
    }
}

// ===========================================================================
extern "C" void kernel_launch(void* const* d_in, const int* in_sizes, int n_in,
                              void* d_out, int out_size)
{
    const float* x   = (const float*)d_in[0];
    const float* pft = (const float*)d_in[1];
    const float* psl = (const float*)d_in[2];
    const float* Wv  = (const float*)d_in[3];
    const float* Wo  = (const float*)d_in[4];
    const float* Wp  = (const float*)d_in[5];
    const float* sc  = (const float*)d_in[6];
    const float* ofs = (const float*)d_in[7];
    const float* prj = (const float*)d_in[8];
    float* out = (float*)d_out;

    float *ppart, *pnf;
    cudaGetSymbolAddress((void**)&ppart, g_part);
    cudaGetSymbolAddress((void**)&pnf,   g_nf);

    __half *pqp16, *pkh, *pkl, *pvh, *pvl, *pkvt;
    __half *ppph, *pppl, *psph, *pspl, *pprjh, *pprjl;
    cudaGetSymbolAddress((void**)&pqp16, g_qp16);
    cudaGetSymbolAddress((void**)&pkh,   g_kh16);
    cudaGetSymbolAddress((void**)&pkl,   g_kl16);
    cudaGetSymbolAddress((void**)&pvh,   g_vh16);
    cudaGetSymbolAddress((void**)&pvl,   g_vl16);
    cudaGetSymbolAddress((void**)&pkvt,  g_kvT16);
    cudaGetSymbolAddress((void**)&ppph,  g_pph);
    cudaGetSymbolAddress((void**)&pppl,  g_ppl);
    cudaGetSymbolAddress((void**)&psph,  g_sph);
    cudaGetSymbolAddress((void**)&pspl,  g_spl);
    cudaGetSymbolAddress((void**)&pprjh, g_prjh);
    cudaGetSymbolAddress((void**)&pprjl, g_prjl);

    __half *xh, *ph, *pl, *sh, *sl, *zh;
    __half *wvh, *wph, *wpl, *woh;
    cudaGetSymbolAddress((void**)&xh,  g_x16h);
    cudaGetSymbolAddress((void**)&ph,  g_p16h);
    cudaGetSymbolAddress((void**)&pl,  g_p16l);
    cudaGetSymbolAddress((void**)&sh,  g_s16h);
    cudaGetSymbolAddress((void**)&sl,  g_s16l);
    cudaGetSymbolAddress((void**)&zh,  g_z16h);
    cudaGetSymbolAddress((void**)&wvh, g_WvTh);
    cudaGetSymbolAddress((void**)&wph, g_WpTh);
    cudaGetSymbolAddress((void**)&wpl, g_WpTl);
    cudaGetSymbolAddress((void**)&woh, g_WoTh);

    cudaFuncSetAttribute(tc_gemm3, cudaFuncAttributeMaxDynamicSharedMemorySize,
                         TCG_SMEM);
    cudaFuncSetAttribute(feat3_kernel, cudaFuncAttributeMaxDynamicSharedMemorySize,
                         F3_SMEM);
    cudaFuncSetAttribute(kv_hmma_kernel, cudaFuncAttributeMaxDynamicSharedMemorySize,
                         KV_SMEM);
    cudaFuncSetAttribute(z_hmma_kernel, cudaFuncAttributeMaxDynamicSharedMemorySize,
                         Z_SMEM);

    const int Mrows = B_ * L_;                       // 16384
    const int nsplit = (int)(NROW16 / 1024);

    split1_kernel<<<nsplit, 256>>>(x, xh);
    split2_kernel<<<nsplit, 256>>>(pft, ph, pl);
    split2_kernel<<<nsplit, 256>>>(psl, sh, sl);
    dim3 wg(DM_ / 32, DM_ / 32);
    wtrans_split_kernel<<<wg, 256>>>(Wv, wvh, (__half*)0);
    wtrans_split_kernel<<<wg, 256>>>(Wp, wph, wpl);
    wtrans_split_kernel<<<wg, 256>>>(Wo, woh, (__half*)0);
    proj_split_kernel<<<(M_ * D_ + 255) / 256, 256>>>(prj, pprjh, pprjl);

    dim3 gg(DM_ / 128, Mrows / 128);                 // (8, 128)
    // v GEMM: 1-term, fp16 hi/lo output
    tc_gemm3<<<gg, TG_THREADS, TCG_SMEM>>>(xh, xh, wvh, wvh,
                                           (float*)0, pvh, pvl, DM_, DM_, 1, 1);
    // pos/slope GEMMs: 3-term, fp16 hi/lo output (feeds feat3)
    tc_gemm3<<<gg, TG_THREADS, TCG_SMEM>>>(ph, pl, wph, wpl,
                                           (float*)0, ppph, pppl, DM_, DM_, 3, 1);
    tc_gemm3<<<gg, TG_THREADS, TCG_SMEM>>>(sh, sl, wph, wpl,
                                           (float*)0, psph, pspl, DM_, DM_, 3, 1);

    feat3_kernel<<<dim3(Mrows / 128, H_), 256, F3_SMEM>>>(
        ppph, pppl, psph, pspl, pprjh, pprjl, sc, ofs, pqp16, pkh, pkl, pnf);

    kv_hmma_kernel<<<dim3(NCHUNK, H_, B_), 256, KV_SMEM>>>(pkh, pkl, pvh, pvl, ppart);
    kv_reduce_kernel<<<(B_ * H_ * 2 * M_ * D_) / 256, 256>>>(ppart, pkvt);

    z_hmma_kernel<<<dim3(L_ / 128, H_, B_), 256, Z_SMEM>>>(pqp16, pkvt, pnf, zh);

    // out GEMM: 1-term, fp32 output
    tc_gemm3<<<gg, TG_THREADS, TCG_SMEM>>>(zh, zh, woh, woh,
                                           out, (__half*)0, (__half*)0, DM_, DM_, 1, 0);
}

// round 10
// speedup vs baseline: 3.8498x; 1.2997x over previous
#include <cuda_runtime.h>
#include <cuda_fp16.h>
#include <cstdint>
#include <math.h>

// ---------------------------------------------------------------------------
// LinearSelfAttention — round 10:
//   * tc_gemm1: compact 1-term GEMM (2 CTAs/SM) for v / out
//   * tc_gemm_pair: fused pos+slope 3-term GEMMs sharing Wp tiles
//   (no numeric change vs R9: rel_err should be identical)
//   B=4, L=4096, H=16, D=64, M=128 (2M=256), D_MODEL=1024
// ---------------------------------------------------------------------------

#define B_ 4
#define L_ 4096
#define H_ 16
#define D_ 64
#define M_ 128
#define DM_ 1024
#define NCHUNK 8
#define LC_ (L_ / NCHUNK)    // 512

#define NORMALIZER 0.35355339059327373f
#define RATIO      0.08838834764831845f

// ----- fp32 scratch -----
__device__ float g_part[(size_t)B_ * H_ * NCHUNK * 2 * M_ * D_];
__device__ float g_nf  [(size_t)B_ * L_ * H_];

// ----- fp16 scratch -----
#define NROW16 ((size_t)B_ * L_ * DM_)
__device__ __half g_qp16 [(size_t)B_ * L_ * H_ * 2 * M_];
__device__ __half g_kh16 [(size_t)B_ * L_ * H_ * 2 * M_];
__device__ __half g_kl16 [(size_t)B_ * L_ * H_ * 2 * M_];
__device__ __half g_vh16 [NROW16];
__device__ __half g_vl16 [NROW16];
__device__ __half g_kvT16[(size_t)B_ * H_ * D_ * 2 * M_];
__device__ __half g_pph  [NROW16];
__device__ __half g_ppl  [NROW16];
__device__ __half g_sph  [NROW16];
__device__ __half g_spl  [NROW16];
__device__ __half g_prjh [(size_t)M_ * D_];
__device__ __half g_prjl [(size_t)M_ * D_];
__device__ __half g_x16h [NROW16];
__device__ __half g_p16h [NROW16];
__device__ __half g_p16l [NROW16];
__device__ __half g_s16h [NROW16];
__device__ __half g_s16l [NROW16];
__device__ __half g_z16h [NROW16];
__device__ __half g_WvTh [(size_t)DM_ * DM_];
__device__ __half g_WpTh [(size_t)DM_ * DM_];
__device__ __half g_WpTl [(size_t)DM_ * DM_];
__device__ __half g_WoTh [(size_t)DM_ * DM_];

// ===========================================================================
// PTX helpers (base sm_103 ISA: cp.async / ldmatrix / mma.sync)
// ===========================================================================
__device__ __forceinline__ uint32_t smem_u32(const void* p) {
    uint32_t a;
    asm("{ .reg .u64 t; cvta.to.shared.u64 t, %1; cvt.u32.u64 %0, t; }"
        : "=r"(a) : "l"(p));
    return a;
}
__device__ __forceinline__ void ldmatrix_x4(uint32_t* r, uint32_t addr) {
    asm volatile("ldmatrix.sync.aligned.m8n8.x4.shared.b16 {%0,%1,%2,%3}, [%4];"
                 : "=r"(r[0]), "=r"(r[1]), "=r"(r[2]), "=r"(r[3]) : "r"(addr));
}
__device__ __forceinline__ void ldmatrix_x2(uint32_t* r, uint32_t addr) {
    asm volatile("ldmatrix.sync.aligned.m8n8.x2.shared.b16 {%0,%1}, [%2];"
                 : "=r"(r[0]), "=r"(r[1]) : "r"(addr));
}
__device__ __forceinline__ void ldmatrix_x4_t(uint32_t* r, uint32_t addr) {
    asm volatile("ldmatrix.sync.aligned.m8n8.x4.trans.shared.b16 {%0,%1,%2,%3}, [%4];"
                 : "=r"(r[0]), "=r"(r[1]), "=r"(r[2]), "=r"(r[3]) : "r"(addr));
}
__device__ __forceinline__ void ldmatrix_x2_t(uint32_t* r, uint32_t addr) {
    asm volatile("ldmatrix.sync.aligned.m8n8.x2.trans.shared.b16 {%0,%1}, [%2];"
                 : "=r"(r[0]), "=r"(r[1]) : "r"(addr));
}
__device__ __forceinline__ void mma16816(float* c, const uint32_t* a,
                                         const uint32_t* b) {
    asm volatile(
        "mma.sync.aligned.m16n8k16.row.col.f32.f16.f16.f32 "
        "{%0,%1,%2,%3}, {%4,%5,%6,%7}, {%8,%9}, {%0,%1,%2,%3};"
        : "+f"(c[0]), "+f"(c[1]), "+f"(c[2]), "+f"(c[3])
        : "r"(a[0]), "r"(a[1]), "r"(a[2]), "r"(a[3]), "r"(b[0]), "r"(b[1]));
}

#define KC_ 64
#define ROWB 144
#define TB_ (128 * ROWB)               // 18432 per 128x64 tile

// ===========================================================================
// tc_gemm1: C = A @ B^T, single term, compact smem -> 2 CTAs/SM.
// out16: 0 -> fp32 C; 1 -> fp16 Ch/Cl.
// ===========================================================================
#define G1_STAGE (2 * TB_)             // 36864
#define G1_SMEM (2 * G1_STAGE)         // 73728

__global__ __launch_bounds__(256, 2)
void tc_gemm1(const __half* __restrict__ A0, const __half* __restrict__ B0,
              float* __restrict__ C, __half* __restrict__ Ch,
              __half* __restrict__ Cl, int Nld, int K, int out16)
{
    extern __shared__ char smem[];
    const uint32_t sb = smem_u32(smem);
    const int tid = threadIdx.x;
    const int wid = tid >> 5;
    const int lane = tid & 31;
    const int wm = wid & 1;
    const int wn = wid >> 1;
    const int n0 = blockIdx.x * 128;
    const int m0 = blockIdx.y * 128;

    const uint32_t a_off = (uint32_t)((((lane >> 3) & 1) * 8 + (lane & 7)) * ROWB
                                      + ((lane >> 4) * 8) * 2);
    const int bl_ = lane & 15;
    const uint32_t b_off = (uint32_t)(((bl_ & 7)) * ROWB + (((bl_ >> 3) & 1) * 8) * 2);

    float acc[4][4][4];
#pragma unroll
    for (int i = 0; i < 4; i++)
#pragma unroll
        for (int j = 0; j < 4; j++)
#pragma unroll
            for (int q = 0; q < 4; q++) acc[i][j][q] = 0.0f;

    const int nch = K / KC_;

    auto load_stage = [&](int s, int chunk) {
        const int k0 = chunk * KC_;
        const uint32_t stage = sb + s * G1_STAGE;
#pragma unroll
        for (int buf = 0; buf < 2; buf++) {
            const __half* src = buf ? B0 : A0;
            const int r0 = buf ? n0 : m0;
            const uint32_t tb = stage + buf * TB_;
#pragma unroll
            for (int j = 0; j < 4; j++) {
                const int c = tid + j * 256;
                const int row = c >> 3;
                const int seg = c & 7;
                const uint32_t dst = tb + (uint32_t)(row * ROWB + seg * 16);
                const __half* sp = src + (size_t)(r0 + row) * K + k0 + seg * 8;
                asm volatile("cp.async.cg.shared.global [%0], [%1], 16;\n"
                             :: "r"(dst), "l"(sp));
            }
        }
        asm volatile("cp.async.commit_group;\n");
    };

    load_stage(0, 0);

    for (int i = 0; i < nch; i++) {
        const int s = i & 1;
        if (i + 1 < nch) {
            load_stage(s ^ 1, i + 1);
            asm volatile("cp.async.wait_group 1;\n");
        } else {
            asm volatile("cp.async.wait_group 0;\n");
        }
        __syncthreads();

        const uint32_t stage = sb + s * G1_STAGE;
        const uint32_t Ah = stage;
        const uint32_t Bh = stage + TB_;
        const uint32_t a_row = (uint32_t)(wm * 64 * ROWB);
        const uint32_t b_row = (uint32_t)(wn * 32 * ROWB);

#pragma unroll
        for (int kk = 0; kk < 4; kk++) {
            const uint32_t kb = (uint32_t)(kk * 32);
            uint32_t ah[4][4], bh[4][2];
#pragma unroll
            for (int mf = 0; mf < 4; mf++)
                ldmatrix_x4(ah[mf], Ah + a_row + (uint32_t)(mf * 16 * ROWB) + kb + a_off);
#pragma unroll
            for (int nf = 0; nf < 4; nf++)
                ldmatrix_x2(bh[nf], Bh + b_row + (uint32_t)(nf * 8 * ROWB) + kb + b_off);
#pragma unroll
            for (int mf = 0; mf < 4; mf++)
#pragma unroll
                for (int nf = 0; nf < 4; nf++)
                    mma16816(acc[mf][nf], ah[mf], bh[nf]);
        }
        __syncthreads();
    }

    const int mrow = lane >> 2;
    const int ncol = (lane & 3) * 2;
#pragma unroll
    for (int mf = 0; mf < 4; mf++) {
        const int gm = m0 + wm * 64 + mf * 16 + mrow;
#pragma unroll
        for (int nf = 0; nf < 4; nf++) {
            const int gn = n0 + wn * 32 + nf * 8 + ncol;
            if (!out16) {
                *(float2*)(C + (size_t)gm * Nld + gn) =
                    make_float2(acc[mf][nf][0], acc[mf][nf][1]);
                *(float2*)(C + (size_t)(gm + 8) * Nld + gn) =
                    make_float2(acc[mf][nf][2], acc[mf][nf][3]);
            } else {
#pragma unroll
                for (int hh = 0; hh < 2; hh++) {
                    const float v0 = acc[mf][nf][hh * 2 + 0];
                    const float v1 = acc[mf][nf][hh * 2 + 1];
                    const __half h0 = __float2half_rn(v0);
                    const __half h1 = __float2half_rn(v1);
                    const __half e0 = __float2half_rn(v0 - __half2float(h0));
                    const __half e1 = __float2half_rn(v1 - __half2float(h1));
                    const size_t o = (size_t)(gm + hh * 8) * Nld + gn;
                    *(__half2*)(Ch + o) = __halves2half2(h0, h1);
                    *(__half2*)(Cl + o) = __halves2half2(e0, e1);
                }
            }
        }
    }
}

// ===========================================================================
// tc_gemm_pair: two 3-term GEMMs sharing B (Wp hi/lo):
//   Cp = (Ap0+Ap1) @ (B0+B1)^T,  Cs = (As0+As1) @ (B0+B1)^T
// Buffers/stage: Aph, Apl, Ash, Asl, Bh, Bl  (6 x 18432 = 110592)
// ===========================================================================
#define GP_STAGE (6 * TB_)             // 110592
#define GP_SMEM (2 * GP_STAGE)         // 221184

__global__ __launch_bounds__(256, 1)
void tc_gemm_pair(const __half* __restrict__ Ap0, const __half* __restrict__ Ap1,
                  const __half* __restrict__ As0, const __half* __restrict__ As1,
                  const __half* __restrict__ B0, const __half* __restrict__ B1,
                  __half* __restrict__ Chp, __half* __restrict__ Clp,
                  __half* __restrict__ Chs, __half* __restrict__ Cls,
                  int Nld, int K)
{
    extern __shared__ char smem[];
    const uint32_t sb = smem_u32(smem);
    const int tid = threadIdx.x;
    const int wid = tid >> 5;
    const int lane = tid & 31;
    const int wm = wid & 1;
    const int wn = wid >> 1;
    const int n0 = blockIdx.x * 128;
    const int m0 = blockIdx.y * 128;

    const __half* srcs[6] = {Ap0, Ap1, As0, As1, B0, B1};

    const uint32_t a_off = (uint32_t)((((lane >> 3) & 1) * 8 + (lane & 7)) * ROWB
                                      + ((lane >> 4) * 8) * 2);
    const int bl_ = lane & 15;
    const uint32_t b_off = (uint32_t)(((bl_ & 7)) * ROWB + (((bl_ >> 3) & 1) * 8) * 2);

    float accp[4][4][4], accs[4][4][4];
#pragma unroll
    for (int i = 0; i < 4; i++)
#pragma unroll
        for (int j = 0; j < 4; j++)
#pragma unroll
            for (int q = 0; q < 4; q++) { accp[i][j][q] = 0.0f; accs[i][j][q] = 0.0f; }

    const int nch = K / KC_;

    auto load_stage = [&](int s, int chunk) {
        const int k0 = chunk * KC_;
        const uint32_t stage = sb + s * GP_STAGE;
#pragma unroll
        for (int buf = 0; buf < 6; buf++) {
            const __half* src = srcs[buf];
            const int r0 = (buf < 4) ? m0 : n0;
            const uint32_t tb = stage + buf * TB_;
#pragma unroll
            for (int j = 0; j < 4; j++) {
                const int c = tid + j * 256;
                const int row = c >> 3;
                const int seg = c & 7;
                const uint32_t dst = tb + (uint32_t)(row * ROWB + seg * 16);
                const __half* sp = src + (size_t)(r0 + row) * K + k0 + seg * 8;
                asm volatile("cp.async.cg.shared.global [%0], [%1], 16;\n"
                             :: "r"(dst), "l"(sp));
            }
        }
        asm volatile("cp.async.commit_group;\n");
    };

    load_stage(0, 0);

    for (int i = 0; i < nch; i++) {
        const int s = i & 1;
        if (i + 1 < nch) {
            load_stage(s ^ 1, i + 1);
            asm volatile("cp.async.wait_group 1;\n");
        } else {
            asm volatile("cp.async.wait_group 0;\n");
        }
        __syncthreads();

        const uint32_t stage = sb + s * GP_STAGE;
        const uint32_t Bh = stage + 4 * TB_;
        const uint32_t Bl = stage + 5 * TB_;
        const uint32_t a_row = (uint32_t)(wm * 64 * ROWB);
        const uint32_t b_row = (uint32_t)(wn * 32 * ROWB);

#pragma unroll
        for (int kk = 0; kk < 4; kk++) {
            const uint32_t kb = (uint32_t)(kk * 32);
            uint32_t bh[4][2], blr[4][2];
#pragma unroll
            for (int nf = 0; nf < 4; nf++) {
                const uint32_t ro = b_row + (uint32_t)(nf * 8 * ROWB) + kb + b_off;
                ldmatrix_x2(bh[nf], Bh + ro);
                ldmatrix_x2(blr[nf], Bl + ro);
            }
#pragma unroll
            for (int set = 0; set < 2; set++) {
                const uint32_t AH = stage + (set ? 2 : 0) * TB_;
                const uint32_t AL = stage + (set ? 3 : 1) * TB_;
                uint32_t ah[4][4], al[4][4];
#pragma unroll
                for (int mf = 0; mf < 4; mf++) {
                    const uint32_t ro = a_row + (uint32_t)(mf * 16 * ROWB) + kb + a_off;
                    ldmatrix_x4(ah[mf], AH + ro);
                    ldmatrix_x4(al[mf], AL + ro);
                }
#pragma unroll
                for (int mf = 0; mf < 4; mf++)
#pragma unroll
                    for (int nf = 0; nf < 4; nf++) {
                        if (set == 0) {
                            mma16816(accp[mf][nf], ah[mf], bh[nf]);
                            mma16816(accp[mf][nf], al[mf], bh[nf]);
                            mma16816(accp[mf][nf], ah[mf], blr[nf]);
                        } else {
                            mma16816(accs[mf][nf], ah[mf], bh[nf]);
                            mma16816(accs[mf][nf], al[mf], bh[nf]);
                            mma16816(accs[mf][nf], ah[mf], blr[nf]);
                        }
                    }
            }
        }
        __syncthreads();
    }

    const int mrow = lane >> 2;
    const int ncol = (lane & 3) * 2;
#pragma unroll
    for (int set = 0; set < 2; set++) {
        __half* Ch = set ? Chs : Chp;
        __half* Cl = set ? Cls : Clp;
#pragma unroll
        for (int mf = 0; mf < 4; mf++) {
            const int gm = m0 + wm * 64 + mf * 16 + mrow;
#pragma unroll
            for (int nf = 0; nf < 4; nf++) {
                const int gn = n0 + wn * 32 + nf * 8 + ncol;
#pragma unroll
                for (int hh = 0; hh < 2; hh++) {
                    const float v0 = set ? accs[mf][nf][hh * 2 + 0]
                                         : accp[mf][nf][hh * 2 + 0];
                    const float v1 = set ? accs[mf][nf][hh * 2 + 1]
                                         : accp[mf][nf][hh * 2 + 1];
                    const __half h0 = __float2half_rn(v0);
                    const __half h1 = __float2half_rn(v1);
                    const __half e0 = __float2half_rn(v0 - __half2float(h0));
                    const __half e1 = __float2half_rn(v1 - __half2float(h1));
                    const size_t o = (size_t)(gm + hh * 8) * Nld + gn;
                    *(__half2*)(Ch + o) = __halves2half2(h0, h1);
                    *(__half2*)(Cl + o) = __halves2half2(e0, e1);
                }
            }
        }
    }
}

// ===========================================================================
// split / transpose helpers
// ===========================================================================
__global__ __launch_bounds__(256)
void split2_kernel(const float* __restrict__ src, __half* __restrict__ hi,
                   __half* __restrict__ lo)
{
    const size_t i0 = ((size_t)blockIdx.x * 256 + threadIdx.x) * 4;
    float4 v = *(const float4*)(src + i0);
    float f[4] = {v.x, v.y, v.z, v.w};
    __half2 h2[2], l2[2];
#pragma unroll
    for (int j = 0; j < 2; j++) {
        __half ha = __float2half_rn(f[j * 2]);
        __half hb = __float2half_rn(f[j * 2 + 1]);
        h2[j] = __halves2half2(ha, hb);
        l2[j] = __halves2half2(__float2half_rn(f[j * 2] - __half2float(ha)),
                               __float2half_rn(f[j * 2 + 1] - __half2float(hb)));
    }
    *(__half2*)(hi + i0)     = h2[0];
    *(__half2*)(hi + i0 + 2) = h2[1];
    *(__half2*)(lo + i0)     = l2[0];
    *(__half2*)(lo + i0 + 2) = l2[1];
}

__global__ __launch_bounds__(256)
void split1_kernel(const float* __restrict__ src, __half* __restrict__ hi)
{
    const size_t i0 = ((size_t)blockIdx.x * 256 + threadIdx.x) * 4;
    float4 v = *(const float4*)(src + i0);
    __half2 a = __halves2half2(__float2half_rn(v.x), __float2half_rn(v.y));
    __half2 b = __halves2half2(__float2half_rn(v.z), __float2half_rn(v.w));
    *(__half2*)(hi + i0)     = a;
    *(__half2*)(hi + i0 + 2) = b;
}

__global__ __launch_bounds__(256)
void wtrans_split_kernel(const float* __restrict__ W, __half* __restrict__ th,
                         __half* __restrict__ tl)
{
    __shared__ float tile[32][33];
    const int tx = threadIdx.x & 31;
    const int ty = threadIdx.x >> 5;
    const int n0 = blockIdx.x * 32;
    const int k0 = blockIdx.y * 32;
#pragma unroll
    for (int i = 0; i < 4; i++)
        tile[ty + i * 8][tx] = W[(size_t)(k0 + ty + i * 8) * DM_ + n0 + tx];
    __syncthreads();
#pragma unroll
    for (int i = 0; i < 4; i++) {
        const int n = ty + i * 8;
        float v = tile[tx][n];
        __half h = __float2half_rn(v);
        const size_t o = (size_t)(n0 + n) * DM_ + k0 + tx;
        th[o] = h;
        if (tl) tl[o] = __float2half_rn(v - __half2float(h));
    }
}

__global__ __launch_bounds__(256)
void proj_split_kernel(const float* __restrict__ proj, __half* __restrict__ ph,
                       __half* __restrict__ pl)
{
    const int i = blockIdx.x * 256 + threadIdx.x;
    if (i < M_ * D_) {
        const float v = NORMALIZER * proj[i];
        const __half h = __float2half_rn(v);
        ph[i] = h;
        pl[i] = __float2half_rn(v - __half2float(h));
    }
}

// ===========================================================================
// feat3 (unchanged from R9)
// ===========================================================================
#define F3_AT (128 * ROWB)
#define F3_STAGE_OFF (6 * F3_AT)
#define F3_SMEM (F3_STAGE_OFF + 8 * 16 * 256 * 2)

__global__ __launch_bounds__(256, 1)
void feat3_kernel(const __half* __restrict__ pph, const __half* __restrict__ ppl,
                  const __half* __restrict__ sph, const __half* __restrict__ spl,
                  const __half* __restrict__ prjh, const __half* __restrict__ prjl,
                  const float* __restrict__ scale, const float* __restrict__ offs,
                  __half* __restrict__ qp16, __half* __restrict__ kh16,
                  __half* __restrict__ kl16, float* __restrict__ nf)
{
    extern __shared__ char smem[];
    __shared__ float nfp[256];
    const uint32_t sb = smem_u32(smem);
    const int tid = threadIdx.x;
    const int wid = tid >> 5;
    const int lane = tid & 31;
    const int h = blockIdx.y;
    const int r0 = blockIdx.x * 128;
    const float s = scale[h];
    const float off = offs[h];

    {
        const __half* abuf[4] = {pph, ppl, sph, spl};
#pragma unroll
        for (int buf = 0; buf < 4; buf++) {
#pragma unroll
            for (int j = 0; j < 4; j++) {
                const int c = tid + j * 256;
                const int row = c >> 3;
                const int seg = c & 7;
                const uint32_t dst = sb + (uint32_t)(buf * F3_AT + row * ROWB + seg * 16);
                const __half* sp_ = abuf[buf] + (size_t)(r0 + row) * DM_ + h * 64 + seg * 8;
                asm volatile("cp.async.cg.shared.global [%0], [%1], 16;\n"
                             :: "r"(dst), "l"(sp_));
            }
        }
        const __half* pbuf[2] = {prjh, prjl};
#pragma unroll
        for (int buf = 0; buf < 2; buf++) {
#pragma unroll
            for (int j = 0; j < 4; j++) {
                const int c = tid + j * 256;
                const int row = c >> 3;
                const int seg = c & 7;
                const uint32_t dst = sb + (uint32_t)((4 + buf) * F3_AT + row * ROWB + seg * 16);
                asm volatile("cp.async.cg.shared.global [%0], [%1], 16;\n"
                             :: "r"(dst), "l"(pbuf[buf] + row * 64 + seg * 8));
            }
        }
        asm volatile("cp.async.commit_group;\n");
        asm volatile("cp.async.wait_group 0;\n");
        __syncthreads();
    }

    {
        const int r = tid >> 1;
        const int hf = tid & 1;
        const uint32_t bh_ = sb + (uint32_t)(2 * F3_AT + r * ROWB + hf * 64);
        const uint32_t bl_ = sb + (uint32_t)(3 * F3_AT + r * ROWB + hf * 64);
        float s2 = 0.0f;
#pragma unroll
        for (int j = 0; j < 16; j++) {
            __half2 vh = *(__half2*)(smem + (bh_ - sb) + j * 4);
            __half2 vl = *(__half2*)(smem + (bl_ - sb) + j * 4);
            const float a0 = __half2float(__low2half(vh)) + __half2float(__low2half(vl));
            const float a1 = __half2float(__high2half(vh)) + __half2float(__high2half(vl));
            s2 += a0 * a0 + a1 * a1;
        }
        nfp[tid] = s2;
    }
    __syncthreads();
    if (tid < 128) {
        const float v2 = nfp[tid * 2] + nfp[tid * 2 + 1];
        nf[(size_t)(r0 + tid) * H_ + h] = sqrtf(v2) * (1.0f / (float)L_);
    }

    const uint32_t a_off = (uint32_t)((((lane >> 3) & 1) * 8 + (lane & 7)) * ROWB
                                      + ((lane >> 4) * 8) * 2);
    const int bl_ = lane & 15;
    const uint32_t b_off = (uint32_t)(((bl_ & 7)) * ROWB + (((bl_ >> 3) & 1) * 8) * 2);

    float g1[16][4], g2[16][4];
#pragma unroll
    for (int i = 0; i < 16; i++)
#pragma unroll
        for (int q = 0; q < 4; q++) { g1[i][q] = 0.0f; g2[i][q] = 0.0f; }

    const uint32_t APH = sb;
    const uint32_t APL = sb + F3_AT;
    const uint32_t ASH = sb + 2 * F3_AT;
    const uint32_t ASL = sb + 3 * F3_AT;
    const uint32_t BH  = sb + 4 * F3_AT;
    const uint32_t BL  = sb + 5 * F3_AT;
    const uint32_t a_base = (uint32_t)(wid * 16 * ROWB) + a_off;

#pragma unroll
    for (int kk = 0; kk < 4; kk++) {
        const uint32_t kb = (uint32_t)(kk * 32);
        uint32_t aph[4], apl[4], ash[4], asl[4];
        ldmatrix_x4(aph, APH + a_base + kb);
        ldmatrix_x4(apl, APL + a_base + kb);
        ldmatrix_x4(ash, ASH + a_base + kb);
        ldmatrix_x4(asl, ASL + a_base + kb);
#pragma unroll
        for (int nf8 = 0; nf8 < 16; nf8++) {
            const uint32_t ro = (uint32_t)(nf8 * 8 * ROWB) + kb + b_off;
            uint32_t bh2[2], bl2[2];
            ldmatrix_x2(bh2, BH + ro);
            ldmatrix_x2(bl2, BL + ro);
            mma16816(g1[nf8], aph, bh2);
            mma16816(g1[nf8], apl, bh2);
            mma16816(g1[nf8], aph, bl2);
            mma16816(g2[nf8], ash, bh2);
            mma16816(g2[nf8], asl, bh2);
            mma16816(g2[nf8], ash, bl2);
        }
    }

    const int mrow = lane >> 2;
    const int ncol = (lane & 3) * 2;
    const uint32_t stage = sb + (uint32_t)(F3_STAGE_OFF + wid * 8192);

#pragma unroll
    for (int pass = 0; pass < 3; pass++) {
#pragma unroll
        for (int nf8 = 0; nf8 < 16; nf8++) {
#pragma unroll
            for (int hh = 0; hh < 2; hh++) {
                const int lr = mrow + hh * 8;
                const int m = nf8 * 8 + ncol;
                float d0, d1;
                if (pass == 0) {
                    d0 = s * g1[nf8][hh * 2 + 0];
                    d1 = s * g1[nf8][hh * 2 + 1];
                } else {
                    d0 = s * (g1[nf8][hh * 2 + 0] + off * g2[nf8][hh * 2 + 0]);
                    d1 = s * (g1[nf8][hh * 2 + 1] + off * g2[nf8][hh * 2 + 1]);
                }
                float s0, c0, s1, c1;
                __sincosf(d0, &s0, &c0);
                __sincosf(d1, &s1, &c1);
                s0 *= RATIO; c0 *= RATIO; s1 *= RATIO; c1 *= RATIO;
                __half2 vs, vc;
                if (pass < 2) {
                    vs = __halves2half2(__float2half_rn(s0), __float2half_rn(s1));
                    vc = __halves2half2(__float2half_rn(c0), __float2half_rn(c1));
                } else {
                    const __half hs0 = __float2half_rn(s0);
                    const __half hs1 = __float2half_rn(s1);
                    const __half hc0 = __float2half_rn(c0);
                    const __half hc1 = __float2half_rn(c1);
                    vs = __halves2half2(__float2half_rn(s0 - __half2float(hs0)),
                                        __float2half_rn(s1 - __half2float(hs1)));
                    vc = __halves2half2(__float2half_rn(c0 - __half2float(hc0)),
                                        __float2half_rn(c1 - __half2float(hc1)));
                }
                *(__half2*)(smem + (stage - sb) + lr * 512 + m * 2) = vs;
                *(__half2*)(smem + (stage - sb) + lr * 512 + (M_ + m) * 2) = vc;
            }
        }
        __syncwarp();
        __half* outp = (pass == 0) ? qp16 : (pass == 1 ? kh16 : kl16);
#pragma unroll
        for (int it = 0; it < 16; it++) {
            const int idx = lane + it * 32;
            const int lr = idx >> 5;
            const int seg = idx & 31;
            const uint4 v = *(uint4*)(smem + (stage - sb) + lr * 512 + seg * 16);
            *(uint4*)(outp + ((size_t)(r0 + wid * 16 + lr) * H_ + h) * (2 * M_)
                      + seg * 8) = v;
        }
        __syncwarp();
    }
}

// ===========================================================================
// kv_hmma (unchanged)
// ===========================================================================
#define KROWB 528
#define VROWB 144
#define KTB (64 * KROWB)
#define VTB (64 * VROWB)
#define KV_STAGE (2 * KTB + 2 * VTB)
#define KV_SMEM (2 * KV_STAGE)

__global__ __launch_bounds__(256, 1)
void kv_hmma_kernel(const __half* __restrict__ kh16, const __half* __restrict__ kl16,
                    const __half* __restrict__ vh16, const __half* __restrict__ vl16,
                    float* __restrict__ part)
{
    extern __shared__ char smem[];
    const uint32_t sb = smem_u32(smem);
    const int tid = threadIdx.x;
    const int wid = tid >> 5;
    const int lane = tid & 31;
    const int wm = wid & 3;
    const int wd = wid >> 2;
    const int chunk = blockIdx.x;
    const int h = blockIdx.y;
    const int b = blockIdx.z;
    const int lbase = chunk * LC_;

    const int grp = lane >> 3;
    const int lrow = lane & 7;
    const uint32_t a_off = (uint32_t)(((grp >> 1) * 8 + lrow) * KROWB
                                      + ((grp & 1) * 8) * 2);
    const int bl_ = lane & 15;
    const uint32_t b_off = (uint32_t)((((bl_ >> 3) * 8) + (bl_ & 7)) * VROWB);

    float acc[4][4][4];
#pragma unroll
    for (int i = 0; i < 4; i++)
#pragma unroll
        for (int j = 0; j < 4; j++)
#pragma unroll
            for (int q = 0; q < 4; q++) acc[i][j][q] = 0.0f;

    auto load_stage = [&](int s, int it) {
        const int l0 = lbase + it * 64;
        const uint32_t stage = sb + s * KV_STAGE;
#pragma unroll
        for (int j = 0; j < 8; j++) {
            const int c = tid + j * 256;
            const int row = c >> 5;
            const int seg = c & 31;
            const size_t src = ((size_t)(b * L_ + l0 + row) * H_ + h) * (2 * M_) + seg * 8;
            const uint32_t d0 = stage + (uint32_t)(row * KROWB + seg * 16);
            asm volatile("cp.async.cg.shared.global [%0], [%1], 16;\n"
                         :: "r"(d0), "l"(kh16 + src));
            asm volatile("cp.async.cg.shared.global [%0], [%1], 16;\n"
                         :: "r"(d0 + KTB), "l"(kl16 + src));
        }
#pragma unroll
        for (int j = 0; j < 2; j++) {
            const int c = tid + j * 256;
            const int row = c >> 3;
            const int seg = c & 7;
            const size_t src = (size_t)(b * L_ + l0 + row) * DM_ + h * 64 + seg * 8;
            const uint32_t d0 = stage + (uint32_t)(2 * KTB + row * VROWB + seg * 16);
            asm volatile("cp.async.cg.shared.global [%0], [%1], 16;\n"
                         :: "r"(d0), "l"(vh16 + src));
            asm volatile("cp.async.cg.shared.global [%0], [%1], 16;\n"
                         :: "r"(d0 + VTB), "l"(vl16 + src));
        }
        asm volatile("cp.async.commit_group;\n");
    };

    const int NIT = LC_ / 64;
    load_stage(0, 0);

    for (int it = 0; it < NIT; it++) {
        const int s = it & 1;
        if (it + 1 < NIT) {
            load_stage(s ^ 1, it + 1);
            asm volatile("cp.async.wait_group 1;\n");
        } else {
            asm volatile("cp.async.wait_group 0;\n");
        }
        __syncthreads();

        const uint32_t stage = sb + s * KV_STAGE;
        const uint32_t KH = stage;
        const uint32_t KL = stage + KTB;
        const uint32_t VH = stage + 2 * KTB;
        const uint32_t VL = VH + VTB;
        const uint32_t a_base = (uint32_t)((wm * 64) * 2) + a_off;
        const uint32_t b_base = (uint32_t)((wd * 32) * 2) + b_off;

#pragma unroll
        for (int kk = 0; kk < 4; kk++) {
            uint32_t akh[4][4], akl[4][4], bvh[4][2], bvl[4][2];
#pragma unroll
            for (int mf = 0; mf < 4; mf++) {
                const uint32_t ro = (uint32_t)(kk * 16 * KROWB) + a_base
                                    + (uint32_t)(mf * 16 * 2);
                ldmatrix_x4_t(akh[mf], KH + ro);
                ldmatrix_x4_t(akl[mf], KL + ro);
            }
#pragma unroll
            for (int nf = 0; nf < 4; nf++) {
                const uint32_t ro = (uint32_t)(kk * 16 * VROWB) + b_base
                                    + (uint32_t)(nf * 8 * 2);
                ldmatrix_x2_t(bvh[nf], VH + ro);
                ldmatrix_x2_t(bvl[nf], VL + ro);
            }
#pragma unroll
            for (int mf = 0; mf < 4; mf++)
#pragma unroll
                for (int nf = 0; nf < 4; nf++) {
                    mma16816(acc[mf][nf], akh[mf], bvh[nf]);
                    mma16816(acc[mf][nf], akl[mf], bvh[nf]);
                    mma16816(acc[mf][nf], akh[mf], bvl[nf]);
                }
        }
        __syncthreads();
    }

    const size_t pbase = ((size_t)((b * H_ + h) * NCHUNK + chunk)) * (2 * M_ * D_);
    const int mrow = lane >> 2;
    const int ncol = (lane & 3) * 2;
#pragma unroll
    for (int mf = 0; mf < 4; mf++) {
        const int m = wm * 64 + mf * 16 + mrow;
#pragma unroll
        for (int nf = 0; nf < 4; nf++) {
            const int d = wd * 32 + nf * 8 + ncol;
            *(float2*)(part + pbase + (size_t)m * D_ + d) =
                make_float2(acc[mf][nf][0], acc[mf][nf][1]);
            *(float2*)(part + pbase + (size_t)(m + 8) * D_ + d) =
                make_float2(acc[mf][nf][2], acc[mf][nf][3]);
        }
    }
}

__global__ __launch_bounds__(256)
void kv_reduce_kernel(const float* __restrict__ part, __half* __restrict__ kvt)
{
    const int idx = blockIdx.x * 256 + threadIdx.x;
    const int bh = idx / (2 * M_ * D_);
    const int md = idx % (2 * M_ * D_);
    float s = 0.0f;
#pragma unroll
    for (int c = 0; c < NCHUNK; c++)
        s += part[((size_t)bh * NCHUNK + c) * (2 * M_ * D_) + md];
    const int m = md >> 6;
    const int d = md & 63;
    kvt[((size_t)bh * D_ + d) * (2 * M_) + m] = __float2half_rn(s);
}

// ===========================================================================
// z_hmma (unchanged)
// ===========================================================================
#define ROWZB 528
#define ZA_BYTES (128 * ROWZB)
#define ZB_BYTES (64 * ROWZB)
#define Z_SMEM (ZA_BYTES + ZB_BYTES)

__global__ __launch_bounds__(256)
void z_hmma_kernel(const __half* __restrict__ qp16, const __half* __restrict__ kvt,
                   const float* __restrict__ nf, __half* __restrict__ zh)
{
    extern __shared__ char smem[];
    const uint32_t sb = smem_u32(smem);
    const int tid = threadIdx.x;
    const int wid = tid >> 5;
    const int lane = tid & 31;
    const int lt = blockIdx.x;
    const int h = blockIdx.y;
    const int b = blockIdx.z;
    const int l0 = lt * 128;

    {
        const __half* src = qp16 + ((size_t)(b * L_ + l0) * H_ + h) * (2 * M_);
#pragma unroll
        for (int j = 0; j < 16; j++) {
            const int c = tid + j * 256;
            const int row = c >> 5;
            const int seg = c & 31;
            const uint32_t dst = sb + (uint32_t)(row * ROWZB + seg * 16);
            asm volatile("cp.async.cg.shared.global [%0], [%1], 16;\n"
                         :: "r"(dst), "l"(src + (size_t)row * H_ * (2 * M_) + seg * 8));
        }
    }
    {
        const __half* src = kvt + (size_t)(b * H_ + h) * D_ * (2 * M_);
#pragma unroll
        for (int j = 0; j < 8; j++) {
            const int c = tid + j * 256;
            const int row = c >> 5;
            const int seg = c & 31;
            const uint32_t dst = sb + (uint32_t)(ZA_BYTES + row * ROWZB + seg * 16);
            asm volatile("cp.async.cg.shared.global [%0], [%1], 16;\n"
                         :: "r"(dst), "l"(src + (size_t)row * (2 * M_) + seg * 8));
        }
    }
    asm volatile("cp.async.commit_group;\n");
    asm volatile("cp.async.wait_group 0;\n");
    __syncthreads();

    const uint32_t a_off = (uint32_t)((((lane >> 3) & 1) * 8 + (lane & 7)) * ROWZB
                                      + (lane >> 4) * 16);
    const int bl_ = lane & 15;
    const uint32_t b_off = (uint32_t)((bl_ & 7) * ROWZB + ((bl_ >> 3) & 1) * 16);

    float acc[8][4];
#pragma unroll
    for (int j = 0; j < 8; j++)
#pragma unroll
        for (int q = 0; q < 4; q++) acc[j][q] = 0.0f;

    const uint32_t a_base = sb + (uint32_t)(wid * 16 * ROWZB) + a_off;
    const uint32_t b_base = sb + ZA_BYTES + b_off;

#pragma unroll
    for (int kk = 0; kk < 16; kk++) {
        const uint32_t kb = (uint32_t)(kk * 32);
        uint32_t a[4];
        ldmatrix_x4(a, a_base + kb);
#pragma unroll
        for (int j = 0; j < 8; j++) {
            uint32_t bfr[2];
            ldmatrix_x2(bfr, b_base + (uint32_t)(j * 8 * ROWZB) + kb);
            mma16816(acc[j], a, bfr);
        }
    }

    const int mrow = lane >> 2;
    const int ncol = (lane & 3) * 2;
    const int gl0 = l0 + wid * 16 + mrow;
    const float f0 = nf[(size_t)(b * L_ + gl0) * H_ + h];
    const float f1 = nf[(size_t)(b * L_ + gl0 + 8) * H_ + h];
#pragma unroll
    for (int j = 0; j < 8; j++) {
        const int gn = h * 64 + j * 8 + ncol;
#pragma unroll
        for (int half = 0; half < 2; half++) {
            const int row = gl0 + half * 8;
            const float f = half ? f1 : f0;
            const float v0 = acc[j][half * 2 + 0] * f;
            const float v1 = acc[j][half * 2 + 1] * f;
            const size_t o = (size_t)(b * L_ + row) * DM_ + gn;
            *(__half2*)(zh + o) = __halves2half2(__float2half_rn(v0),
                                                 __float2half_rn(v1));
        }
    }
}

// ===========================================================================
extern "C" void kernel_launch(void* const* d_in, const int* in_sizes, int n_in,
                              void* d_out, int out_size)
{
    const float* x   = (const float*)d_in[0];
    const float* pft = (const float*)d_in[1];
    const float* psl = (const float*)d_in[2];
    const float* Wv  = (const float*)d_in[3];
    const float* Wo  = (const float*)d_in[4];
    const float* Wp  = (const float*)d_in[5];
    const float* sc  = (const float*)d_in[6];
    const float* ofs = (const float*)d_in[7];
    const float* prj = (const float*)d_in[8];
    float* out = (float*)d_out;

    float *ppart, *pnf;
    cudaGetSymbolAddress((void**)&ppart, g_part);
    cudaGetSymbolAddress((void**)&pnf,   g_nf);

    __half *pqp16, *pkh, *pkl, *pvh, *pvl, *pkvt;
    __half *ppph, *pppl, *psph, *pspl, *pprjh, *pprjl;
    cudaGetSymbolAddress((void**)&pqp16, g_qp16);
    cudaGetSymbolAddress((void**)&pkh,   g_kh16);
    cudaGetSymbolAddress((void**)&pkl,   g_kl16);
    cudaGetSymbolAddress((void**)&pvh,   g_vh16);
    cudaGetSymbolAddress((void**)&pvl,   g_vl16);
    cudaGetSymbolAddress((void**)&pkvt,  g_kvT16);
    cudaGetSymbolAddress((void**)&ppph,  g_pph);
    cudaGetSymbolAddress((void**)&pppl,  g_ppl);
    cudaGetSymbolAddress((void**)&psph,  g_sph);
    cudaGetSymbolAddress((void**)&pspl,  g_spl);
    cudaGetSymbolAddress((void**)&pprjh, g_prjh);
    cudaGetSymbolAddress((void**)&pprjl, g_prjl);

    __half *xh, *ph, *pl, *sh, *sl, *zh;
    __half *wvh, *wph, *wpl, *woh;
    cudaGetSymbolAddress((void**)&xh,  g_x16h);
    cudaGetSymbolAddress((void**)&ph,  g_p16h);
    cudaGetSymbolAddress((void**)&pl,  g_p16l);
    cudaGetSymbolAddress((void**)&sh,  g_s16h);
    cudaGetSymbolAddress((void**)&sl,  g_s16l);
    cudaGetSymbolAddress((void**)&zh,  g_z16h);
    cudaGetSymbolAddress((void**)&wvh, g_WvTh);
    cudaGetSymbolAddress((void**)&wph, g_WpTh);
    cudaGetSymbolAddress((void**)&wpl, g_WpTl);
    cudaGetSymbolAddress((void**)&woh, g_WoTh);

    cudaFuncSetAttribute(tc_gemm1, cudaFuncAttributeMaxDynamicSharedMemorySize,
                         G1_SMEM);
    cudaFuncSetAttribute(tc_gemm_pair, cudaFuncAttributeMaxDynamicSharedMemorySize,
                         GP_SMEM);
    cudaFuncSetAttribute(feat3_kernel, cudaFuncAttributeMaxDynamicSharedMemorySize,
                         F3_SMEM);
    cudaFuncSetAttribute(kv_hmma_kernel, cudaFuncAttributeMaxDynamicSharedMemorySize,
                         KV_SMEM);
    cudaFuncSetAttribute(z_hmma_kernel, cudaFuncAttributeMaxDynamicSharedMemorySize,
                         Z_SMEM);

    const int Mrows = B_ * L_;                       // 16384
    const int nsplit = (int)(NROW16 / 1024);

    split1_kernel<<<nsplit, 256>>>(x, xh);
    split2_kernel<<<nsplit, 256>>>(pft, ph, pl);
    split2_kernel<<<nsplit, 256>>>(psl, sh, sl);
    dim3 wg(DM_ / 32, DM_ / 32);
    wtrans_split_kernel<<<wg, 256>>>(Wv, wvh, (__half*)0);
    wtrans_split_kernel<<<wg, 256>>>(Wp, wph, wpl);
    wtrans_split_kernel<<<wg, 256>>>(Wo, woh, (__half*)0);
    proj_split_kernel<<<(M_ * D_ + 255) / 256, 256>>>(prj, pprjh, pprjl);

    dim3 gg(DM_ / 128, Mrows / 128);                 // (8, 128)
    // v GEMM: 1-term compact, fp16 hi/lo output
    tc_gemm1<<<gg, 256, G1_SMEM>>>(xh, wvh, (float*)0, pvh, pvl, DM_, DM_, 1);
    // pos+slope fused 3-term pair, fp16 hi/lo outputs
    tc_gemm_pair<<<gg, 256, GP_SMEM>>>(ph, pl, sh, sl, wph, wpl,
                                       ppph, pppl, psph, pspl, DM_, DM_);

    feat3_kernel<<<dim3(Mrows / 128, H_), 256, F3_SMEM>>>(
        ppph, pppl, psph, pspl, pprjh, pprjl, sc, ofs, pqp16, pkh, pkl, pnf);

    kv_hmma_kernel<<<dim3(NCHUNK, H_, B_), 256, KV_SMEM>>>(pkh, pkl, pvh, pvl, ppart);
    kv_reduce_kernel<<<(B_ * H_ * 2 * M_ * D_) / 256, 256>>>(ppart, pkvt);

    z_hmma_kernel<<<dim3(L_ / 128, H_, B_), 256, Z_SMEM>>>(pqp16, pkvt, pnf, zh);

    // out GEMM: 1-term compact, fp32 output
    tc_gemm1<<<gg, 256, G1_SMEM>>>(zh, woh, out, (__half*)0, (__half*)0, DM_, DM_, 0);
}